// round 9
// baseline (speedup 1.0000x reference)
#include <cuda_runtime.h>
#include <cuda_bf16.h>
#include <math.h>

#define BB 2
#define SS 1024
#define DDIM 512
#define HH 8
#define DH 64
#define FF 2048
#define MM (BB*SS)

// ---------------- scratch (no allocation allowed) ----------------
__device__ float g_xn[MM*DDIM];
__device__ float g_q [MM*DDIM];
__device__ float g_k [MM*DDIM];
__device__ float g_v [MM*DDIM];
__device__ float g_att[MM*DDIM];
__device__ float g_h [MM*DDIM];
__device__ float g_hn[MM*DDIM];
__device__ float g_f1[MM*FF];
__device__ float g_u [MM];
__device__ float g_lam[BB];
__device__ int   g_sp [BB];

// ---------------- helpers ----------------
__device__ __forceinline__ void bsplit(float x0, float x1, unsigned &hw, unsigned &lw){
    asm("cvt.rn.bf16x2.f32 %0, %1, %2;" : "=r"(hw) : "f"(x1), "f"(x0));
    float h0 = __uint_as_float(hw << 16);
    float h1 = __uint_as_float(hw & 0xffff0000u);
    float l0 = x0 - h0, l1 = x1 - h1;
    asm("cvt.rn.bf16x2.f32 %0, %1, %2;" : "=r"(lw) : "f"(l1), "f"(l0));
}

__device__ __forceinline__ void mma16(float* c, const unsigned* a, const unsigned* b){
    asm volatile(
        "mma.sync.aligned.m16n8k16.row.col.f32.bf16.bf16.f32 "
        "{%0,%1,%2,%3}, {%4,%5,%6,%7}, {%8,%9}, {%0,%1,%2,%3};\n"
        : "+f"(c[0]), "+f"(c[1]), "+f"(c[2]), "+f"(c[3])
        : "r"(a[0]), "r"(a[1]), "r"(a[2]), "r"(a[3]), "r"(b[0]), "r"(b[1]));
}

__device__ __forceinline__ float gelu_exact(float v){
    return 0.5f * v * (1.0f + erff(v * 0.70710678118654752f));
}

// ---------------- lam / sparse flag ----------------
__global__ void lam_kernel(const float* __restrict__ u_prev){
    int b = threadIdx.x;
    if (b < BB){
        float lam = 10.0f * expf(-5.0f * u_prev[b]);
        g_lam[b] = lam;
        g_sp[b]  = (lam >= 1.0f) ? 1 : 0;
    }
}

// ---------------- LayerNorm ----------------
__global__ void ln_kernel(const float* __restrict__ x, const float* __restrict__ g,
                          const float* __restrict__ be, float* __restrict__ y){
    int row = blockIdx.x;
    int t = threadIdx.x;
    const float* xr = x + (size_t)row * DDIM;
    float4 v = *(const float4*)(xr + t*4);
    float s  = v.x + v.y + v.z + v.w;
    float ss = v.x*v.x + v.y*v.y + v.z*v.z + v.w*v.w;
    #pragma unroll
    for (int o = 16; o; o >>= 1){
        s  += __shfl_xor_sync(0xffffffffu, s,  o);
        ss += __shfl_xor_sync(0xffffffffu, ss, o);
    }
    __shared__ float ps[4], pss[4];
    int w = t >> 5;
    if ((t & 31) == 0){ ps[w] = s; pss[w] = ss; }
    __syncthreads();
    s  = ps[0] + ps[1] + ps[2] + ps[3];
    ss = pss[0] + pss[1] + pss[2] + pss[3];
    float mean = s * (1.0f/DDIM);
    float var  = ss * (1.0f/DDIM) - mean*mean;
    float inv  = rsqrtf(var + 1e-5f);
    float4 gv = *(const float4*)(g  + t*4);
    float4 bv = *(const float4*)(be + t*4);
    float4 o;
    o.x = (v.x - mean)*inv*gv.x + bv.x;
    o.y = (v.y - mean)*inv*gv.y + bv.y;
    o.z = (v.z - mean)*inv*gv.z + bv.z;
    o.w = (v.w - mean)*inv*gv.w + bv.w;
    *(float4*)(y + (size_t)row * DDIM + t*4) = o;
}

// ---------------- bf16x3 tensor-core GEMM body (term-major ILP) ----------------
// C[M,N] = A[M,K] @ W[N,K]^T (+bias)(+res)(gelu), fp32 in/out.
// BMx64 tile, BK=32, 128 threads (4 warps, 2x2), warp tile (BM/2)x32.
// MMAs issued term-major (hh all tiles, hl all, lh all) -> RAW distance 8.
template<int BM, bool GELU, bool RES>
__device__ __forceinline__ void gemm_body(
        const float* __restrict__ A, const float* __restrict__ W,
        const float* __restrict__ bias, const float* __restrict__ res,
        float* __restrict__ C, int Kn, int Nn, int m0, int n0){
    constexpr int MTILES = BM/16;
    constexpr int WMT    = MTILES/2;
    constexpr int AIT    = BM/16;

    __shared__ unsigned Ah[2][MTILES][32][4];
    __shared__ unsigned Al[2][MTILES][32][4];
    __shared__ unsigned Bh[2][8][32][2];
    __shared__ unsigned Bl[2][8][32][2];

    const int tid = threadIdx.x;
    const int warp = tid >> 5, ln = tid & 31;
    const int wm = warp >> 1, wn = warp & 1;
    const int gid = ln >> 2, t4 = ln & 3;

    float acc[WMT][4][4];
    #pragma unroll
    for (int mt = 0; mt < WMT; mt++)
        #pragma unroll
        for (int nt = 0; nt < 4; nt++)
            #pragma unroll
            for (int r = 0; r < 4; r++) acc[mt][nt][r] = 0.0f;

    float4 av[AIT], wv4[4];
    // prefetch first tile
    #pragma unroll
    for (int i = 0; i < AIT; i++){
        int f = tid + i*128;
        int row = f >> 3, kq = (f & 7) << 2;
        av[i] = *(const float4*)(A + (size_t)(m0 + row)*Kn + kq);
    }
    #pragma unroll
    for (int i = 0; i < 4; i++){
        int f = tid + i*128;
        int row = f >> 3, kq = (f & 7) << 2;
        wv4[i] = *(const float4*)(W + (size_t)(n0 + row)*Kn + kq);
    }

    for (int kt = 0; kt < Kn; kt += 32){
        __syncthreads();
        #pragma unroll
        for (int i = 0; i < AIT; i++){
            int f = tid + i*128;
            int row = f >> 3, kq = (f & 7) << 2;
            int ks = kq >> 4, kk = kq & 15;
            int mt = row >> 4, rr = row & 15;
            int slot = ((rr >> 3) & 1) + (((kk >> 3) & 1) << 1);
            int lane = (rr & 7)*4 + ((kk & 7) >> 1);
            unsigned h0, l0, h1, l1;
            bsplit(av[i].x, av[i].y, h0, l0);
            bsplit(av[i].z, av[i].w, h1, l1);
            Ah[ks][mt][lane  ][slot] = h0;
            Ah[ks][mt][lane+1][slot] = h1;
            Al[ks][mt][lane  ][slot] = l0;
            Al[ks][mt][lane+1][slot] = l1;
        }
        #pragma unroll
        for (int i = 0; i < 4; i++){
            int f = tid + i*128;
            int row = f >> 3, kq = (f & 7) << 2;
            int ks = kq >> 4, kk = kq & 15;
            int nt = row >> 3;
            int slot = (kk >> 3) & 1;
            int lane = (row & 7)*4 + ((kk & 7) >> 1);
            unsigned h0, l0, h1, l1;
            bsplit(wv4[i].x, wv4[i].y, h0, l0);
            bsplit(wv4[i].z, wv4[i].w, h1, l1);
            Bh[ks][nt][lane  ][slot] = h0;
            Bh[ks][nt][lane+1][slot] = h1;
            Bl[ks][nt][lane  ][slot] = l0;
            Bl[ks][nt][lane+1][slot] = l1;
        }
        __syncthreads();

        // prefetch next tile while MMAs run
        if (kt + 32 < Kn){
            #pragma unroll
            for (int i = 0; i < AIT; i++){
                int f = tid + i*128;
                int row = f >> 3, kq = (f & 7) << 2;
                av[i] = *(const float4*)(A + (size_t)(m0 + row)*Kn + kt + 32 + kq);
            }
            #pragma unroll
            for (int i = 0; i < 4; i++){
                int f = tid + i*128;
                int row = f >> 3, kq = (f & 7) << 2;
                wv4[i] = *(const float4*)(W + (size_t)(n0 + row)*Kn + kt + 32 + kq);
            }
        }

        #pragma unroll
        for (int ks = 0; ks < 2; ks++){
            unsigned ah[WMT][4], al[WMT][4], bh[4][2], bl[4][2];
            #pragma unroll
            for (int mt = 0; mt < WMT; mt++){
                *(uint4*)ah[mt] = *(const uint4*)Ah[ks][wm*WMT + mt][ln];
                *(uint4*)al[mt] = *(const uint4*)Al[ks][wm*WMT + mt][ln];
            }
            #pragma unroll
            for (int nt = 0; nt < 4; nt++){
                *(uint2*)bh[nt] = *(const uint2*)Bh[ks][wn*4 + nt][ln];
                *(uint2*)bl[nt] = *(const uint2*)Bl[ks][wn*4 + nt][ln];
            }
            // term-major: 8 independent MMAs per pass, RAW distance 8
            #pragma unroll
            for (int mt = 0; mt < WMT; mt++)
                #pragma unroll
                for (int nt = 0; nt < 4; nt++)
                    mma16(acc[mt][nt], ah[mt], bh[nt]);
            #pragma unroll
            for (int mt = 0; mt < WMT; mt++)
                #pragma unroll
                for (int nt = 0; nt < 4; nt++)
                    mma16(acc[mt][nt], ah[mt], bl[nt]);
            #pragma unroll
            for (int mt = 0; mt < WMT; mt++)
                #pragma unroll
                for (int nt = 0; nt < 4; nt++)
                    mma16(acc[mt][nt], al[mt], bh[nt]);
        }
    }

    #pragma unroll
    for (int mt = 0; mt < WMT; mt++){
        #pragma unroll
        for (int rr = 0; rr < 2; rr++){
            int m = m0 + wm*(BM/2) + mt*16 + gid + rr*8;
            #pragma unroll
            for (int nt = 0; nt < 4; nt++){
                int n = n0 + wn*32 + nt*8 + t4*2;
                float2 o;
                o.x = acc[mt][nt][rr*2 + 0];
                o.y = acc[mt][nt][rr*2 + 1];
                float2 bv = *(const float2*)(bias + n);
                o.x += bv.x; o.y += bv.y;
                if (RES){
                    float2 rv = *(const float2*)(res + (size_t)m*Nn + n);
                    o.x += rv.x; o.y += rv.y;
                }
                if (GELU){
                    o.x = gelu_exact(o.x);
                    o.y = gelu_exact(o.y);
                }
                *(float2*)(C + (size_t)m*Nn + n) = o;
            }
        }
    }
}

// ---------------- GEMM kernels ----------------
__global__ void __launch_bounds__(128, 5)
qkv_kernel(const float* __restrict__ xn,
           const float* __restrict__ wq, const float* __restrict__ wk, const float* __restrict__ wv,
           const float* __restrict__ bq, const float* __restrict__ bk, const float* __restrict__ bv,
           float* __restrict__ q, float* __restrict__ k, float* __restrict__ v){
    int sel = blockIdx.x >> 3;
    int n0 = (blockIdx.x & 7) << 6;
    const float* W    = (sel == 0) ? wq : (sel == 1) ? wk : wv;
    const float* bias = (sel == 0) ? bq : (sel == 1) ? bk : bv;
    float* C          = (sel == 0) ? q  : (sel == 1) ? k  : v;
    gemm_body<64,false,false>(xn, W, bias, nullptr, C, DDIM, DDIM, blockIdx.y*64, n0);
}

template<bool GELU, bool RES>
__global__ void __launch_bounds__(128, 5)
gemm64(const float* __restrict__ A, const float* __restrict__ W,
       const float* __restrict__ bias, const float* __restrict__ res,
       float* __restrict__ C, int Kn, int Nn){
    gemm_body<64,GELU,RES>(A, W, bias, res, C, Kn, Nn, blockIdx.y*64, blockIdx.x*64);
}

template<bool GELU, bool RES>
__global__ void __launch_bounds__(128, 5)
gemm32(const float* __restrict__ A, const float* __restrict__ W,
       const float* __restrict__ bias, const float* __restrict__ res,
       float* __restrict__ C, int Kn, int Nn){
    gemm_body<32,GELU,RES>(A, W, bias, res, C, Kn, Nn, blockIdx.y*32, blockIdx.x*64);
}

// ---------------- tensor-core flash attention (round-4 version) ----------------
__global__ void __launch_bounds__(128)
attn_kernel(const float* __restrict__ Q, const float* __restrict__ K,
            const float* __restrict__ V, float* __restrict__ O){
    __shared__ unsigned Kh[4][8][32][2], Kl[4][8][32][2];
    __shared__ unsigned Vh[4][8][32][2], Vl[4][8][32][2];

    const int bh = blockIdx.y;
    const int b = bh / HH, h = bh % HH;
    const int q0 = blockIdx.x * 64;
    const float lam = g_lam[b];
    const int sp = g_sp[b];
    const int tid = threadIdx.x;
    const int w = tid >> 5, ln = tid & 31;
    const int gid = ln >> 2, t4 = ln & 3;
    const int r0 = q0 + w*16 + gid;
    const int r1 = r0 + 8;

    unsigned qh[4][4], ql[4][4];
    {
        const float* Qb = Q + (size_t)(b*SS)*DDIM + h*DH;
        #pragma unroll
        for (int ks = 0; ks < 4; ks++){
            int kcol = ks*16 + t4*2;
            float2 q00 = *(const float2*)(Qb + (size_t)r0*DDIM + kcol);
            float2 q10 = *(const float2*)(Qb + (size_t)r1*DDIM + kcol);
            float2 q01 = *(const float2*)(Qb + (size_t)r0*DDIM + kcol + 8);
            float2 q11 = *(const float2*)(Qb + (size_t)r1*DDIM + kcol + 8);
            bsplit(q00.x, q00.y, qh[ks][0], ql[ks][0]);
            bsplit(q10.x, q10.y, qh[ks][1], ql[ks][1]);
            bsplit(q01.x, q01.y, qh[ks][2], ql[ks][2]);
            bsplit(q11.x, q11.y, qh[ks][3], ql[ks][3]);
        }
    }

    float oacc[8][4];
    #pragma unroll
    for (int nt = 0; nt < 8; nt++)
        #pragma unroll
        for (int r = 0; r < 4; r++) oacc[nt][r] = 0.0f;
    float mrow0 = -INFINITY, mrow1 = -INFINITY;
    float lrow0 = 0.0f, lrow1 = 0.0f;

    int klo = 0, khi = SS/64;
    if (sp){
        int lo = q0 - 51; if (lo < 0) lo = 0;
        int hi = q0 + 114; if (hi > SS-1) hi = SS-1;
        klo = lo >> 6; khi = (hi >> 6) + 1;
    }

    const float* Kb = K + (size_t)(b*SS)*DDIM + h*DH;
    const float* Vb = V + (size_t)(b*SS)*DDIM + h*DH;

    for (int kb = klo; kb < khi; kb++){
        __syncthreads();
        #pragma unroll
        for (int i = 0; i < 4; i++){
            int f = tid + i*128;
            int r = f >> 3;
            int d8 = (f & 7) * 8;
            float4 x0 = *(const float4*)(Kb + (size_t)(kb*64 + r)*DDIM + d8);
            float4 x1 = *(const float4*)(Kb + (size_t)(kb*64 + r)*DDIM + d8 + 4);
            int ks = d8 >> 4, slot = (d8 >> 3) & 1;
            int lbase = (r & 7) * 4;
            int nt = r >> 3;
            unsigned h0,l0,h1,l1,h2,l2,h3,l3;
            bsplit(x0.x, x0.y, h0, l0);
            bsplit(x0.z, x0.w, h1, l1);
            bsplit(x1.x, x1.y, h2, l2);
            bsplit(x1.z, x1.w, h3, l3);
            Kh[ks][nt][lbase+0][slot] = h0;  Kl[ks][nt][lbase+0][slot] = l0;
            Kh[ks][nt][lbase+1][slot] = h1;  Kl[ks][nt][lbase+1][slot] = l1;
            Kh[ks][nt][lbase+2][slot] = h2;  Kl[ks][nt][lbase+2][slot] = l2;
            Kh[ks][nt][lbase+3][slot] = h3;  Kl[ks][nt][lbase+3][slot] = l3;
        }
        #pragma unroll
        for (int i = 0; i < 4; i++){
            int f = tid + i*128;
            int spr = f >> 4;
            int d4 = (f & 15) * 4;
            int s = spr * 2;
            float4 x0 = *(const float4*)(Vb + (size_t)(kb*64 + s    )*DDIM + d4);
            float4 x1 = *(const float4*)(Vb + (size_t)(kb*64 + s + 1)*DDIM + d4);
            int ks = s >> 4, slot = (s >> 3) & 1;
            int tp = (s & 7) >> 1;
            float a0[4] = {x0.x, x0.y, x0.z, x0.w};
            float a1[4] = {x1.x, x1.y, x1.z, x1.w};
            #pragma unroll
            for (int j = 0; j < 4; j++){
                int d = d4 + j;
                unsigned hv, lv;
                bsplit(a0[j], a1[j], hv, lv);
                Vh[ks][d>>3][(d&7)*4 + tp][slot] = hv;
                Vl[ks][d>>3][(d&7)*4 + tp][slot] = lv;
            }
        }
        __syncthreads();

        float sfrag[8][4];
        #pragma unroll
        for (int nt = 0; nt < 8; nt++)
            #pragma unroll
            for (int r = 0; r < 4; r++) sfrag[nt][r] = 0.0f;
        #pragma unroll
        for (int ks = 0; ks < 4; ks++){
            #pragma unroll
            for (int nt = 0; nt < 8; nt++){
                unsigned kh2[2], kl2[2];
                *(uint2*)kh2 = *(const uint2*)Kh[ks][nt][ln];
                *(uint2*)kl2 = *(const uint2*)Kl[ks][nt][ln];
                mma16(sfrag[nt], qh[ks], kh2);
                mma16(sfrag[nt], qh[ks], kl2);
                mma16(sfrag[nt], ql[ks], kh2);
            }
        }

        float mx0 = -INFINITY, mx1 = -INFINITY;
        #pragma unroll
        for (int nt = 0; nt < 8; nt++){
            #pragma unroll
            for (int e = 0; e < 2; e++){
                int c = kb*64 + nt*8 + t4*2 + e;
                bool in0 = (c >= r0 - 51) && (c <= r0 + 51);
                bool in1 = (c >= r1 - 51) && (c <= r1 + 51);
                float v0 = sfrag[nt][e]   * 0.125f;
                float v1 = sfrag[nt][2+e] * 0.125f;
                if (sp){
                    v0 = in0 ? v0 : -INFINITY;
                    v1 = in1 ? v1 : -INFINITY;
                } else {
                    if (!in0) v0 -= lam;
                    if (!in1) v1 -= lam;
                }
                sfrag[nt][e]   = v0;
                sfrag[nt][2+e] = v1;
                mx0 = fmaxf(mx0, v0);
                mx1 = fmaxf(mx1, v1);
            }
        }
        #pragma unroll
        for (int o = 1; o <= 2; o <<= 1){
            mx0 = fmaxf(mx0, __shfl_xor_sync(0xffffffffu, mx0, o));
            mx1 = fmaxf(mx1, __shfl_xor_sync(0xffffffffu, mx1, o));
        }
        float mnew0 = fmaxf(mrow0, mx0);
        float mnew1 = fmaxf(mrow1, mx1);
        float sf0 = (mrow0 == mnew0) ? 1.0f : __expf(mrow0 - mnew0);
        float sf1 = (mrow1 == mnew1) ? 1.0f : __expf(mrow1 - mnew1);
        float mc0 = fmaxf(mnew0, -1e30f);
        float mc1 = fmaxf(mnew1, -1e30f);
        float rs0 = 0.0f, rs1 = 0.0f;
        #pragma unroll
        for (int nt = 0; nt < 8; nt++){
            #pragma unroll
            for (int e = 0; e < 2; e++){
                float p0 = __expf(sfrag[nt][e]   - mc0);
                float p1 = __expf(sfrag[nt][2+e] - mc1);
                sfrag[nt][e]   = p0;
                sfrag[nt][2+e] = p1;
                rs0 += p0; rs1 += p1;
            }
        }
        #pragma unroll
        for (int o = 1; o <= 2; o <<= 1){
            rs0 += __shfl_xor_sync(0xffffffffu, rs0, o);
            rs1 += __shfl_xor_sync(0xffffffffu, rs1, o);
        }
        lrow0 = lrow0 * sf0 + rs0;  mrow0 = mnew0;
        lrow1 = lrow1 * sf1 + rs1;  mrow1 = mnew1;
        #pragma unroll
        for (int nt = 0; nt < 8; nt++){
            oacc[nt][0] *= sf0; oacc[nt][1] *= sf0;
            oacc[nt][2] *= sf1; oacc[nt][3] *= sf1;
        }

        #pragma unroll
        for (int pks = 0; pks < 4; pks++){
            unsigned pah[4], pal[4];
            bsplit(sfrag[2*pks  ][0], sfrag[2*pks  ][1], pah[0], pal[0]);
            bsplit(sfrag[2*pks  ][2], sfrag[2*pks  ][3], pah[1], pal[1]);
            bsplit(sfrag[2*pks+1][0], sfrag[2*pks+1][1], pah[2], pal[2]);
            bsplit(sfrag[2*pks+1][2], sfrag[2*pks+1][3], pah[3], pal[3]);
            #pragma unroll
            for (int nt = 0; nt < 8; nt++){
                unsigned vh2[2], vl2[2];
                *(uint2*)vh2 = *(const uint2*)Vh[pks][nt][ln];
                *(uint2*)vl2 = *(const uint2*)Vl[pks][nt][ln];
                mma16(oacc[nt], pah, vh2);
                mma16(oacc[nt], pah, vl2);
                mma16(oacc[nt], pal, vh2);
            }
        }
    }

    float inv0 = 1.0f / lrow0;
    float inv1 = 1.0f / lrow1;
    float* Ob = O + (size_t)(b*SS)*DDIM + h*DH;
    #pragma unroll
    for (int nt = 0; nt < 8; nt++){
        int d = nt*8 + t4*2;
        float2 o0, o1;
        o0.x = oacc[nt][0]*inv0; o0.y = oacc[nt][1]*inv0;
        o1.x = oacc[nt][2]*inv1; o1.y = oacc[nt][3]*inv1;
        *(float2*)(Ob + (size_t)r0*DDIM + d) = o0;
        *(float2*)(Ob + (size_t)r1*DDIM + d) = o1;
    }
}

// ---------------- per-row u, then per-batch mean ----------------
__global__ void u_row_kernel(const float* __restrict__ outp, const float* __restrict__ x){
    int row = blockIdx.x;
    int t = threadIdx.x;
    float4 ov = *(const float4*)(outp + (size_t)row*DDIM + t*4);
    float4 xv = *(const float4*)(x    + (size_t)row*DDIM + t*4);
    float dx = ov.x - xv.x, dy = ov.y - xv.y, dz = ov.z - xv.z, dw = ov.w - xv.w;
    float d2 = dx*dx + dy*dy + dz*dz + dw*dw;
    float x2 = xv.x*xv.x + xv.y*xv.y + xv.z*xv.z + xv.w*xv.w;
    #pragma unroll
    for (int o = 16; o; o >>= 1){
        d2 += __shfl_xor_sync(0xffffffffu, d2, o);
        x2 += __shfl_xor_sync(0xffffffffu, x2, o);
    }
    __shared__ float pd[4], px[4];
    int w = t >> 5;
    if ((t & 31) == 0){ pd[w] = d2; px[w] = x2; }
    __syncthreads();
    if (t == 0){
        d2 = pd[0]+pd[1]+pd[2]+pd[3];
        x2 = px[0]+px[1]+px[2]+px[3];
        g_u[row] = sqrtf(d2) / (sqrtf(x2) + 1e-8f);
    }
}

__global__ void u_mean_kernel(float* __restrict__ outp, int out_size){
    int b = blockIdx.x;
    int t = threadIdx.x;
    float s = 0.0f;
    for (int i = t; i < SS; i += 256) s += g_u[b*SS + i];
    #pragma unroll
    for (int o = 16; o; o >>= 1) s += __shfl_xor_sync(0xffffffffu, s, o);
    __shared__ float ps[8];
    int w = t >> 5;
    if ((t & 31) == 0) ps[w] = s;
    __syncthreads();
    if (t == 0){
        s = 0.0f;
        #pragma unroll
        for (int i = 0; i < 8; i++) s += ps[i];
        int idx = MM*DDIM + b;
        if (idx < out_size) outp[idx] = s * (1.0f/SS);
    }
}

// ---------------- launch ----------------
extern "C" void kernel_launch(void* const* d_in, const int* in_sizes, int n_in,
                              void* d_out, int out_size){
    const float* x      = (const float*)d_in[0];
    const float* u_prev = (const float*)d_in[1];
    const float* wq = (const float*)d_in[2];  const float* bq = (const float*)d_in[3];
    const float* wk = (const float*)d_in[4];  const float* bk = (const float*)d_in[5];
    const float* wv = (const float*)d_in[6];  const float* bv = (const float*)d_in[7];
    const float* wo = (const float*)d_in[8];  const float* bo = (const float*)d_in[9];
    const float* ln1g = (const float*)d_in[10]; const float* ln1b = (const float*)d_in[11];
    const float* ln2g = (const float*)d_in[12]; const float* ln2b = (const float*)d_in[13];
    const float* w1 = (const float*)d_in[14]; const float* b1 = (const float*)d_in[15];
    const float* w2 = (const float*)d_in[16]; const float* b2 = (const float*)d_in[17];
    float* outp = (float*)d_out;

    float *p_xn, *p_q, *p_k, *p_v, *p_att, *p_h, *p_hn, *p_f1;
    cudaGetSymbolAddress((void**)&p_xn,  g_xn);
    cudaGetSymbolAddress((void**)&p_q,   g_q);
    cudaGetSymbolAddress((void**)&p_k,   g_k);
    cudaGetSymbolAddress((void**)&p_v,   g_v);
    cudaGetSymbolAddress((void**)&p_att, g_att);
    cudaGetSymbolAddress((void**)&p_h,   g_h);
    cudaGetSymbolAddress((void**)&p_hn,  g_hn);
    cudaGetSymbolAddress((void**)&p_f1,  g_f1);

    lam_kernel<<<1, 32>>>(u_prev);
    ln_kernel<<<MM, 128>>>(x, ln1g, ln1b, p_xn);

    qkv_kernel<<<dim3(24, MM/64), 128>>>(p_xn, wq, wk, wv, bq, bk, bv, p_q, p_k, p_v);

    attn_kernel<<<dim3(SS/64, BB*HH), 128>>>(p_q, p_k, p_v, p_att);

    gemm32<false,true><<<dim3(DDIM/64, MM/32), 128>>>(p_att, wo, bo, x, p_h, DDIM, DDIM);

    ln_kernel<<<MM, 128>>>(p_h, ln2g, ln2b, p_hn);

    gemm64<true,false><<<dim3(FF/64, MM/64), 128>>>(p_hn, w1, b1, nullptr, p_f1, DDIM, FF);
    gemm32<false,true><<<dim3(DDIM/64, MM/32), 128>>>(p_f1, w2, b2, p_h, outp, FF, DDIM);

    u_row_kernel<<<MM, 128>>>(outp, x);
    u_mean_kernel<<<BB, 256>>>(outp, out_size);
}

// round 10
// speedup vs baseline: 1.0571x; 1.0571x over previous
#include <cuda_runtime.h>
#include <cuda_bf16.h>
#include <math.h>

#define BB 2
#define SS 1024
#define DDIM 512
#define HH 8
#define DH 64
#define FF 2048
#define MM (BB*SS)

// ---------------- scratch (no allocation allowed) ----------------
__device__ float g_xn[MM*DDIM];
__device__ float g_q [MM*DDIM];
__device__ float g_k [MM*DDIM];
__device__ float g_v [MM*DDIM];
__device__ float g_att[MM*DDIM];
__device__ float g_h [MM*DDIM];
__device__ float g_hn[MM*DDIM];
__device__ float g_f1[MM*FF];
__device__ float g_lam[BB];
__device__ int   g_sp [BB];

// ---------------- helpers ----------------
__device__ __forceinline__ void bsplit(float x0, float x1, unsigned &hw, unsigned &lw){
    asm("cvt.rn.bf16x2.f32 %0, %1, %2;" : "=r"(hw) : "f"(x1), "f"(x0));
    float h0 = __uint_as_float(hw << 16);
    float h1 = __uint_as_float(hw & 0xffff0000u);
    float l0 = x0 - h0, l1 = x1 - h1;
    asm("cvt.rn.bf16x2.f32 %0, %1, %2;" : "=r"(lw) : "f"(l1), "f"(l0));
}

__device__ __forceinline__ void mma16(float* c, const unsigned* a, const unsigned* b){
    asm volatile(
        "mma.sync.aligned.m16n8k16.row.col.f32.bf16.bf16.f32 "
        "{%0,%1,%2,%3}, {%4,%5,%6,%7}, {%8,%9}, {%0,%1,%2,%3};\n"
        : "+f"(c[0]), "+f"(c[1]), "+f"(c[2]), "+f"(c[3])
        : "r"(a[0]), "r"(a[1]), "r"(a[2]), "r"(a[3]), "r"(b[0]), "r"(b[1]));
}

__device__ __forceinline__ float gelu_exact(float v){
    return 0.5f * v * (1.0f + erff(v * 0.70710678118654752f));
}

// ---------------- LayerNorm (+optional lam compute / u-slot zero in block 0) ----------------
template<bool DOLAM>
__global__ void ln_kernel(const float* __restrict__ x, const float* __restrict__ g,
                          const float* __restrict__ be, float* __restrict__ y,
                          const float* __restrict__ u_prev, float* __restrict__ outp,
                          int out_size){
    int row = blockIdx.x;
    int t = threadIdx.x;
    if (DOLAM && row == 0 && t < BB){
        float lam = 10.0f * expf(-5.0f * u_prev[t]);
        g_lam[t] = lam;
        g_sp[t]  = (lam >= 1.0f) ? 1 : 0;
        int idx = MM*DDIM + t;
        if (idx < out_size) outp[idx] = 0.0f;
    }
    const float* xr = x + (size_t)row * DDIM;
    float4 v = *(const float4*)(xr + t*4);
    float s  = v.x + v.y + v.z + v.w;
    float ss = v.x*v.x + v.y*v.y + v.z*v.z + v.w*v.w;
    #pragma unroll
    for (int o = 16; o; o >>= 1){
        s  += __shfl_xor_sync(0xffffffffu, s,  o);
        ss += __shfl_xor_sync(0xffffffffu, ss, o);
    }
    __shared__ float ps[4], pss[4];
    int w = t >> 5;
    if ((t & 31) == 0){ ps[w] = s; pss[w] = ss; }
    __syncthreads();
    s  = ps[0] + ps[1] + ps[2] + ps[3];
    ss = pss[0] + pss[1] + pss[2] + pss[3];
    float mean = s * (1.0f/DDIM);
    float var  = ss * (1.0f/DDIM) - mean*mean;
    float inv  = rsqrtf(var + 1e-5f);
    float4 gv = *(const float4*)(g  + t*4);
    float4 bv = *(const float4*)(be + t*4);
    float4 o;
    o.x = (v.x - mean)*inv*gv.x + bv.x;
    o.y = (v.y - mean)*inv*gv.y + bv.y;
    o.z = (v.z - mean)*inv*gv.z + bv.z;
    o.w = (v.w - mean)*inv*gv.w + bv.w;
    *(float4*)(y + (size_t)row * DDIM + t*4) = o;
}

// ---------------- bf16x3 tensor-core GEMM body (round-4 exact) ----------------
template<int BM, bool GELU, bool RES>
__device__ __forceinline__ void gemm_body(
        const float* __restrict__ A, const float* __restrict__ W,
        const float* __restrict__ bias, const float* __restrict__ res,
        float* __restrict__ C, int Kn, int Nn, int m0, int n0){
    constexpr int MTILES = BM/16;
    constexpr int WMT    = MTILES/2;
    constexpr int AIT    = BM/16;

    __shared__ unsigned Ah[2][MTILES][32][4];
    __shared__ unsigned Al[2][MTILES][32][4];
    __shared__ unsigned Bh[2][8][32][2];
    __shared__ unsigned Bl[2][8][32][2];

    const int tid = threadIdx.x;
    const int warp = tid >> 5, ln = tid & 31;
    const int wm = warp >> 1, wn = warp & 1;
    const int gid = ln >> 2, t4 = ln & 3;

    float acc[WMT][4][4];
    #pragma unroll
    for (int mt = 0; mt < WMT; mt++)
        #pragma unroll
        for (int nt = 0; nt < 4; nt++)
            #pragma unroll
            for (int r = 0; r < 4; r++) acc[mt][nt][r] = 0.0f;

    float4 av[AIT], wv4[4];
    #pragma unroll
    for (int i = 0; i < AIT; i++){
        int f = tid + i*128;
        int row = f >> 3, kq = (f & 7) << 2;
        av[i] = *(const float4*)(A + (size_t)(m0 + row)*Kn + kq);
    }
    #pragma unroll
    for (int i = 0; i < 4; i++){
        int f = tid + i*128;
        int row = f >> 3, kq = (f & 7) << 2;
        wv4[i] = *(const float4*)(W + (size_t)(n0 + row)*Kn + kq);
    }

    for (int kt = 0; kt < Kn; kt += 32){
        __syncthreads();
        #pragma unroll
        for (int i = 0; i < AIT; i++){
            int f = tid + i*128;
            int row = f >> 3, kq = (f & 7) << 2;
            int ks = kq >> 4, kk = kq & 15;
            int mt = row >> 4, rr = row & 15;
            int slot = ((rr >> 3) & 1) + (((kk >> 3) & 1) << 1);
            int lane = (rr & 7)*4 + ((kk & 7) >> 1);
            unsigned h0, l0, h1, l1;
            bsplit(av[i].x, av[i].y, h0, l0);
            bsplit(av[i].z, av[i].w, h1, l1);
            Ah[ks][mt][lane  ][slot] = h0;
            Ah[ks][mt][lane+1][slot] = h1;
            Al[ks][mt][lane  ][slot] = l0;
            Al[ks][mt][lane+1][slot] = l1;
        }
        #pragma unroll
        for (int i = 0; i < 4; i++){
            int f = tid + i*128;
            int row = f >> 3, kq = (f & 7) << 2;
            int ks = kq >> 4, kk = kq & 15;
            int nt = row >> 3;
            int slot = (kk >> 3) & 1;
            int lane = (row & 7)*4 + ((kk & 7) >> 1);
            unsigned h0, l0, h1, l1;
            bsplit(wv4[i].x, wv4[i].y, h0, l0);
            bsplit(wv4[i].z, wv4[i].w, h1, l1);
            Bh[ks][nt][lane  ][slot] = h0;
            Bh[ks][nt][lane+1][slot] = h1;
            Bl[ks][nt][lane  ][slot] = l0;
            Bl[ks][nt][lane+1][slot] = l1;
        }
        __syncthreads();

        if (kt + 32 < Kn){
            #pragma unroll
            for (int i = 0; i < AIT; i++){
                int f = tid + i*128;
                int row = f >> 3, kq = (f & 7) << 2;
                av[i] = *(const float4*)(A + (size_t)(m0 + row)*Kn + kt + 32 + kq);
            }
            #pragma unroll
            for (int i = 0; i < 4; i++){
                int f = tid + i*128;
                int row = f >> 3, kq = (f & 7) << 2;
                wv4[i] = *(const float4*)(W + (size_t)(n0 + row)*Kn + kt + 32 + kq);
            }
        }

        #pragma unroll
        for (int ks = 0; ks < 2; ks++){
            unsigned ah[WMT][4], al[WMT][4], bh[4][2], bl[4][2];
            #pragma unroll
            for (int mt = 0; mt < WMT; mt++){
                *(uint4*)ah[mt] = *(const uint4*)Ah[ks][wm*WMT + mt][ln];
                *(uint4*)al[mt] = *(const uint4*)Al[ks][wm*WMT + mt][ln];
            }
            #pragma unroll
            for (int nt = 0; nt < 4; nt++){
                *(uint2*)bh[nt] = *(const uint2*)Bh[ks][wn*4 + nt][ln];
                *(uint2*)bl[nt] = *(const uint2*)Bl[ks][wn*4 + nt][ln];
            }
            #pragma unroll
            for (int mt = 0; mt < WMT; mt++)
                #pragma unroll
                for (int nt = 0; nt < 4; nt++){
                    mma16(acc[mt][nt], ah[mt], bh[nt]);
                    mma16(acc[mt][nt], ah[mt], bl[nt]);
                    mma16(acc[mt][nt], al[mt], bh[nt]);
                }
        }
    }

    #pragma unroll
    for (int mt = 0; mt < WMT; mt++){
        #pragma unroll
        for (int rr = 0; rr < 2; rr++){
            int m = m0 + wm*(BM/2) + mt*16 + gid + rr*8;
            #pragma unroll
            for (int nt = 0; nt < 4; nt++){
                int n = n0 + wn*32 + nt*8 + t4*2;
                float2 o;
                o.x = acc[mt][nt][rr*2 + 0];
                o.y = acc[mt][nt][rr*2 + 1];
                float2 bv = *(const float2*)(bias + n);
                o.x += bv.x; o.y += bv.y;
                if (RES){
                    float2 rv = *(const float2*)(res + (size_t)m*Nn + n);
                    o.x += rv.x; o.y += rv.y;
                }
                if (GELU){
                    o.x = gelu_exact(o.x);
                    o.y = gelu_exact(o.y);
                }
                *(float2*)(C + (size_t)m*Nn + n) = o;
            }
        }
    }
}

// ---------------- GEMM kernels ----------------
__global__ void __launch_bounds__(128)
qkv_kernel(const float* __restrict__ xn,
           const float* __restrict__ wq, const float* __restrict__ wk, const float* __restrict__ wv,
           const float* __restrict__ bq, const float* __restrict__ bk, const float* __restrict__ bv,
           float* __restrict__ q, float* __restrict__ k, float* __restrict__ v){
    int sel = blockIdx.x >> 3;
    int n0 = (blockIdx.x & 7) << 6;
    const float* W    = (sel == 0) ? wq : (sel == 1) ? wk : wv;
    const float* bias = (sel == 0) ? bq : (sel == 1) ? bk : bv;
    float* C          = (sel == 0) ? q  : (sel == 1) ? k  : v;
    gemm_body<64,false,false>(xn, W, bias, nullptr, C, DDIM, DDIM, blockIdx.y*64, n0);
}

template<bool GELU, bool RES>
__global__ void __launch_bounds__(128)
gemm64(const float* __restrict__ A, const float* __restrict__ W,
       const float* __restrict__ bias, const float* __restrict__ res,
       float* __restrict__ C, int Kn, int Nn){
    gemm_body<64,GELU,RES>(A, W, bias, res, C, Kn, Nn, blockIdx.y*64, blockIdx.x*64);
}

template<bool GELU, bool RES>
__global__ void __launch_bounds__(128)
gemm32(const float* __restrict__ A, const float* __restrict__ W,
       const float* __restrict__ bias, const float* __restrict__ res,
       float* __restrict__ C, int Kn, int Nn){
    gemm_body<32,GELU,RES>(A, W, bias, res, C, Kn, Nn, blockIdx.y*32, blockIdx.x*64);
}

// ---------------- tensor-core flash attention (round-4 exact) ----------------
__global__ void __launch_bounds__(128)
attn_kernel(const float* __restrict__ Q, const float* __restrict__ K,
            const float* __restrict__ V, float* __restrict__ O){
    __shared__ unsigned Kh[4][8][32][2], Kl[4][8][32][2];
    __shared__ unsigned Vh[4][8][32][2], Vl[4][8][32][2];

    const int bh = blockIdx.y;
    const int b = bh / HH, h = bh % HH;
    const int q0 = blockIdx.x * 64;
    const float lam = g_lam[b];
    const int sp = g_sp[b];
    const int tid = threadIdx.x;
    const int w = tid >> 5, ln = tid & 31;
    const int gid = ln >> 2, t4 = ln & 3;
    const int r0 = q0 + w*16 + gid;
    const int r1 = r0 + 8;

    unsigned qh[4][4], ql[4][4];
    {
        const float* Qb = Q + (size_t)(b*SS)*DDIM + h*DH;
        #pragma unroll
        for (int ks = 0; ks < 4; ks++){
            int kcol = ks*16 + t4*2;
            float2 q00 = *(const float2*)(Qb + (size_t)r0*DDIM + kcol);
            float2 q10 = *(const float2*)(Qb + (size_t)r1*DDIM + kcol);
            float2 q01 = *(const float2*)(Qb + (size_t)r0*DDIM + kcol + 8);
            float2 q11 = *(const float2*)(Qb + (size_t)r1*DDIM + kcol + 8);
            bsplit(q00.x, q00.y, qh[ks][0], ql[ks][0]);
            bsplit(q10.x, q10.y, qh[ks][1], ql[ks][1]);
            bsplit(q01.x, q01.y, qh[ks][2], ql[ks][2]);
            bsplit(q11.x, q11.y, qh[ks][3], ql[ks][3]);
        }
    }

    float oacc[8][4];
    #pragma unroll
    for (int nt = 0; nt < 8; nt++)
        #pragma unroll
        for (int r = 0; r < 4; r++) oacc[nt][r] = 0.0f;
    float mrow0 = -INFINITY, mrow1 = -INFINITY;
    float lrow0 = 0.0f, lrow1 = 0.0f;

    int klo = 0, khi = SS/64;
    if (sp){
        int lo = q0 - 51; if (lo < 0) lo = 0;
        int hi = q0 + 114; if (hi > SS-1) hi = SS-1;
        klo = lo >> 6; khi = (hi >> 6) + 1;
    }

    const float* Kb = K + (size_t)(b*SS)*DDIM + h*DH;
    const float* Vb = V + (size_t)(b*SS)*DDIM + h*DH;

    for (int kb = klo; kb < khi; kb++){
        __syncthreads();
        #pragma unroll
        for (int i = 0; i < 4; i++){
            int f = tid + i*128;
            int r = f >> 3;
            int d8 = (f & 7) * 8;
            float4 x0 = *(const float4*)(Kb + (size_t)(kb*64 + r)*DDIM + d8);
            float4 x1 = *(const float4*)(Kb + (size_t)(kb*64 + r)*DDIM + d8 + 4);
            int ks = d8 >> 4, slot = (d8 >> 3) & 1;
            int lbase = (r & 7) * 4;
            int nt = r >> 3;
            unsigned h0,l0,h1,l1,h2,l2,h3,l3;
            bsplit(x0.x, x0.y, h0, l0);
            bsplit(x0.z, x0.w, h1, l1);
            bsplit(x1.x, x1.y, h2, l2);
            bsplit(x1.z, x1.w, h3, l3);
            Kh[ks][nt][lbase+0][slot] = h0;  Kl[ks][nt][lbase+0][slot] = l0;
            Kh[ks][nt][lbase+1][slot] = h1;  Kl[ks][nt][lbase+1][slot] = l1;
            Kh[ks][nt][lbase+2][slot] = h2;  Kl[ks][nt][lbase+2][slot] = l2;
            Kh[ks][nt][lbase+3][slot] = h3;  Kl[ks][nt][lbase+3][slot] = l3;
        }
        #pragma unroll
        for (int i = 0; i < 4; i++){
            int f = tid + i*128;
            int spr = f >> 4;
            int d4 = (f & 15) * 4;
            int s = spr * 2;
            float4 x0 = *(const float4*)(Vb + (size_t)(kb*64 + s    )*DDIM + d4);
            float4 x1 = *(const float4*)(Vb + (size_t)(kb*64 + s + 1)*DDIM + d4);
            int ks = s >> 4, slot = (s >> 3) & 1;
            int tp = (s & 7) >> 1;
            float a0[4] = {x0.x, x0.y, x0.z, x0.w};
            float a1[4] = {x1.x, x1.y, x1.z, x1.w};
            #pragma unroll
            for (int j = 0; j < 4; j++){
                int d = d4 + j;
                unsigned hv, lv;
                bsplit(a0[j], a1[j], hv, lv);
                Vh[ks][d>>3][(d&7)*4 + tp][slot] = hv;
                Vl[ks][d>>3][(d&7)*4 + tp][slot] = lv;
            }
        }
        __syncthreads();

        float sfrag[8][4];
        #pragma unroll
        for (int nt = 0; nt < 8; nt++)
            #pragma unroll
            for (int r = 0; r < 4; r++) sfrag[nt][r] = 0.0f;
        #pragma unroll
        for (int ks = 0; ks < 4; ks++){
            #pragma unroll
            for (int nt = 0; nt < 8; nt++){
                unsigned kh2[2], kl2[2];
                *(uint2*)kh2 = *(const uint2*)Kh[ks][nt][ln];
                *(uint2*)kl2 = *(const uint2*)Kl[ks][nt][ln];
                mma16(sfrag[nt], qh[ks], kh2);
                mma16(sfrag[nt], qh[ks], kl2);
                mma16(sfrag[nt], ql[ks], kh2);
            }
        }

        float mx0 = -INFINITY, mx1 = -INFINITY;
        #pragma unroll
        for (int nt = 0; nt < 8; nt++){
            #pragma unroll
            for (int e = 0; e < 2; e++){
                int c = kb*64 + nt*8 + t4*2 + e;
                bool in0 = (c >= r0 - 51) && (c <= r0 + 51);
                bool in1 = (c >= r1 - 51) && (c <= r1 + 51);
                float v0 = sfrag[nt][e]   * 0.125f;
                float v1 = sfrag[nt][2+e] * 0.125f;
                if (sp){
                    v0 = in0 ? v0 : -INFINITY;
                    v1 = in1 ? v1 : -INFINITY;
                } else {
                    if (!in0) v0 -= lam;
                    if (!in1) v1 -= lam;
                }
                sfrag[nt][e]   = v0;
                sfrag[nt][2+e] = v1;
                mx0 = fmaxf(mx0, v0);
                mx1 = fmaxf(mx1, v1);
            }
        }
        #pragma unroll
        for (int o = 1; o <= 2; o <<= 1){
            mx0 = fmaxf(mx0, __shfl_xor_sync(0xffffffffu, mx0, o));
            mx1 = fmaxf(mx1, __shfl_xor_sync(0xffffffffu, mx1, o));
        }
        float mnew0 = fmaxf(mrow0, mx0);
        float mnew1 = fmaxf(mrow1, mx1);
        float sf0 = (mrow0 == mnew0) ? 1.0f : __expf(mrow0 - mnew0);
        float sf1 = (mrow1 == mnew1) ? 1.0f : __expf(mrow1 - mnew1);
        float mc0 = fmaxf(mnew0, -1e30f);
        float mc1 = fmaxf(mnew1, -1e30f);
        float rs0 = 0.0f, rs1 = 0.0f;
        #pragma unroll
        for (int nt = 0; nt < 8; nt++){
            #pragma unroll
            for (int e = 0; e < 2; e++){
                float p0 = __expf(sfrag[nt][e]   - mc0);
                float p1 = __expf(sfrag[nt][2+e] - mc1);
                sfrag[nt][e]   = p0;
                sfrag[nt][2+e] = p1;
                rs0 += p0; rs1 += p1;
            }
        }
        #pragma unroll
        for (int o = 1; o <= 2; o <<= 1){
            rs0 += __shfl_xor_sync(0xffffffffu, rs0, o);
            rs1 += __shfl_xor_sync(0xffffffffu, rs1, o);
        }
        lrow0 = lrow0 * sf0 + rs0;  mrow0 = mnew0;
        lrow1 = lrow1 * sf1 + rs1;  mrow1 = mnew1;
        #pragma unroll
        for (int nt = 0; nt < 8; nt++){
            oacc[nt][0] *= sf0; oacc[nt][1] *= sf0;
            oacc[nt][2] *= sf1; oacc[nt][3] *= sf1;
        }

        #pragma unroll
        for (int pks = 0; pks < 4; pks++){
            unsigned pah[4], pal[4];
            bsplit(sfrag[2*pks  ][0], sfrag[2*pks  ][1], pah[0], pal[0]);
            bsplit(sfrag[2*pks  ][2], sfrag[2*pks  ][3], pah[1], pal[1]);
            bsplit(sfrag[2*pks+1][0], sfrag[2*pks+1][1], pah[2], pal[2]);
            bsplit(sfrag[2*pks+1][2], sfrag[2*pks+1][3], pah[3], pal[3]);
            #pragma unroll
            for (int nt = 0; nt < 8; nt++){
                unsigned vh2[2], vl2[2];
                *(uint2*)vh2 = *(const uint2*)Vh[pks][nt][ln];
                *(uint2*)vl2 = *(const uint2*)Vl[pks][nt][ln];
                mma16(oacc[nt], pah, vh2);
                mma16(oacc[nt], pah, vl2);
                mma16(oacc[nt], pal, vh2);
            }
        }
    }

    float inv0 = 1.0f / lrow0;
    float inv1 = 1.0f / lrow1;
    float* Ob = O + (size_t)(b*SS)*DDIM + h*DH;
    #pragma unroll
    for (int nt = 0; nt < 8; nt++){
        int d = nt*8 + t4*2;
        float2 o0, o1;
        o0.x = oacc[nt][0]*inv0; o0.y = oacc[nt][1]*inv0;
        o1.x = oacc[nt][2]*inv1; o1.y = oacc[nt][3]*inv1;
        *(float2*)(Ob + (size_t)r0*DDIM + d) = o0;
        *(float2*)(Ob + (size_t)r1*DDIM + d) = o1;
    }
}

// ---------------- per-row u with fused batch-mean (atomic) ----------------
__global__ void u_row_kernel(float* __restrict__ outp, const float* __restrict__ x,
                             int out_size){
    int row = blockIdx.x;
    int t = threadIdx.x;
    float4 ov = *(const float4*)(outp + (size_t)row*DDIM + t*4);
    float4 xv = *(const float4*)(x    + (size_t)row*DDIM + t*4);
    float dx = ov.x - xv.x, dy = ov.y - xv.y, dz = ov.z - xv.z, dw = ov.w - xv.w;
    float d2 = dx*dx + dy*dy + dz*dz + dw*dw;
    float x2 = xv.x*xv.x + xv.y*xv.y + xv.z*xv.z + xv.w*xv.w;
    #pragma unroll
    for (int o = 16; o; o >>= 1){
        d2 += __shfl_xor_sync(0xffffffffu, d2, o);
        x2 += __shfl_xor_sync(0xffffffffu, x2, o);
    }
    __shared__ float pd[4], px[4];
    int w = t >> 5;
    if ((t & 31) == 0){ pd[w] = d2; px[w] = x2; }
    __syncthreads();
    if (t == 0){
        d2 = pd[0]+pd[1]+pd[2]+pd[3];
        x2 = px[0]+px[1]+px[2]+px[3];
        float u = sqrtf(d2) / (sqrtf(x2) + 1e-8f);
        int b = row >> 10;   // row / SS
        int idx = MM*DDIM + b;
        if (idx < out_size) atomicAdd(outp + idx, u * (1.0f/SS));
    }
}

// ---------------- launch ----------------
extern "C" void kernel_launch(void* const* d_in, const int* in_sizes, int n_in,
                              void* d_out, int out_size){
    const float* x      = (const float*)d_in[0];
    const float* u_prev = (const float*)d_in[1];
    const float* wq = (const float*)d_in[2];  const float* bq = (const float*)d_in[3];
    const float* wk = (const float*)d_in[4];  const float* bk = (const float*)d_in[5];
    const float* wv = (const float*)d_in[6];  const float* bv = (const float*)d_in[7];
    const float* wo = (const float*)d_in[8];  const float* bo = (const float*)d_in[9];
    const float* ln1g = (const float*)d_in[10]; const float* ln1b = (const float*)d_in[11];
    const float* ln2g = (const float*)d_in[12]; const float* ln2b = (const float*)d_in[13];
    const float* w1 = (const float*)d_in[14]; const float* b1 = (const float*)d_in[15];
    const float* w2 = (const float*)d_in[16]; const float* b2 = (const float*)d_in[17];
    float* outp = (float*)d_out;

    float *p_xn, *p_q, *p_k, *p_v, *p_att, *p_h, *p_hn, *p_f1;
    cudaGetSymbolAddress((void**)&p_xn,  g_xn);
    cudaGetSymbolAddress((void**)&p_q,   g_q);
    cudaGetSymbolAddress((void**)&p_k,   g_k);
    cudaGetSymbolAddress((void**)&p_v,   g_v);
    cudaGetSymbolAddress((void**)&p_att, g_att);
    cudaGetSymbolAddress((void**)&p_h,   g_h);
    cudaGetSymbolAddress((void**)&p_hn,  g_hn);
    cudaGetSymbolAddress((void**)&p_f1,  g_f1);

    // LN1 + lam/sp + output u-slot zeroing (fused)
    ln_kernel<true><<<MM, 128>>>(x, ln1g, ln1b, p_xn, u_prev, outp, out_size);

    qkv_kernel<<<dim3(24, MM/64), 128>>>(p_xn, wq, wk, wv, bq, bk, bv, p_q, p_k, p_v);

    attn_kernel<<<dim3(SS/64, BB*HH), 128>>>(p_q, p_k, p_v, p_att);

    gemm32<false,true><<<dim3(DDIM/64, MM/32), 128>>>(p_att, wo, bo, x, p_h, DDIM, DDIM);

    ln_kernel<false><<<MM, 128>>>(p_h, ln2g, ln2b, p_hn, nullptr, nullptr, 0);

    gemm64<true,false><<<dim3(FF/64, MM/64), 128>>>(p_hn, w1, b1, nullptr, p_f1, DDIM, FF);
    gemm32<false,true><<<dim3(DDIM/64, MM/32), 128>>>(p_f1, w2, b2, p_h, outp, FF, DDIM);

    // per-row u + fused batch mean via atomicAdd into pre-zeroed slots
    u_row_kernel<<<MM, 128>>>(outp, x, out_size);
}

// round 11
// speedup vs baseline: 1.1107x; 1.0507x over previous
#include <cuda_runtime.h>
#include <cuda_bf16.h>
#include <math.h>

#define BB 2
#define SS 1024
#define DDIM 512
#define HH 8
#define DH 64
#define FF 2048
#define MM (BB*SS)

// ---------------- scratch (no allocation allowed) ----------------
__device__ float g_xn[MM*DDIM];
__device__ float g_q [MM*DDIM];
__device__ float g_k [MM*DDIM];
__device__ float g_v [MM*DDIM];
__device__ float g_att[MM*DDIM];
__device__ float g_h [MM*DDIM];
__device__ float g_hn[MM*DDIM];
__device__ float g_f1[MM*FF];
__device__ float g_part[4*MM*DDIM];   // split-K partial slabs
__device__ float g_lam[BB];
__device__ int   g_sp [BB];

// ---------------- helpers ----------------
__device__ __forceinline__ void bsplit(float x0, float x1, unsigned &hw, unsigned &lw){
    asm("cvt.rn.bf16x2.f32 %0, %1, %2;" : "=r"(hw) : "f"(x1), "f"(x0));
    float h0 = __uint_as_float(hw << 16);
    float h1 = __uint_as_float(hw & 0xffff0000u);
    float l0 = x0 - h0, l1 = x1 - h1;
    asm("cvt.rn.bf16x2.f32 %0, %1, %2;" : "=r"(lw) : "f"(l1), "f"(l0));
}

__device__ __forceinline__ void mma16(float* c, const unsigned* a, const unsigned* b){
    asm volatile(
        "mma.sync.aligned.m16n8k16.row.col.f32.bf16.bf16.f32 "
        "{%0,%1,%2,%3}, {%4,%5,%6,%7}, {%8,%9}, {%0,%1,%2,%3};\n"
        : "+f"(c[0]), "+f"(c[1]), "+f"(c[2]), "+f"(c[3])
        : "r"(a[0]), "r"(a[1]), "r"(a[2]), "r"(a[3]), "r"(b[0]), "r"(b[1]));
}

__device__ __forceinline__ float gelu_exact(float v){
    return 0.5f * v * (1.0f + erff(v * 0.70710678118654752f));
}

// ---------------- LayerNorm1 (+lam compute / u-slot zero in block 0) ----------------
__global__ void ln1_kernel(const float* __restrict__ x, const float* __restrict__ g,
                           const float* __restrict__ be, float* __restrict__ y,
                           const float* __restrict__ u_prev, float* __restrict__ outp,
                           int out_size){
    int row = blockIdx.x;
    int t = threadIdx.x;
    if (row == 0 && t < BB){
        float lam = 10.0f * expf(-5.0f * u_prev[t]);
        g_lam[t] = lam;
        g_sp[t]  = (lam >= 1.0f) ? 1 : 0;
        int idx = MM*DDIM + t;
        if (idx < out_size) outp[idx] = 0.0f;
    }
    const float* xr = x + (size_t)row * DDIM;
    float4 v = *(const float4*)(xr + t*4);
    float s  = v.x + v.y + v.z + v.w;
    float ss = v.x*v.x + v.y*v.y + v.z*v.z + v.w*v.w;
    #pragma unroll
    for (int o = 16; o; o >>= 1){
        s  += __shfl_xor_sync(0xffffffffu, s,  o);
        ss += __shfl_xor_sync(0xffffffffu, ss, o);
    }
    __shared__ float ps[4], pss[4];
    int w = t >> 5;
    if ((t & 31) == 0){ ps[w] = s; pss[w] = ss; }
    __syncthreads();
    s  = ps[0] + ps[1] + ps[2] + ps[3];
    ss = pss[0] + pss[1] + pss[2] + pss[3];
    float mean = s * (1.0f/DDIM);
    float var  = ss * (1.0f/DDIM) - mean*mean;
    float inv  = rsqrtf(var + 1e-5f);
    float4 gv = *(const float4*)(g  + t*4);
    float4 bv = *(const float4*)(be + t*4);
    float4 o;
    o.x = (v.x - mean)*inv*gv.x + bv.x;
    o.y = (v.y - mean)*inv*gv.y + bv.y;
    o.z = (v.z - mean)*inv*gv.z + bv.z;
    o.w = (v.w - mean)*inv*gv.w + bv.w;
    *(float4*)(y + (size_t)row * DDIM + t*4) = o;
}

// ---------------- fused: h = p0+p1+x+bo ; hn = LN2(h) ----------------
__global__ void ln2_fused(const float* __restrict__ p0, const float* __restrict__ p1,
                          const float* __restrict__ x, const float* __restrict__ bo,
                          const float* __restrict__ g, const float* __restrict__ be,
                          float* __restrict__ h, float* __restrict__ hn){
    int row = blockIdx.x;
    int t = threadIdx.x;
    size_t off = (size_t)row*DDIM + t*4;
    float4 a = *(const float4*)(p0 + off);
    float4 b = *(const float4*)(p1 + off);
    float4 xv = *(const float4*)(x + off);
    float4 bv0 = *(const float4*)(bo + t*4);
    float4 v;
    v.x = a.x + b.x + xv.x + bv0.x;
    v.y = a.y + b.y + xv.y + bv0.y;
    v.z = a.z + b.z + xv.z + bv0.z;
    v.w = a.w + b.w + xv.w + bv0.w;
    *(float4*)(h + off) = v;

    float s  = v.x + v.y + v.z + v.w;
    float ss = v.x*v.x + v.y*v.y + v.z*v.z + v.w*v.w;
    #pragma unroll
    for (int o = 16; o; o >>= 1){
        s  += __shfl_xor_sync(0xffffffffu, s,  o);
        ss += __shfl_xor_sync(0xffffffffu, ss, o);
    }
    __shared__ float ps[4], pss[4];
    int w = t >> 5;
    if ((t & 31) == 0){ ps[w] = s; pss[w] = ss; }
    __syncthreads();
    s  = ps[0] + ps[1] + ps[2] + ps[3];
    ss = pss[0] + pss[1] + pss[2] + pss[3];
    float mean = s * (1.0f/DDIM);
    float var  = ss * (1.0f/DDIM) - mean*mean;
    float inv  = rsqrtf(var + 1e-5f);
    float4 gv = *(const float4*)(g  + t*4);
    float4 bv = *(const float4*)(be + t*4);
    float4 o;
    o.x = (v.x - mean)*inv*gv.x + bv.x;
    o.y = (v.y - mean)*inv*gv.y + bv.y;
    o.z = (v.z - mean)*inv*gv.z + bv.z;
    o.w = (v.w - mean)*inv*gv.w + bv.w;
    *(float4*)(hn + off) = o;
}

// ---------------- bf16x3 tensor-core GEMM body (round-4 exact) ----------------
template<int BM, bool GELU, bool RES>
__device__ __forceinline__ void gemm_body(
        const float* __restrict__ A, const float* __restrict__ W,
        const float* __restrict__ bias, const float* __restrict__ res,
        float* __restrict__ C, int Kn, int Nn, int m0, int n0){
    constexpr int MTILES = BM/16;
    constexpr int WMT    = MTILES/2;
    constexpr int AIT    = BM/16;

    __shared__ unsigned Ah[2][MTILES][32][4];
    __shared__ unsigned Al[2][MTILES][32][4];
    __shared__ unsigned Bh[2][8][32][2];
    __shared__ unsigned Bl[2][8][32][2];

    const int tid = threadIdx.x;
    const int warp = tid >> 5, ln = tid & 31;
    const int wm = warp >> 1, wn = warp & 1;
    const int gid = ln >> 2, t4 = ln & 3;

    float acc[WMT][4][4];
    #pragma unroll
    for (int mt = 0; mt < WMT; mt++)
        #pragma unroll
        for (int nt = 0; nt < 4; nt++)
            #pragma unroll
            for (int r = 0; r < 4; r++) acc[mt][nt][r] = 0.0f;

    float4 av[AIT], wv4[4];
    #pragma unroll
    for (int i = 0; i < AIT; i++){
        int f = tid + i*128;
        int row = f >> 3, kq = (f & 7) << 2;
        av[i] = *(const float4*)(A + (size_t)(m0 + row)*Kn + kq);
    }
    #pragma unroll
    for (int i = 0; i < 4; i++){
        int f = tid + i*128;
        int row = f >> 3, kq = (f & 7) << 2;
        wv4[i] = *(const float4*)(W + (size_t)(n0 + row)*Kn + kq);
    }

    for (int kt = 0; kt < Kn; kt += 32){
        __syncthreads();
        #pragma unroll
        for (int i = 0; i < AIT; i++){
            int f = tid + i*128;
            int row = f >> 3, kq = (f & 7) << 2;
            int ks = kq >> 4, kk = kq & 15;
            int mt = row >> 4, rr = row & 15;
            int slot = ((rr >> 3) & 1) + (((kk >> 3) & 1) << 1);
            int lane = (rr & 7)*4 + ((kk & 7) >> 1);
            unsigned h0, l0, h1, l1;
            bsplit(av[i].x, av[i].y, h0, l0);
            bsplit(av[i].z, av[i].w, h1, l1);
            Ah[ks][mt][lane  ][slot] = h0;
            Ah[ks][mt][lane+1][slot] = h1;
            Al[ks][mt][lane  ][slot] = l0;
            Al[ks][mt][lane+1][slot] = l1;
        }
        #pragma unroll
        for (int i = 0; i < 4; i++){
            int f = tid + i*128;
            int row = f >> 3, kq = (f & 7) << 2;
            int ks = kq >> 4, kk = kq & 15;
            int nt = row >> 3;
            int slot = (kk >> 3) & 1;
            int lane = (row & 7)*4 + ((kk & 7) >> 1);
            unsigned h0, l0, h1, l1;
            bsplit(wv4[i].x, wv4[i].y, h0, l0);
            bsplit(wv4[i].z, wv4[i].w, h1, l1);
            Bh[ks][nt][lane  ][slot] = h0;
            Bh[ks][nt][lane+1][slot] = h1;
            Bl[ks][nt][lane  ][slot] = l0;
            Bl[ks][nt][lane+1][slot] = l1;
        }
        __syncthreads();

        if (kt + 32 < Kn){
            #pragma unroll
            for (int i = 0; i < AIT; i++){
                int f = tid + i*128;
                int row = f >> 3, kq = (f & 7) << 2;
                av[i] = *(const float4*)(A + (size_t)(m0 + row)*Kn + kt + 32 + kq);
            }
            #pragma unroll
            for (int i = 0; i < 4; i++){
                int f = tid + i*128;
                int row = f >> 3, kq = (f & 7) << 2;
                wv4[i] = *(const float4*)(W + (size_t)(n0 + row)*Kn + kt + 32 + kq);
            }
        }

        #pragma unroll
        for (int ks = 0; ks < 2; ks++){
            unsigned ah[WMT][4], al[WMT][4], bh[4][2], bl[4][2];
            #pragma unroll
            for (int mt = 0; mt < WMT; mt++){
                *(uint4*)ah[mt] = *(const uint4*)Ah[ks][wm*WMT + mt][ln];
                *(uint4*)al[mt] = *(const uint4*)Al[ks][wm*WMT + mt][ln];
            }
            #pragma unroll
            for (int nt = 0; nt < 4; nt++){
                *(uint2*)bh[nt] = *(const uint2*)Bh[ks][wn*4 + nt][ln];
                *(uint2*)bl[nt] = *(const uint2*)Bl[ks][wn*4 + nt][ln];
            }
            #pragma unroll
            for (int mt = 0; mt < WMT; mt++)
                #pragma unroll
                for (int nt = 0; nt < 4; nt++){
                    mma16(acc[mt][nt], ah[mt], bh[nt]);
                    mma16(acc[mt][nt], ah[mt], bl[nt]);
                    mma16(acc[mt][nt], al[mt], bh[nt]);
                }
        }
    }

    #pragma unroll
    for (int mt = 0; mt < WMT; mt++){
        #pragma unroll
        for (int rr = 0; rr < 2; rr++){
            int m = m0 + wm*(BM/2) + mt*16 + gid + rr*8;
            #pragma unroll
            for (int nt = 0; nt < 4; nt++){
                int n = n0 + wn*32 + nt*8 + t4*2;
                float2 o;
                o.x = acc[mt][nt][rr*2 + 0];
                o.y = acc[mt][nt][rr*2 + 1];
                float2 bv = *(const float2*)(bias + n);
                o.x += bv.x; o.y += bv.y;
                if (RES){
                    float2 rv = *(const float2*)(res + (size_t)m*Nn + n);
                    o.x += rv.x; o.y += rv.y;
                }
                if (GELU){
                    o.x = gelu_exact(o.x);
                    o.y = gelu_exact(o.y);
                }
                *(float2*)(C + (size_t)m*Nn + n) = o;
            }
        }
    }
}

// ---------------- split-K GEMM (BM=32, raw partial output, no epilogue) ----------------
// Partial C_z[M,512] = A[:, z*Kloop : (z+1)*Kloop] @ W[:, same]^T
__global__ void __launch_bounds__(128)
gemm_split(const float* __restrict__ A, const float* __restrict__ W,
           float* __restrict__ Cpart, int Kn, int Kloop){
    constexpr int BM = 32;
    const int z = blockIdx.z;
    const int kbase = z * Kloop;
    const int m0 = blockIdx.y * BM;
    const int n0 = blockIdx.x * 64;
    float* Cp = Cpart + (size_t)z * MM * DDIM;

    __shared__ unsigned Ah[2][2][32][4];
    __shared__ unsigned Al[2][2][32][4];
    __shared__ unsigned Bh[2][8][32][2];
    __shared__ unsigned Bl[2][8][32][2];

    const int tid = threadIdx.x;
    const int warp = tid >> 5, ln = tid & 31;
    const int wm = warp >> 1, wn = warp & 1;
    const int gid = ln >> 2, t4 = ln & 3;

    float acc[1][4][4];
    #pragma unroll
    for (int nt = 0; nt < 4; nt++)
        #pragma unroll
        for (int r = 0; r < 4; r++) acc[0][nt][r] = 0.0f;

    float4 av[2], wv4[4];
    #pragma unroll
    for (int i = 0; i < 2; i++){
        int f = tid + i*128;
        int row = f >> 3, kq = (f & 7) << 2;
        av[i] = *(const float4*)(A + (size_t)(m0 + row)*Kn + kbase + kq);
    }
    #pragma unroll
    for (int i = 0; i < 4; i++){
        int f = tid + i*128;
        int row = f >> 3, kq = (f & 7) << 2;
        wv4[i] = *(const float4*)(W + (size_t)(n0 + row)*Kn + kbase + kq);
    }

    for (int kt = 0; kt < Kloop; kt += 32){
        __syncthreads();
        #pragma unroll
        for (int i = 0; i < 2; i++){
            int f = tid + i*128;
            int row = f >> 3, kq = (f & 7) << 2;
            int ks = kq >> 4, kk = kq & 15;
            int mt = row >> 4, rr = row & 15;
            int slot = ((rr >> 3) & 1) + (((kk >> 3) & 1) << 1);
            int lane = (rr & 7)*4 + ((kk & 7) >> 1);
            unsigned h0, l0, h1, l1;
            bsplit(av[i].x, av[i].y, h0, l0);
            bsplit(av[i].z, av[i].w, h1, l1);
            Ah[ks][mt][lane  ][slot] = h0;
            Ah[ks][mt][lane+1][slot] = h1;
            Al[ks][mt][lane  ][slot] = l0;
            Al[ks][mt][lane+1][slot] = l1;
        }
        #pragma unroll
        for (int i = 0; i < 4; i++){
            int f = tid + i*128;
            int row = f >> 3, kq = (f & 7) << 2;
            int ks = kq >> 4, kk = kq & 15;
            int nt = row >> 3;
            int slot = (kk >> 3) & 1;
            int lane = (row & 7)*4 + ((kk & 7) >> 1);
            unsigned h0, l0, h1, l1;
            bsplit(wv4[i].x, wv4[i].y, h0, l0);
            bsplit(wv4[i].z, wv4[i].w, h1, l1);
            Bh[ks][nt][lane  ][slot] = h0;
            Bh[ks][nt][lane+1][slot] = h1;
            Bl[ks][nt][lane  ][slot] = l0;
            Bl[ks][nt][lane+1][slot] = l1;
        }
        __syncthreads();

        if (kt + 32 < Kloop){
            #pragma unroll
            for (int i = 0; i < 2; i++){
                int f = tid + i*128;
                int row = f >> 3, kq = (f & 7) << 2;
                av[i] = *(const float4*)(A + (size_t)(m0 + row)*Kn + kbase + kt + 32 + kq);
            }
            #pragma unroll
            for (int i = 0; i < 4; i++){
                int f = tid + i*128;
                int row = f >> 3, kq = (f & 7) << 2;
                wv4[i] = *(const float4*)(W + (size_t)(n0 + row)*Kn + kbase + kt + 32 + kq);
            }
        }

        #pragma unroll
        for (int ks = 0; ks < 2; ks++){
            unsigned ah[4], al[4], bh[4][2], bl[4][2];
            *(uint4*)ah = *(const uint4*)Ah[ks][wm][ln];
            *(uint4*)al = *(const uint4*)Al[ks][wm][ln];
            #pragma unroll
            for (int nt = 0; nt < 4; nt++){
                *(uint2*)bh[nt] = *(const uint2*)Bh[ks][wn*4 + nt][ln];
                *(uint2*)bl[nt] = *(const uint2*)Bl[ks][wn*4 + nt][ln];
            }
            #pragma unroll
            for (int nt = 0; nt < 4; nt++){
                mma16(acc[0][nt], ah, bh[nt]);
                mma16(acc[0][nt], ah, bl[nt]);
                mma16(acc[0][nt], al, bh[nt]);
            }
        }
    }

    #pragma unroll
    for (int rr = 0; rr < 2; rr++){
        int m = m0 + wm*16 + gid + rr*8;
        #pragma unroll
        for (int nt = 0; nt < 4; nt++){
            int n = n0 + wn*32 + nt*8 + t4*2;
            float2 o;
            o.x = acc[0][nt][rr*2 + 0];
            o.y = acc[0][nt][rr*2 + 1];
            *(float2*)(Cp + (size_t)m*DDIM + n) = o;
        }
    }
}

// ---------------- GEMM kernels ----------------
__global__ void __launch_bounds__(128)
qkv_kernel(const float* __restrict__ xn,
           const float* __restrict__ wq, const float* __restrict__ wk, const float* __restrict__ wv,
           const float* __restrict__ bq, const float* __restrict__ bk, const float* __restrict__ bv,
           float* __restrict__ q, float* __restrict__ k, float* __restrict__ v){
    int sel = blockIdx.x >> 3;
    int n0 = (blockIdx.x & 7) << 6;
    const float* W    = (sel == 0) ? wq : (sel == 1) ? wk : wv;
    const float* bias = (sel == 0) ? bq : (sel == 1) ? bk : bv;
    float* C          = (sel == 0) ? q  : (sel == 1) ? k  : v;
    gemm_body<64,false,false>(xn, W, bias, nullptr, C, DDIM, DDIM, blockIdx.y*64, n0);
}

template<bool GELU, bool RES>
__global__ void __launch_bounds__(128)
gemm64(const float* __restrict__ A, const float* __restrict__ W,
       const float* __restrict__ bias, const float* __restrict__ res,
       float* __restrict__ C, int Kn, int Nn){
    gemm_body<64,GELU,RES>(A, W, bias, res, C, Kn, Nn, blockIdx.y*64, blockIdx.x*64);
}

// ---------------- tensor-core flash attention (round-4 exact) ----------------
__global__ void __launch_bounds__(128)
attn_kernel(const float* __restrict__ Q, const float* __restrict__ K,
            const float* __restrict__ V, float* __restrict__ O){
    __shared__ unsigned Kh[4][8][32][2], Kl[4][8][32][2];
    __shared__ unsigned Vh[4][8][32][2], Vl[4][8][32][2];

    const int bh = blockIdx.y;
    const int b = bh / HH, h = bh % HH;
    const int q0 = blockIdx.x * 64;
    const float lam = g_lam[b];
    const int sp = g_sp[b];
    const int tid = threadIdx.x;
    const int w = tid >> 5, ln = tid & 31;
    const int gid = ln >> 2, t4 = ln & 3;
    const int r0 = q0 + w*16 + gid;
    const int r1 = r0 + 8;

    unsigned qh[4][4], ql[4][4];
    {
        const float* Qb = Q + (size_t)(b*SS)*DDIM + h*DH;
        #pragma unroll
        for (int ks = 0; ks < 4; ks++){
            int kcol = ks*16 + t4*2;
            float2 q00 = *(const float2*)(Qb + (size_t)r0*DDIM + kcol);
            float2 q10 = *(const float2*)(Qb + (size_t)r1*DDIM + kcol);
            float2 q01 = *(const float2*)(Qb + (size_t)r0*DDIM + kcol + 8);
            float2 q11 = *(const float2*)(Qb + (size_t)r1*DDIM + kcol + 8);
            bsplit(q00.x, q00.y, qh[ks][0], ql[ks][0]);
            bsplit(q10.x, q10.y, qh[ks][1], ql[ks][1]);
            bsplit(q01.x, q01.y, qh[ks][2], ql[ks][2]);
            bsplit(q11.x, q11.y, qh[ks][3], ql[ks][3]);
        }
    }

    float oacc[8][4];
    #pragma unroll
    for (int nt = 0; nt < 8; nt++)
        #pragma unroll
        for (int r = 0; r < 4; r++) oacc[nt][r] = 0.0f;
    float mrow0 = -INFINITY, mrow1 = -INFINITY;
    float lrow0 = 0.0f, lrow1 = 0.0f;

    int klo = 0, khi = SS/64;
    if (sp){
        int lo = q0 - 51; if (lo < 0) lo = 0;
        int hi = q0 + 114; if (hi > SS-1) hi = SS-1;
        klo = lo >> 6; khi = (hi >> 6) + 1;
    }

    const float* Kb = K + (size_t)(b*SS)*DDIM + h*DH;
    const float* Vb = V + (size_t)(b*SS)*DDIM + h*DH;

    for (int kb = klo; kb < khi; kb++){
        __syncthreads();
        #pragma unroll
        for (int i = 0; i < 4; i++){
            int f = tid + i*128;
            int r = f >> 3;
            int d8 = (f & 7) * 8;
            float4 x0 = *(const float4*)(Kb + (size_t)(kb*64 + r)*DDIM + d8);
            float4 x1 = *(const float4*)(Kb + (size_t)(kb*64 + r)*DDIM + d8 + 4);
            int ks = d8 >> 4, slot = (d8 >> 3) & 1;
            int lbase = (r & 7) * 4;
            int nt = r >> 3;
            unsigned h0,l0,h1,l1,h2,l2,h3,l3;
            bsplit(x0.x, x0.y, h0, l0);
            bsplit(x0.z, x0.w, h1, l1);
            bsplit(x1.x, x1.y, h2, l2);
            bsplit(x1.z, x1.w, h3, l3);
            Kh[ks][nt][lbase+0][slot] = h0;  Kl[ks][nt][lbase+0][slot] = l0;
            Kh[ks][nt][lbase+1][slot] = h1;  Kl[ks][nt][lbase+1][slot] = l1;
            Kh[ks][nt][lbase+2][slot] = h2;  Kl[ks][nt][lbase+2][slot] = l2;
            Kh[ks][nt][lbase+3][slot] = h3;  Kl[ks][nt][lbase+3][slot] = l3;
        }
        #pragma unroll
        for (int i = 0; i < 4; i++){
            int f = tid + i*128;
            int spr = f >> 4;
            int d4 = (f & 15) * 4;
            int s = spr * 2;
            float4 x0 = *(const float4*)(Vb + (size_t)(kb*64 + s    )*DDIM + d4);
            float4 x1 = *(const float4*)(Vb + (size_t)(kb*64 + s + 1)*DDIM + d4);
            int ks = s >> 4, slot = (s >> 3) & 1;
            int tp = (s & 7) >> 1;
            float a0[4] = {x0.x, x0.y, x0.z, x0.w};
            float a1[4] = {x1.x, x1.y, x1.z, x1.w};
            #pragma unroll
            for (int j = 0; j < 4; j++){
                int d = d4 + j;
                unsigned hv, lv;
                bsplit(a0[j], a1[j], hv, lv);
                Vh[ks][d>>3][(d&7)*4 + tp][slot] = hv;
                Vl[ks][d>>3][(d&7)*4 + tp][slot] = lv;
            }
        }
        __syncthreads();

        float sfrag[8][4];
        #pragma unroll
        for (int nt = 0; nt < 8; nt++)
            #pragma unroll
            for (int r = 0; r < 4; r++) sfrag[nt][r] = 0.0f;
        #pragma unroll
        for (int ks = 0; ks < 4; ks++){
            #pragma unroll
            for (int nt = 0; nt < 8; nt++){
                unsigned kh2[2], kl2[2];
                *(uint2*)kh2 = *(const uint2*)Kh[ks][nt][ln];
                *(uint2*)kl2 = *(const uint2*)Kl[ks][nt][ln];
                mma16(sfrag[nt], qh[ks], kh2);
                mma16(sfrag[nt], qh[ks], kl2);
                mma16(sfrag[nt], ql[ks], kh2);
            }
        }

        float mx0 = -INFINITY, mx1 = -INFINITY;
        #pragma unroll
        for (int nt = 0; nt < 8; nt++){
            #pragma unroll
            for (int e = 0; e < 2; e++){
                int c = kb*64 + nt*8 + t4*2 + e;
                bool in0 = (c >= r0 - 51) && (c <= r0 + 51);
                bool in1 = (c >= r1 - 51) && (c <= r1 + 51);
                float v0 = sfrag[nt][e]   * 0.125f;
                float v1 = sfrag[nt][2+e] * 0.125f;
                if (sp){
                    v0 = in0 ? v0 : -INFINITY;
                    v1 = in1 ? v1 : -INFINITY;
                } else {
                    if (!in0) v0 -= lam;
                    if (!in1) v1 -= lam;
                }
                sfrag[nt][e]   = v0;
                sfrag[nt][2+e] = v1;
                mx0 = fmaxf(mx0, v0);
                mx1 = fmaxf(mx1, v1);
            }
        }
        #pragma unroll
        for (int o = 1; o <= 2; o <<= 1){
            mx0 = fmaxf(mx0, __shfl_xor_sync(0xffffffffu, mx0, o));
            mx1 = fmaxf(mx1, __shfl_xor_sync(0xffffffffu, mx1, o));
        }
        float mnew0 = fmaxf(mrow0, mx0);
        float mnew1 = fmaxf(mrow1, mx1);
        float sf0 = (mrow0 == mnew0) ? 1.0f : __expf(mrow0 - mnew0);
        float sf1 = (mrow1 == mnew1) ? 1.0f : __expf(mrow1 - mnew1);
        float mc0 = fmaxf(mnew0, -1e30f);
        float mc1 = fmaxf(mnew1, -1e30f);
        float rs0 = 0.0f, rs1 = 0.0f;
        #pragma unroll
        for (int nt = 0; nt < 8; nt++){
            #pragma unroll
            for (int e = 0; e < 2; e++){
                float p0 = __expf(sfrag[nt][e]   - mc0);
                float p1 = __expf(sfrag[nt][2+e] - mc1);
                sfrag[nt][e]   = p0;
                sfrag[nt][2+e] = p1;
                rs0 += p0; rs1 += p1;
            }
        }
        #pragma unroll
        for (int o = 1; o <= 2; o <<= 1){
            rs0 += __shfl_xor_sync(0xffffffffu, rs0, o);
            rs1 += __shfl_xor_sync(0xffffffffu, rs1, o);
        }
        lrow0 = lrow0 * sf0 + rs0;  mrow0 = mnew0;
        lrow1 = lrow1 * sf1 + rs1;  mrow1 = mnew1;
        #pragma unroll
        for (int nt = 0; nt < 8; nt++){
            oacc[nt][0] *= sf0; oacc[nt][1] *= sf0;
            oacc[nt][2] *= sf1; oacc[nt][3] *= sf1;
        }

        #pragma unroll
        for (int pks = 0; pks < 4; pks++){
            unsigned pah[4], pal[4];
            bsplit(sfrag[2*pks  ][0], sfrag[2*pks  ][1], pah[0], pal[0]);
            bsplit(sfrag[2*pks  ][2], sfrag[2*pks  ][3], pah[1], pal[1]);
            bsplit(sfrag[2*pks+1][0], sfrag[2*pks+1][1], pah[2], pal[2]);
            bsplit(sfrag[2*pks+1][2], sfrag[2*pks+1][3], pah[3], pal[3]);
            #pragma unroll
            for (int nt = 0; nt < 8; nt++){
                unsigned vh2[2], vl2[2];
                *(uint2*)vh2 = *(const uint2*)Vh[pks][nt][ln];
                *(uint2*)vl2 = *(const uint2*)Vl[pks][nt][ln];
                mma16(oacc[nt], pah, vh2);
                mma16(oacc[nt], pah, vl2);
                mma16(oacc[nt], pal, vh2);
            }
        }
    }

    float inv0 = 1.0f / lrow0;
    float inv1 = 1.0f / lrow1;
    float* Ob = O + (size_t)(b*SS)*DDIM + h*DH;
    #pragma unroll
    for (int nt = 0; nt < 8; nt++){
        int d = nt*8 + t4*2;
        float2 o0, o1;
        o0.x = oacc[nt][0]*inv0; o0.y = oacc[nt][1]*inv0;
        o1.x = oacc[nt][2]*inv1; o1.y = oacc[nt][3]*inv1;
        *(float2*)(Ob + (size_t)r0*DDIM + d) = o0;
        *(float2*)(Ob + (size_t)r1*DDIM + d) = o1;
    }
}

// ---------------- final: out = p0+p1+p2+p3 + b2 + h ; u per-row + batch mean ----------------
__global__ void u_final(const float* __restrict__ p0, const float* __restrict__ p1,
                        const float* __restrict__ p2, const float* __restrict__ p3,
                        const float* __restrict__ b2, const float* __restrict__ hres,
                        const float* __restrict__ x, float* __restrict__ outp,
                        int out_size){
    int row = blockIdx.x;
    int t = threadIdx.x;
    size_t off = (size_t)row*DDIM + t*4;
    float4 a0 = *(const float4*)(p0 + off);
    float4 a1 = *(const float4*)(p1 + off);
    float4 a2 = *(const float4*)(p2 + off);
    float4 a3 = *(const float4*)(p3 + off);
    float4 bv = *(const float4*)(b2 + t*4);
    float4 hv = *(const float4*)(hres + off);
    float4 o;
    o.x = a0.x + a1.x + a2.x + a3.x + bv.x + hv.x;
    o.y = a0.y + a1.y + a2.y + a3.y + bv.y + hv.y;
    o.z = a0.z + a1.z + a2.z + a3.z + bv.z + hv.z;
    o.w = a0.w + a1.w + a2.w + a3.w + bv.w + hv.w;
    *(float4*)(outp + off) = o;

    float4 xv = *(const float4*)(x + off);
    float dx = o.x - xv.x, dy = o.y - xv.y, dz = o.z - xv.z, dw = o.w - xv.w;
    float d2 = dx*dx + dy*dy + dz*dz + dw*dw;
    float x2 = xv.x*xv.x + xv.y*xv.y + xv.z*xv.z + xv.w*xv.w;
    #pragma unroll
    for (int o2 = 16; o2; o2 >>= 1){
        d2 += __shfl_xor_sync(0xffffffffu, d2, o2);
        x2 += __shfl_xor_sync(0xffffffffu, x2, o2);
    }
    __shared__ float pd[4], px[4];
    int w = t >> 5;
    if ((t & 31) == 0){ pd[w] = d2; px[w] = x2; }
    __syncthreads();
    if (t == 0){
        d2 = pd[0]+pd[1]+pd[2]+pd[3];
        x2 = px[0]+px[1]+px[2]+px[3];
        float u = sqrtf(d2) / (sqrtf(x2) + 1e-8f);
        int b = row >> 10;
        int idx = MM*DDIM + b;
        if (idx < out_size) atomicAdd(outp + idx, u * (1.0f/SS));
    }
}

// ---------------- launch ----------------
extern "C" void kernel_launch(void* const* d_in, const int* in_sizes, int n_in,
                              void* d_out, int out_size){
    const float* x      = (const float*)d_in[0];
    const float* u_prev = (const float*)d_in[1];
    const float* wq = (const float*)d_in[2];  const float* bq = (const float*)d_in[3];
    const float* wk = (const float*)d_in[4];  const float* bk = (const float*)d_in[5];
    const float* wv = (const float*)d_in[6];  const float* bv = (const float*)d_in[7];
    const float* wo = (const float*)d_in[8];  const float* bo = (const float*)d_in[9];
    const float* ln1g = (const float*)d_in[10]; const float* ln1b = (const float*)d_in[11];
    const float* ln2g = (const float*)d_in[12]; const float* ln2b = (const float*)d_in[13];
    const float* w1 = (const float*)d_in[14]; const float* b1 = (const float*)d_in[15];
    const float* w2 = (const float*)d_in[16]; const float* b2 = (const float*)d_in[17];
    float* outp = (float*)d_out;

    float *p_xn, *p_q, *p_k, *p_v, *p_att, *p_h, *p_hn, *p_f1, *p_part;
    cudaGetSymbolAddress((void**)&p_xn,  g_xn);
    cudaGetSymbolAddress((void**)&p_q,   g_q);
    cudaGetSymbolAddress((void**)&p_k,   g_k);
    cudaGetSymbolAddress((void**)&p_v,   g_v);
    cudaGetSymbolAddress((void**)&p_att, g_att);
    cudaGetSymbolAddress((void**)&p_h,   g_h);
    cudaGetSymbolAddress((void**)&p_hn,  g_hn);
    cudaGetSymbolAddress((void**)&p_f1,  g_f1);
    cudaGetSymbolAddress((void**)&p_part,g_part);

    const size_t slab = (size_t)MM * DDIM;

    // LN1 + lam/sp + output u-slot zeroing (fused)
    ln1_kernel<<<MM, 128>>>(x, ln1g, ln1b, p_xn, u_prev, outp, out_size);

    qkv_kernel<<<dim3(24, MM/64), 128>>>(p_xn, wq, wk, wv, bq, bk, bv, p_q, p_k, p_v);

    attn_kernel<<<dim3(SS/64, BB*HH), 128>>>(p_q, p_k, p_v, p_att);

    // Wo: split-K x2 -> partials (slabs 0,1)
    gemm_split<<<dim3(DDIM/64, MM/32, 2), 128>>>(p_att, wo, p_part, DDIM, DDIM/2);

    // fused: h = p0+p1+x+bo ; hn = LN2(h)
    ln2_fused<<<MM, 128>>>(p_part, p_part + slab, x, bo, ln2g, ln2b, p_h, p_hn);

    gemm64<true,false><<<dim3(FF/64, MM/64), 128>>>(p_hn, w1, b1, nullptr, p_f1, DDIM, FF);

    // FFN2: split-K x4 -> partials (slabs 0..3)
    gemm_split<<<dim3(DDIM/64, MM/32, 4), 128>>>(p_f1, w2, p_part, FF, FF/4);

    // final: out = sum(partials) + b2 + h ; u per-row + batch mean (atomic)
    u_final<<<MM, 128>>>(p_part, p_part + slab, p_part + 2*slab, p_part + 3*slab,
                         b2, p_h, x, outp, out_size);
}

// round 12
// speedup vs baseline: 1.1915x; 1.0727x over previous
#include <cuda_runtime.h>
#include <cuda_bf16.h>
#include <math.h>

#define BB 2
#define SS 1024
#define DDIM 512
#define HH 8
#define DH 64
#define FF 2048
#define MM (BB*SS)

// ---------------- scratch (no allocation allowed) ----------------
__device__ float g_xn[MM*DDIM];
__device__ float g_att[MM*DDIM];
__device__ float g_h [MM*DDIM];
__device__ float g_hn[MM*DDIM];
__device__ float g_f1[MM*FF];
__device__ float g_part[6*MM*DDIM];   // split-K partial slabs (q0,q1,k0,k1,v0,v1 / reused later)
__device__ float g_lam[BB];
__device__ int   g_sp [BB];

// ---------------- helpers ----------------
__device__ __forceinline__ void bsplit(float x0, float x1, unsigned &hw, unsigned &lw){
    asm("cvt.rn.bf16x2.f32 %0, %1, %2;" : "=r"(hw) : "f"(x1), "f"(x0));
    float h0 = __uint_as_float(hw << 16);
    float h1 = __uint_as_float(hw & 0xffff0000u);
    float l0 = x0 - h0, l1 = x1 - h1;
    asm("cvt.rn.bf16x2.f32 %0, %1, %2;" : "=r"(lw) : "f"(l1), "f"(l0));
}

__device__ __forceinline__ void mma16(float* c, const unsigned* a, const unsigned* b){
    asm volatile(
        "mma.sync.aligned.m16n8k16.row.col.f32.bf16.bf16.f32 "
        "{%0,%1,%2,%3}, {%4,%5,%6,%7}, {%8,%9}, {%0,%1,%2,%3};\n"
        : "+f"(c[0]), "+f"(c[1]), "+f"(c[2]), "+f"(c[3])
        : "r"(a[0]), "r"(a[1]), "r"(a[2]), "r"(a[3]), "r"(b[0]), "r"(b[1]));
}

__device__ __forceinline__ float gelu_exact(float v){
    return 0.5f * v * (1.0f + erff(v * 0.70710678118654752f));
}

// ---------------- LayerNorm1 (+lam compute / u-slot zero in block 0) ----------------
__global__ void ln1_kernel(const float* __restrict__ x, const float* __restrict__ g,
                           const float* __restrict__ be, float* __restrict__ y,
                           const float* __restrict__ u_prev, float* __restrict__ outp,
                           int out_size){
    int row = blockIdx.x;
    int t = threadIdx.x;
    if (row == 0 && t < BB){
        float lam = 10.0f * expf(-5.0f * u_prev[t]);
        g_lam[t] = lam;
        g_sp[t]  = (lam >= 1.0f) ? 1 : 0;
        int idx = MM*DDIM + t;
        if (idx < out_size) outp[idx] = 0.0f;
    }
    const float* xr = x + (size_t)row * DDIM;
    float4 v = *(const float4*)(xr + t*4);
    float s  = v.x + v.y + v.z + v.w;
    float ss = v.x*v.x + v.y*v.y + v.z*v.z + v.w*v.w;
    #pragma unroll
    for (int o = 16; o; o >>= 1){
        s  += __shfl_xor_sync(0xffffffffu, s,  o);
        ss += __shfl_xor_sync(0xffffffffu, ss, o);
    }
    __shared__ float ps[4], pss[4];
    int w = t >> 5;
    if ((t & 31) == 0){ ps[w] = s; pss[w] = ss; }
    __syncthreads();
    s  = ps[0] + ps[1] + ps[2] + ps[3];
    ss = pss[0] + pss[1] + pss[2] + pss[3];
    float mean = s * (1.0f/DDIM);
    float var  = ss * (1.0f/DDIM) - mean*mean;
    float inv  = rsqrtf(var + 1e-5f);
    float4 gv = *(const float4*)(g  + t*4);
    float4 bv = *(const float4*)(be + t*4);
    float4 o;
    o.x = (v.x - mean)*inv*gv.x + bv.x;
    o.y = (v.y - mean)*inv*gv.y + bv.y;
    o.z = (v.z - mean)*inv*gv.z + bv.z;
    o.w = (v.w - mean)*inv*gv.w + bv.w;
    *(float4*)(y + (size_t)row * DDIM + t*4) = o;
}

// ---------------- fused: h = p0+p1+x+bo ; hn = LN2(h) ----------------
__global__ void ln2_fused(const float* __restrict__ p0, const float* __restrict__ p1,
                          const float* __restrict__ x, const float* __restrict__ bo,
                          const float* __restrict__ g, const float* __restrict__ be,
                          float* __restrict__ h, float* __restrict__ hn){
    int row = blockIdx.x;
    int t = threadIdx.x;
    size_t off = (size_t)row*DDIM + t*4;
    float4 a = *(const float4*)(p0 + off);
    float4 b = *(const float4*)(p1 + off);
    float4 xv = *(const float4*)(x + off);
    float4 bv0 = *(const float4*)(bo + t*4);
    float4 v;
    v.x = a.x + b.x + xv.x + bv0.x;
    v.y = a.y + b.y + xv.y + bv0.y;
    v.z = a.z + b.z + xv.z + bv0.z;
    v.w = a.w + b.w + xv.w + bv0.w;
    *(float4*)(h + off) = v;

    float s  = v.x + v.y + v.z + v.w;
    float ss = v.x*v.x + v.y*v.y + v.z*v.z + v.w*v.w;
    #pragma unroll
    for (int o = 16; o; o >>= 1){
        s  += __shfl_xor_sync(0xffffffffu, s,  o);
        ss += __shfl_xor_sync(0xffffffffu, ss, o);
    }
    __shared__ float ps[4], pss[4];
    int w = t >> 5;
    if ((t & 31) == 0){ ps[w] = s; pss[w] = ss; }
    __syncthreads();
    s  = ps[0] + ps[1] + ps[2] + ps[3];
    ss = pss[0] + pss[1] + pss[2] + pss[3];
    float mean = s * (1.0f/DDIM);
    float var  = ss * (1.0f/DDIM) - mean*mean;
    float inv  = rsqrtf(var + 1e-5f);
    float4 gv = *(const float4*)(g  + t*4);
    float4 bv = *(const float4*)(be + t*4);
    float4 o;
    o.x = (v.x - mean)*inv*gv.x + bv.x;
    o.y = (v.y - mean)*inv*gv.y + bv.y;
    o.z = (v.z - mean)*inv*gv.z + bv.z;
    o.w = (v.w - mean)*inv*gv.w + bv.w;
    *(float4*)(hn + off) = o;
}

// ---------------- bf16x3 GEMM body (full-K, with epilogue) ----------------
template<int BM, bool GELU, bool RES>
__device__ __forceinline__ void gemm_body(
        const float* __restrict__ A, const float* __restrict__ W,
        const float* __restrict__ bias, const float* __restrict__ res,
        float* __restrict__ C, int Kn, int Nn, int m0, int n0){
    constexpr int MTILES = BM/16;
    constexpr int WMT    = MTILES/2;
    constexpr int AIT    = BM/16;

    __shared__ unsigned Ah[2][MTILES][32][4];
    __shared__ unsigned Al[2][MTILES][32][4];
    __shared__ unsigned Bh[2][8][32][2];
    __shared__ unsigned Bl[2][8][32][2];

    const int tid = threadIdx.x;
    const int warp = tid >> 5, ln = tid & 31;
    const int wm = warp >> 1, wn = warp & 1;
    const int gid = ln >> 2, t4 = ln & 3;

    float acc[WMT][4][4];
    #pragma unroll
    for (int mt = 0; mt < WMT; mt++)
        #pragma unroll
        for (int nt = 0; nt < 4; nt++)
            #pragma unroll
            for (int r = 0; r < 4; r++) acc[mt][nt][r] = 0.0f;

    float4 av[AIT], wv4[4];
    #pragma unroll
    for (int i = 0; i < AIT; i++){
        int f = tid + i*128;
        int row = f >> 3, kq = (f & 7) << 2;
        av[i] = *(const float4*)(A + (size_t)(m0 + row)*Kn + kq);
    }
    #pragma unroll
    for (int i = 0; i < 4; i++){
        int f = tid + i*128;
        int row = f >> 3, kq = (f & 7) << 2;
        wv4[i] = *(const float4*)(W + (size_t)(n0 + row)*Kn + kq);
    }

    for (int kt = 0; kt < Kn; kt += 32){
        __syncthreads();
        #pragma unroll
        for (int i = 0; i < AIT; i++){
            int f = tid + i*128;
            int row = f >> 3, kq = (f & 7) << 2;
            int ks = kq >> 4, kk = kq & 15;
            int mt = row >> 4, rr = row & 15;
            int slot = ((rr >> 3) & 1) + (((kk >> 3) & 1) << 1);
            int lane = (rr & 7)*4 + ((kk & 7) >> 1);
            unsigned h0, l0, h1, l1;
            bsplit(av[i].x, av[i].y, h0, l0);
            bsplit(av[i].z, av[i].w, h1, l1);
            Ah[ks][mt][lane  ][slot] = h0;
            Ah[ks][mt][lane+1][slot] = h1;
            Al[ks][mt][lane  ][slot] = l0;
            Al[ks][mt][lane+1][slot] = l1;
        }
        #pragma unroll
        for (int i = 0; i < 4; i++){
            int f = tid + i*128;
            int row = f >> 3, kq = (f & 7) << 2;
            int ks = kq >> 4, kk = kq & 15;
            int nt = row >> 3;
            int slot = (kk >> 3) & 1;
            int lane = (row & 7)*4 + ((kk & 7) >> 1);
            unsigned h0, l0, h1, l1;
            bsplit(wv4[i].x, wv4[i].y, h0, l0);
            bsplit(wv4[i].z, wv4[i].w, h1, l1);
            Bh[ks][nt][lane  ][slot] = h0;
            Bh[ks][nt][lane+1][slot] = h1;
            Bl[ks][nt][lane  ][slot] = l0;
            Bl[ks][nt][lane+1][slot] = l1;
        }
        __syncthreads();

        if (kt + 32 < Kn){
            #pragma unroll
            for (int i = 0; i < AIT; i++){
                int f = tid + i*128;
                int row = f >> 3, kq = (f & 7) << 2;
                av[i] = *(const float4*)(A + (size_t)(m0 + row)*Kn + kt + 32 + kq);
            }
            #pragma unroll
            for (int i = 0; i < 4; i++){
                int f = tid + i*128;
                int row = f >> 3, kq = (f & 7) << 2;
                wv4[i] = *(const float4*)(W + (size_t)(n0 + row)*Kn + kt + 32 + kq);
            }
        }

        #pragma unroll
        for (int ks = 0; ks < 2; ks++){
            unsigned ah[WMT][4], al[WMT][4], bh[4][2], bl[4][2];
            #pragma unroll
            for (int mt = 0; mt < WMT; mt++){
                *(uint4*)ah[mt] = *(const uint4*)Ah[ks][wm*WMT + mt][ln];
                *(uint4*)al[mt] = *(const uint4*)Al[ks][wm*WMT + mt][ln];
            }
            #pragma unroll
            for (int nt = 0; nt < 4; nt++){
                *(uint2*)bh[nt] = *(const uint2*)Bh[ks][wn*4 + nt][ln];
                *(uint2*)bl[nt] = *(const uint2*)Bl[ks][wn*4 + nt][ln];
            }
            #pragma unroll
            for (int mt = 0; mt < WMT; mt++)
                #pragma unroll
                for (int nt = 0; nt < 4; nt++){
                    mma16(acc[mt][nt], ah[mt], bh[nt]);
                    mma16(acc[mt][nt], ah[mt], bl[nt]);
                    mma16(acc[mt][nt], al[mt], bh[nt]);
                }
        }
    }

    #pragma unroll
    for (int mt = 0; mt < WMT; mt++){
        #pragma unroll
        for (int rr = 0; rr < 2; rr++){
            int m = m0 + wm*(BM/2) + mt*16 + gid + rr*8;
            #pragma unroll
            for (int nt = 0; nt < 4; nt++){
                int n = n0 + wn*32 + nt*8 + t4*2;
                float2 o;
                o.x = acc[mt][nt][rr*2 + 0];
                o.y = acc[mt][nt][rr*2 + 1];
                float2 bv = *(const float2*)(bias + n);
                o.x += bv.x; o.y += bv.y;
                if (RES){
                    float2 rv = *(const float2*)(res + (size_t)m*Nn + n);
                    o.x += rv.x; o.y += rv.y;
                }
                if (GELU){
                    o.x = gelu_exact(o.x);
                    o.y = gelu_exact(o.y);
                }
                *(float2*)(C + (size_t)m*Nn + n) = o;
            }
        }
    }
}

// ---------------- split-K GEMM body (raw partial output, N stride = DDIM) ----------------
template<int BM>
__device__ __forceinline__ void gemm_split_body(
        const float* __restrict__ A, const float* __restrict__ W,
        float* __restrict__ Cp, int Kn, int Kloop, int kbase, int m0, int n0){
    constexpr int MTILES = BM/16;
    constexpr int WMT    = MTILES/2;
    constexpr int AIT    = BM/16;

    __shared__ unsigned Ah[2][MTILES][32][4];
    __shared__ unsigned Al[2][MTILES][32][4];
    __shared__ unsigned Bh[2][8][32][2];
    __shared__ unsigned Bl[2][8][32][2];

    const int tid = threadIdx.x;
    const int warp = tid >> 5, ln = tid & 31;
    const int wm = warp >> 1, wn = warp & 1;
    const int gid = ln >> 2, t4 = ln & 3;

    float acc[WMT][4][4];
    #pragma unroll
    for (int mt = 0; mt < WMT; mt++)
        #pragma unroll
        for (int nt = 0; nt < 4; nt++)
            #pragma unroll
            for (int r = 0; r < 4; r++) acc[mt][nt][r] = 0.0f;

    float4 av[AIT], wv4[4];
    #pragma unroll
    for (int i = 0; i < AIT; i++){
        int f = tid + i*128;
        int row = f >> 3, kq = (f & 7) << 2;
        av[i] = *(const float4*)(A + (size_t)(m0 + row)*Kn + kbase + kq);
    }
    #pragma unroll
    for (int i = 0; i < 4; i++){
        int f = tid + i*128;
        int row = f >> 3, kq = (f & 7) << 2;
        wv4[i] = *(const float4*)(W + (size_t)(n0 + row)*Kn + kbase + kq);
    }

    for (int kt = 0; kt < Kloop; kt += 32){
        __syncthreads();
        #pragma unroll
        for (int i = 0; i < AIT; i++){
            int f = tid + i*128;
            int row = f >> 3, kq = (f & 7) << 2;
            int ks = kq >> 4, kk = kq & 15;
            int mt = row >> 4, rr = row & 15;
            int slot = ((rr >> 3) & 1) + (((kk >> 3) & 1) << 1);
            int lane = (rr & 7)*4 + ((kk & 7) >> 1);
            unsigned h0, l0, h1, l1;
            bsplit(av[i].x, av[i].y, h0, l0);
            bsplit(av[i].z, av[i].w, h1, l1);
            Ah[ks][mt][lane  ][slot] = h0;
            Ah[ks][mt][lane+1][slot] = h1;
            Al[ks][mt][lane  ][slot] = l0;
            Al[ks][mt][lane+1][slot] = l1;
        }
        #pragma unroll
        for (int i = 0; i < 4; i++){
            int f = tid + i*128;
            int row = f >> 3, kq = (f & 7) << 2;
            int ks = kq >> 4, kk = kq & 15;
            int nt = row >> 3;
            int slot = (kk >> 3) & 1;
            int lane = (row & 7)*4 + ((kk & 7) >> 1);
            unsigned h0, l0, h1, l1;
            bsplit(wv4[i].x, wv4[i].y, h0, l0);
            bsplit(wv4[i].z, wv4[i].w, h1, l1);
            Bh[ks][nt][lane  ][slot] = h0;
            Bh[ks][nt][lane+1][slot] = h1;
            Bl[ks][nt][lane  ][slot] = l0;
            Bl[ks][nt][lane+1][slot] = l1;
        }
        __syncthreads();

        if (kt + 32 < Kloop){
            #pragma unroll
            for (int i = 0; i < AIT; i++){
                int f = tid + i*128;
                int row = f >> 3, kq = (f & 7) << 2;
                av[i] = *(const float4*)(A + (size_t)(m0 + row)*Kn + kbase + kt + 32 + kq);
            }
            #pragma unroll
            for (int i = 0; i < 4; i++){
                int f = tid + i*128;
                int row = f >> 3, kq = (f & 7) << 2;
                wv4[i] = *(const float4*)(W + (size_t)(n0 + row)*Kn + kbase + kt + 32 + kq);
            }
        }

        #pragma unroll
        for (int ks = 0; ks < 2; ks++){
            unsigned ah[WMT][4], al[WMT][4], bh[4][2], bl[4][2];
            #pragma unroll
            for (int mt = 0; mt < WMT; mt++){
                *(uint4*)ah[mt] = *(const uint4*)Ah[ks][wm*WMT + mt][ln];
                *(uint4*)al[mt] = *(const uint4*)Al[ks][wm*WMT + mt][ln];
            }
            #pragma unroll
            for (int nt = 0; nt < 4; nt++){
                *(uint2*)bh[nt] = *(const uint2*)Bh[ks][wn*4 + nt][ln];
                *(uint2*)bl[nt] = *(const uint2*)Bl[ks][wn*4 + nt][ln];
            }
            #pragma unroll
            for (int mt = 0; mt < WMT; mt++)
                #pragma unroll
                for (int nt = 0; nt < 4; nt++){
                    mma16(acc[mt][nt], ah[mt], bh[nt]);
                    mma16(acc[mt][nt], ah[mt], bl[nt]);
                    mma16(acc[mt][nt], al[mt], bh[nt]);
                }
        }
    }

    #pragma unroll
    for (int mt = 0; mt < WMT; mt++){
        #pragma unroll
        for (int rr = 0; rr < 2; rr++){
            int m = m0 + wm*(BM/2) + mt*16 + gid + rr*8;
            #pragma unroll
            for (int nt = 0; nt < 4; nt++){
                int n = n0 + wn*32 + nt*8 + t4*2;
                float2 o;
                o.x = acc[mt][nt][rr*2 + 0];
                o.y = acc[mt][nt][rr*2 + 1];
                *(float2*)(Cp + (size_t)m*DDIM + n) = o;
            }
        }
    }
}

// ---------------- split-K kernels ----------------
// QKV split-K x2: x = sel(3)*8 + ntile(8), y = mtile(32, BM=64), z = ksplit(2)
__global__ void __launch_bounds__(128)
qkv_split(const float* __restrict__ xn,
          const float* __restrict__ wq, const float* __restrict__ wk, const float* __restrict__ wv,
          float* __restrict__ part){
    int sel = blockIdx.x >> 3;
    int n0  = (blockIdx.x & 7) << 6;
    int z   = blockIdx.z;
    const float* W = (sel == 0) ? wq : (sel == 1) ? wk : wv;
    float* Cp = part + (size_t)(sel*2 + z) * MM * DDIM;
    gemm_split_body<64>(xn, W, Cp, DDIM, DDIM/2, z*(DDIM/2), blockIdx.y*64, n0);
}

// generic split (Wo: BM=32, FFN2: BM=64)
template<int BM>
__global__ void __launch_bounds__(128)
gemm_split(const float* __restrict__ A, const float* __restrict__ W,
           float* __restrict__ Cpart, int Kn, int Kloop){
    float* Cp = Cpart + (size_t)blockIdx.z * MM * DDIM;
    gemm_split_body<BM>(A, W, Cp, Kn, Kloop, blockIdx.z*Kloop, blockIdx.y*BM, blockIdx.x*64);
}

// ---------------- full-K GEMM kernel (FFN1) ----------------
template<bool GELU, bool RES>
__global__ void __launch_bounds__(128)
gemm64(const float* __restrict__ A, const float* __restrict__ W,
       const float* __restrict__ bias, const float* __restrict__ res,
       float* __restrict__ C, int Kn, int Nn){
    gemm_body<64,GELU,RES>(A, W, bias, res, C, Kn, Nn, blockIdx.y*64, blockIdx.x*64);
}

// ---------------- tensor-core flash attention (fused QKV partial reduction + bias) ----------------
__global__ void __launch_bounds__(128, 3)
attn_kernel(const float* __restrict__ q0, const float* __restrict__ q1,
            const float* __restrict__ k0, const float* __restrict__ k1,
            const float* __restrict__ v0, const float* __restrict__ v1,
            const float* __restrict__ bq, const float* __restrict__ bk,
            const float* __restrict__ bv, float* __restrict__ O){
    __shared__ unsigned Kh[4][8][32][2], Kl[4][8][32][2];
    __shared__ unsigned Vh[4][8][32][2], Vl[4][8][32][2];

    const int bh = blockIdx.y;
    const int b = bh / HH, h = bh % HH;
    const int q0i = blockIdx.x * 64;
    const float lam = g_lam[b];
    const int sp = g_sp[b];
    const int tid = threadIdx.x;
    const int w = tid >> 5, ln = tid & 31;
    const int gid = ln >> 2, t4 = ln & 3;
    const int r0 = q0i + w*16 + gid;
    const int r1 = r0 + 8;

    // persistent Q fragments: sum partials + bias, then split
    unsigned qh[4][4], ql[4][4];
    {
        const float* Q0 = q0 + (size_t)(b*SS)*DDIM + h*DH;
        const float* Q1 = q1 + (size_t)(b*SS)*DDIM + h*DH;
        const float* bqh = bq + h*DH;
        #pragma unroll
        for (int ks = 0; ks < 4; ks++){
            int kcol = ks*16 + t4*2;
            float2 b0 = *(const float2*)(bqh + kcol);
            float2 b1 = *(const float2*)(bqh + kcol + 8);
            float2 a00 = *(const float2*)(Q0 + (size_t)r0*DDIM + kcol);
            float2 c00 = *(const float2*)(Q1 + (size_t)r0*DDIM + kcol);
            float2 a10 = *(const float2*)(Q0 + (size_t)r1*DDIM + kcol);
            float2 c10 = *(const float2*)(Q1 + (size_t)r1*DDIM + kcol);
            float2 a01 = *(const float2*)(Q0 + (size_t)r0*DDIM + kcol + 8);
            float2 c01 = *(const float2*)(Q1 + (size_t)r0*DDIM + kcol + 8);
            float2 a11 = *(const float2*)(Q0 + (size_t)r1*DDIM + kcol + 8);
            float2 c11 = *(const float2*)(Q1 + (size_t)r1*DDIM + kcol + 8);
            bsplit(a00.x + c00.x + b0.x, a00.y + c00.y + b0.y, qh[ks][0], ql[ks][0]);
            bsplit(a10.x + c10.x + b0.x, a10.y + c10.y + b0.y, qh[ks][1], ql[ks][1]);
            bsplit(a01.x + c01.x + b1.x, a01.y + c01.y + b1.y, qh[ks][2], ql[ks][2]);
            bsplit(a11.x + c11.x + b1.x, a11.y + c11.y + b1.y, qh[ks][3], ql[ks][3]);
        }
    }

    float oacc[8][4];
    #pragma unroll
    for (int nt = 0; nt < 8; nt++)
        #pragma unroll
        for (int r = 0; r < 4; r++) oacc[nt][r] = 0.0f;
    float mrow0 = -INFINITY, mrow1 = -INFINITY;
    float lrow0 = 0.0f, lrow1 = 0.0f;

    int klo = 0, khi = SS/64;
    if (sp){
        int lo = q0i - 51; if (lo < 0) lo = 0;
        int hi = q0i + 114; if (hi > SS-1) hi = SS-1;
        klo = lo >> 6; khi = (hi >> 6) + 1;
    }

    const float* K0 = k0 + (size_t)(b*SS)*DDIM + h*DH;
    const float* K1 = k1 + (size_t)(b*SS)*DDIM + h*DH;
    const float* V0 = v0 + (size_t)(b*SS)*DDIM + h*DH;
    const float* V1 = v1 + (size_t)(b*SS)*DDIM + h*DH;
    const float* bkh = bk + h*DH;
    const float* bvh = bv + h*DH;

    for (int kb = klo; kb < khi; kb++){
        __syncthreads();
        // stage K tile: sum partials + bias
        #pragma unroll
        for (int i = 0; i < 4; i++){
            int f = tid + i*128;
            int r = f >> 3;
            int d8 = (f & 7) * 8;
            size_t ro = (size_t)(kb*64 + r)*DDIM + d8;
            float4 x0 = *(const float4*)(K0 + ro);
            float4 y0 = *(const float4*)(K1 + ro);
            float4 bb0 = *(const float4*)(bkh + d8);
            float4 x1 = *(const float4*)(K0 + ro + 4);
            float4 y1 = *(const float4*)(K1 + ro + 4);
            float4 bb1 = *(const float4*)(bkh + d8 + 4);
            x0.x += y0.x + bb0.x; x0.y += y0.y + bb0.y;
            x0.z += y0.z + bb0.z; x0.w += y0.w + bb0.w;
            x1.x += y1.x + bb1.x; x1.y += y1.y + bb1.y;
            x1.z += y1.z + bb1.z; x1.w += y1.w + bb1.w;
            int ks = d8 >> 4, slot = (d8 >> 3) & 1;
            int lbase = (r & 7) * 4;
            int nt = r >> 3;
            unsigned h0,l0,h1,l1,h2,l2,h3,l3;
            bsplit(x0.x, x0.y, h0, l0);
            bsplit(x0.z, x0.w, h1, l1);
            bsplit(x1.x, x1.y, h2, l2);
            bsplit(x1.z, x1.w, h3, l3);
            Kh[ks][nt][lbase+0][slot] = h0;  Kl[ks][nt][lbase+0][slot] = l0;
            Kh[ks][nt][lbase+1][slot] = h1;  Kl[ks][nt][lbase+1][slot] = l1;
            Kh[ks][nt][lbase+2][slot] = h2;  Kl[ks][nt][lbase+2][slot] = l2;
            Kh[ks][nt][lbase+3][slot] = h3;  Kl[ks][nt][lbase+3][slot] = l3;
        }
        // stage V tile transposed: sum partials + bias
        #pragma unroll
        for (int i = 0; i < 4; i++){
            int f = tid + i*128;
            int spr = f >> 4;
            int d4 = (f & 15) * 4;
            int s = spr * 2;
            size_t ro0 = (size_t)(kb*64 + s    )*DDIM + d4;
            size_t ro1 = (size_t)(kb*64 + s + 1)*DDIM + d4;
            float4 x0 = *(const float4*)(V0 + ro0);
            float4 y0 = *(const float4*)(V1 + ro0);
            float4 x1 = *(const float4*)(V0 + ro1);
            float4 y1 = *(const float4*)(V1 + ro1);
            float4 bb = *(const float4*)(bvh + d4);
            float a0[4] = {x0.x+y0.x+bb.x, x0.y+y0.y+bb.y, x0.z+y0.z+bb.z, x0.w+y0.w+bb.w};
            float a1[4] = {x1.x+y1.x+bb.x, x1.y+y1.y+bb.y, x1.z+y1.z+bb.z, x1.w+y1.w+bb.w};
            int ks = s >> 4, slot = (s >> 3) & 1;
            int tp = (s & 7) >> 1;
            #pragma unroll
            for (int j = 0; j < 4; j++){
                int d = d4 + j;
                unsigned hv, lv;
                bsplit(a0[j], a1[j], hv, lv);
                Vh[ks][d>>3][(d&7)*4 + tp][slot] = hv;
                Vl[ks][d>>3][(d&7)*4 + tp][slot] = lv;
            }
        }
        __syncthreads();

        float sfrag[8][4];
        #pragma unroll
        for (int nt = 0; nt < 8; nt++)
            #pragma unroll
            for (int r = 0; r < 4; r++) sfrag[nt][r] = 0.0f;
        #pragma unroll
        for (int ks = 0; ks < 4; ks++){
            #pragma unroll
            for (int nt = 0; nt < 8; nt++){
                unsigned kh2[2], kl2[2];
                *(uint2*)kh2 = *(const uint2*)Kh[ks][nt][ln];
                *(uint2*)kl2 = *(const uint2*)Kl[ks][nt][ln];
                mma16(sfrag[nt], qh[ks], kh2);
                mma16(sfrag[nt], qh[ks], kl2);
                mma16(sfrag[nt], ql[ks], kh2);
            }
        }

        float mx0 = -INFINITY, mx1 = -INFINITY;
        #pragma unroll
        for (int nt = 0; nt < 8; nt++){
            #pragma unroll
            for (int e = 0; e < 2; e++){
                int c = kb*64 + nt*8 + t4*2 + e;
                bool in0 = (c >= r0 - 51) && (c <= r0 + 51);
                bool in1 = (c >= r1 - 51) && (c <= r1 + 51);
                float vv0 = sfrag[nt][e]   * 0.125f;
                float vv1 = sfrag[nt][2+e] * 0.125f;
                if (sp){
                    vv0 = in0 ? vv0 : -INFINITY;
                    vv1 = in1 ? vv1 : -INFINITY;
                } else {
                    if (!in0) vv0 -= lam;
                    if (!in1) vv1 -= lam;
                }
                sfrag[nt][e]   = vv0;
                sfrag[nt][2+e] = vv1;
                mx0 = fmaxf(mx0, vv0);
                mx1 = fmaxf(mx1, vv1);
            }
        }
        #pragma unroll
        for (int o = 1; o <= 2; o <<= 1){
            mx0 = fmaxf(mx0, __shfl_xor_sync(0xffffffffu, mx0, o));
            mx1 = fmaxf(mx1, __shfl_xor_sync(0xffffffffu, mx1, o));
        }
        float mnew0 = fmaxf(mrow0, mx0);
        float mnew1 = fmaxf(mrow1, mx1);
        float sf0 = (mrow0 == mnew0) ? 1.0f : __expf(mrow0 - mnew0);
        float sf1 = (mrow1 == mnew1) ? 1.0f : __expf(mrow1 - mnew1);
        float mc0 = fmaxf(mnew0, -1e30f);
        float mc1 = fmaxf(mnew1, -1e30f);
        float rs0 = 0.0f, rs1 = 0.0f;
        #pragma unroll
        for (int nt = 0; nt < 8; nt++){
            #pragma unroll
            for (int e = 0; e < 2; e++){
                float p0 = __expf(sfrag[nt][e]   - mc0);
                float p1 = __expf(sfrag[nt][2+e] - mc1);
                sfrag[nt][e]   = p0;
                sfrag[nt][2+e] = p1;
                rs0 += p0; rs1 += p1;
            }
        }
        #pragma unroll
        for (int o = 1; o <= 2; o <<= 1){
            rs0 += __shfl_xor_sync(0xffffffffu, rs0, o);
            rs1 += __shfl_xor_sync(0xffffffffu, rs1, o);
        }
        lrow0 = lrow0 * sf0 + rs0;  mrow0 = mnew0;
        lrow1 = lrow1 * sf1 + rs1;  mrow1 = mnew1;
        #pragma unroll
        for (int nt = 0; nt < 8; nt++){
            oacc[nt][0] *= sf0; oacc[nt][1] *= sf0;
            oacc[nt][2] *= sf1; oacc[nt][3] *= sf1;
        }

        #pragma unroll
        for (int pks = 0; pks < 4; pks++){
            unsigned pah[4], pal[4];
            bsplit(sfrag[2*pks  ][0], sfrag[2*pks  ][1], pah[0], pal[0]);
            bsplit(sfrag[2*pks  ][2], sfrag[2*pks  ][3], pah[1], pal[1]);
            bsplit(sfrag[2*pks+1][0], sfrag[2*pks+1][1], pah[2], pal[2]);
            bsplit(sfrag[2*pks+1][2], sfrag[2*pks+1][3], pah[3], pal[3]);
            #pragma unroll
            for (int nt = 0; nt < 8; nt++){
                unsigned vh2[2], vl2[2];
                *(uint2*)vh2 = *(const uint2*)Vh[pks][nt][ln];
                *(uint2*)vl2 = *(const uint2*)Vl[pks][nt][ln];
                mma16(oacc[nt], pah, vh2);
                mma16(oacc[nt], pah, vl2);
                mma16(oacc[nt], pal, vh2);
            }
        }
    }

    float inv0 = 1.0f / lrow0;
    float inv1 = 1.0f / lrow1;
    float* Ob = O + (size_t)(b*SS)*DDIM + h*DH;
    #pragma unroll
    for (int nt = 0; nt < 8; nt++){
        int d = nt*8 + t4*2;
        float2 o0, o1;
        o0.x = oacc[nt][0]*inv0; o0.y = oacc[nt][1]*inv0;
        o1.x = oacc[nt][2]*inv1; o1.y = oacc[nt][3]*inv1;
        *(float2*)(Ob + (size_t)r0*DDIM + d) = o0;
        *(float2*)(Ob + (size_t)r1*DDIM + d) = o1;
    }
}

// ---------------- final: out = p0+p1+p2+p3 + b2 + h ; u per-row + batch mean ----------------
__global__ void u_final(const float* __restrict__ p0, const float* __restrict__ p1,
                        const float* __restrict__ p2, const float* __restrict__ p3,
                        const float* __restrict__ b2, const float* __restrict__ hres,
                        const float* __restrict__ x, float* __restrict__ outp,
                        int out_size){
    int row = blockIdx.x;
    int t = threadIdx.x;
    size_t off = (size_t)row*DDIM + t*4;
    float4 a0 = *(const float4*)(p0 + off);
    float4 a1 = *(const float4*)(p1 + off);
    float4 a2 = *(const float4*)(p2 + off);
    float4 a3 = *(const float4*)(p3 + off);
    float4 bv = *(const float4*)(b2 + t*4);
    float4 hv = *(const float4*)(hres + off);
    float4 o;
    o.x = a0.x + a1.x + a2.x + a3.x + bv.x + hv.x;
    o.y = a0.y + a1.y + a2.y + a3.y + bv.y + hv.y;
    o.z = a0.z + a1.z + a2.z + a3.z + bv.z + hv.z;
    o.w = a0.w + a1.w + a2.w + a3.w + bv.w + hv.w;
    *(float4*)(outp + off) = o;

    float4 xv = *(const float4*)(x + off);
    float dx = o.x - xv.x, dy = o.y - xv.y, dz = o.z - xv.z, dw = o.w - xv.w;
    float d2 = dx*dx + dy*dy + dz*dz + dw*dw;
    float x2 = xv.x*xv.x + xv.y*xv.y + xv.z*xv.z + xv.w*xv.w;
    #pragma unroll
    for (int o2 = 16; o2; o2 >>= 1){
        d2 += __shfl_xor_sync(0xffffffffu, d2, o2);
        x2 += __shfl_xor_sync(0xffffffffu, x2, o2);
    }
    __shared__ float pd[4], px[4];
    int w = t >> 5;
    if ((t & 31) == 0){ pd[w] = d2; px[w] = x2; }
    __syncthreads();
    if (t == 0){
        d2 = pd[0]+pd[1]+pd[2]+pd[3];
        x2 = px[0]+px[1]+px[2]+px[3];
        float u = sqrtf(d2) / (sqrtf(x2) + 1e-8f);
        int b = row >> 10;
        int idx = MM*DDIM + b;
        if (idx < out_size) atomicAdd(outp + idx, u * (1.0f/SS));
    }
}

// ---------------- launch ----------------
extern "C" void kernel_launch(void* const* d_in, const int* in_sizes, int n_in,
                              void* d_out, int out_size){
    const float* x      = (const float*)d_in[0];
    const float* u_prev = (const float*)d_in[1];
    const float* wq = (const float*)d_in[2];  const float* bq = (const float*)d_in[3];
    const float* wk = (const float*)d_in[4];  const float* bk = (const float*)d_in[5];
    const float* wv = (const float*)d_in[6];  const float* bv = (const float*)d_in[7];
    const float* wo = (const float*)d_in[8];  const float* bo = (const float*)d_in[9];
    const float* ln1g = (const float*)d_in[10]; const float* ln1b = (const float*)d_in[11];
    const float* ln2g = (const float*)d_in[12]; const float* ln2b = (const float*)d_in[13];
    const float* w1 = (const float*)d_in[14]; const float* b1 = (const float*)d_in[15];
    const float* w2 = (const float*)d_in[16]; const float* b2 = (const float*)d_in[17];
    float* outp = (float*)d_out;

    float *p_xn, *p_att, *p_h, *p_hn, *p_f1, *p_part;
    cudaGetSymbolAddress((void**)&p_xn,  g_xn);
    cudaGetSymbolAddress((void**)&p_att, g_att);
    cudaGetSymbolAddress((void**)&p_h,   g_h);
    cudaGetSymbolAddress((void**)&p_hn,  g_hn);
    cudaGetSymbolAddress((void**)&p_f1,  g_f1);
    cudaGetSymbolAddress((void**)&p_part,g_part);

    const size_t slab = (size_t)MM * DDIM;

    // LN1 + lam/sp + output u-slot zeroing (fused)
    ln1_kernel<<<MM, 128>>>(x, ln1g, ln1b, p_xn, u_prev, outp, out_size);

    // QKV split-K x2 -> 6 partial slabs (q0,q1,k0,k1,v0,v1)
    qkv_split<<<dim3(24, MM/64, 2), 128>>>(p_xn, wq, wk, wv, p_part);

    // attention with fused partial reduction + bias
    attn_kernel<<<dim3(SS/64, BB*HH), 128>>>(
        p_part,            p_part + slab,
        p_part + 2*slab,   p_part + 3*slab,
        p_part + 4*slab,   p_part + 5*slab,
        bq, bk, bv, p_att);

    // Wo: split-K x2 (BM=32) -> partial slabs 0,1 (qkv partials already consumed)
    gemm_split<32><<<dim3(DDIM/64, MM/32, 2), 128>>>(p_att, wo, p_part, DDIM, DDIM/2);

    // fused: h = p0+p1+x+bo ; hn = LN2(h)
    ln2_fused<<<MM, 128>>>(p_part, p_part + slab, x, bo, ln2g, ln2b, p_h, p_hn);

    // FFN1 (full-K, GELU epilogue)
    gemm64<true,false><<<dim3(FF/64, MM/64), 128>>>(p_hn, w1, b1, nullptr, p_f1, DDIM, FF);

    // FFN2: split-K x4 (BM=64) -> partial slabs 0..3
    gemm_split<64><<<dim3(DDIM/64, MM/64, 4), 128>>>(p_f1, w2, p_part, FF, FF/4);

    // final: out = sum(partials) + b2 + h ; u per-row + batch mean (atomic)
    u_final<<<MM, 128>>>(p_part, p_part + slab, p_part + 2*slab, p_part + 3*slab,
                         b2, p_h, x, outp, out_size);
}

// round 13
// speedup vs baseline: 1.2005x; 1.0076x over previous
#include <cuda_runtime.h>
#include <cuda_bf16.h>
#include <math.h>

#define BB 2
#define SS 1024
#define DDIM 512
#define HH 8
#define DH 64
#define FF 2048
#define MM (BB*SS)

// ---------------- scratch (no allocation allowed) ----------------
__device__ float g_xn[MM*DDIM];
__device__ float g_att[MM*DDIM];
__device__ float g_h [MM*DDIM];
__device__ float g_hn[MM*DDIM];
__device__ float g_f1[MM*FF];
__device__ float g_part[8*MM*DDIM];   // split-K partial slabs
__device__ float g_lam[BB];
__device__ int   g_sp [BB];

// ---------------- helpers ----------------
__device__ __forceinline__ void bsplit(float x0, float x1, unsigned &hw, unsigned &lw){
    asm("cvt.rn.bf16x2.f32 %0, %1, %2;" : "=r"(hw) : "f"(x1), "f"(x0));
    float h0 = __uint_as_float(hw << 16);
    float h1 = __uint_as_float(hw & 0xffff0000u);
    float l0 = x0 - h0, l1 = x1 - h1;
    asm("cvt.rn.bf16x2.f32 %0, %1, %2;" : "=r"(lw) : "f"(l1), "f"(l0));
}

__device__ __forceinline__ void mma16(float* c, const unsigned* a, const unsigned* b){
    asm volatile(
        "mma.sync.aligned.m16n8k16.row.col.f32.bf16.bf16.f32 "
        "{%0,%1,%2,%3}, {%4,%5,%6,%7}, {%8,%9}, {%0,%1,%2,%3};\n"
        : "+f"(c[0]), "+f"(c[1]), "+f"(c[2]), "+f"(c[3])
        : "r"(a[0]), "r"(a[1]), "r"(a[2]), "r"(a[3]), "r"(b[0]), "r"(b[1]));
}

__device__ __forceinline__ float gelu_exact(float v){
    return 0.5f * v * (1.0f + erff(v * 0.70710678118654752f));
}

// ---------------- LayerNorm1 (+lam compute / u-slot zero in block 0) ----------------
__global__ void ln1_kernel(const float* __restrict__ x, const float* __restrict__ g,
                           const float* __restrict__ be, float* __restrict__ y,
                           const float* __restrict__ u_prev, float* __restrict__ outp,
                           int out_size){
    int row = blockIdx.x;
    int t = threadIdx.x;
    if (row == 0 && t < BB){
        float lam = 10.0f * expf(-5.0f * u_prev[t]);
        g_lam[t] = lam;
        g_sp[t]  = (lam >= 1.0f) ? 1 : 0;
        int idx = MM*DDIM + t;
        if (idx < out_size) outp[idx] = 0.0f;
    }
    const float* xr = x + (size_t)row * DDIM;
    float4 v = *(const float4*)(xr + t*4);
    float s  = v.x + v.y + v.z + v.w;
    float ss = v.x*v.x + v.y*v.y + v.z*v.z + v.w*v.w;
    #pragma unroll
    for (int o = 16; o; o >>= 1){
        s  += __shfl_xor_sync(0xffffffffu, s,  o);
        ss += __shfl_xor_sync(0xffffffffu, ss, o);
    }
    __shared__ float ps[4], pss[4];
    int w = t >> 5;
    if ((t & 31) == 0){ ps[w] = s; pss[w] = ss; }
    __syncthreads();
    s  = ps[0] + ps[1] + ps[2] + ps[3];
    ss = pss[0] + pss[1] + pss[2] + pss[3];
    float mean = s * (1.0f/DDIM);
    float var  = ss * (1.0f/DDIM) - mean*mean;
    float inv  = rsqrtf(var + 1e-5f);
    float4 gv = *(const float4*)(g  + t*4);
    float4 bv = *(const float4*)(be + t*4);
    float4 o;
    o.x = (v.x - mean)*inv*gv.x + bv.x;
    o.y = (v.y - mean)*inv*gv.y + bv.y;
    o.z = (v.z - mean)*inv*gv.z + bv.z;
    o.w = (v.w - mean)*inv*gv.w + bv.w;
    *(float4*)(y + (size_t)row * DDIM + t*4) = o;
}

// ---------------- fused: h = p0+p1+p2+p3+x+bo ; hn = LN2(h) ----------------
__global__ void ln2_fused(const float* __restrict__ p0, const float* __restrict__ p1,
                          const float* __restrict__ p2, const float* __restrict__ p3,
                          const float* __restrict__ x, const float* __restrict__ bo,
                          const float* __restrict__ g, const float* __restrict__ be,
                          float* __restrict__ h, float* __restrict__ hn){
    int row = blockIdx.x;
    int t = threadIdx.x;
    size_t off = (size_t)row*DDIM + t*4;
    float4 a0 = *(const float4*)(p0 + off);
    float4 a1 = *(const float4*)(p1 + off);
    float4 a2 = *(const float4*)(p2 + off);
    float4 a3 = *(const float4*)(p3 + off);
    float4 xv = *(const float4*)(x + off);
    float4 bv0 = *(const float4*)(bo + t*4);
    float4 v;
    v.x = a0.x + a1.x + a2.x + a3.x + xv.x + bv0.x;
    v.y = a0.y + a1.y + a2.y + a3.y + xv.y + bv0.y;
    v.z = a0.z + a1.z + a2.z + a3.z + xv.z + bv0.z;
    v.w = a0.w + a1.w + a2.w + a3.w + xv.w + bv0.w;
    *(float4*)(h + off) = v;

    float s  = v.x + v.y + v.z + v.w;
    float ss = v.x*v.x + v.y*v.y + v.z*v.z + v.w*v.w;
    #pragma unroll
    for (int o = 16; o; o >>= 1){
        s  += __shfl_xor_sync(0xffffffffu, s,  o);
        ss += __shfl_xor_sync(0xffffffffu, ss, o);
    }
    __shared__ float ps[4], pss[4];
    int w = t >> 5;
    if ((t & 31) == 0){ ps[w] = s; pss[w] = ss; }
    __syncthreads();
    s  = ps[0] + ps[1] + ps[2] + ps[3];
    ss = pss[0] + pss[1] + pss[2] + pss[3];
    float mean = s * (1.0f/DDIM);
    float var  = ss * (1.0f/DDIM) - mean*mean;
    float inv  = rsqrtf(var + 1e-5f);
    float4 gv = *(const float4*)(g  + t*4);
    float4 bv = *(const float4*)(be + t*4);
    float4 o;
    o.x = (v.x - mean)*inv*gv.x + bv.x;
    o.y = (v.y - mean)*inv*gv.y + bv.y;
    o.z = (v.z - mean)*inv*gv.z + bv.z;
    o.w = (v.w - mean)*inv*gv.w + bv.w;
    *(float4*)(hn + off) = o;
}

// ---------------- bf16x3 GEMM body (full-K, with epilogue) ----------------
template<int BM, bool GELU, bool RES>
__device__ __forceinline__ void gemm_body(
        const float* __restrict__ A, const float* __restrict__ W,
        const float* __restrict__ bias, const float* __restrict__ res,
        float* __restrict__ C, int Kn, int Nn, int m0, int n0){
    constexpr int MTILES = BM/16;
    constexpr int WMT    = MTILES/2;
    constexpr int AIT    = BM/16;

    __shared__ unsigned Ah[2][MTILES][32][4];
    __shared__ unsigned Al[2][MTILES][32][4];
    __shared__ unsigned Bh[2][8][32][2];
    __shared__ unsigned Bl[2][8][32][2];

    const int tid = threadIdx.x;
    const int warp = tid >> 5, ln = tid & 31;
    const int wm = warp >> 1, wn = warp & 1;
    const int gid = ln >> 2, t4 = ln & 3;

    float acc[WMT][4][4];
    #pragma unroll
    for (int mt = 0; mt < WMT; mt++)
        #pragma unroll
        for (int nt = 0; nt < 4; nt++)
            #pragma unroll
            for (int r = 0; r < 4; r++) acc[mt][nt][r] = 0.0f;

    float4 av[AIT], wv4[4];
    #pragma unroll
    for (int i = 0; i < AIT; i++){
        int f = tid + i*128;
        int row = f >> 3, kq = (f & 7) << 2;
        av[i] = *(const float4*)(A + (size_t)(m0 + row)*Kn + kq);
    }
    #pragma unroll
    for (int i = 0; i < 4; i++){
        int f = tid + i*128;
        int row = f >> 3, kq = (f & 7) << 2;
        wv4[i] = *(const float4*)(W + (size_t)(n0 + row)*Kn + kq);
    }

    for (int kt = 0; kt < Kn; kt += 32){
        __syncthreads();
        #pragma unroll
        for (int i = 0; i < AIT; i++){
            int f = tid + i*128;
            int row = f >> 3, kq = (f & 7) << 2;
            int ks = kq >> 4, kk = kq & 15;
            int mt = row >> 4, rr = row & 15;
            int slot = ((rr >> 3) & 1) + (((kk >> 3) & 1) << 1);
            int lane = (rr & 7)*4 + ((kk & 7) >> 1);
            unsigned h0, l0, h1, l1;
            bsplit(av[i].x, av[i].y, h0, l0);
            bsplit(av[i].z, av[i].w, h1, l1);
            Ah[ks][mt][lane  ][slot] = h0;
            Ah[ks][mt][lane+1][slot] = h1;
            Al[ks][mt][lane  ][slot] = l0;
            Al[ks][mt][lane+1][slot] = l1;
        }
        #pragma unroll
        for (int i = 0; i < 4; i++){
            int f = tid + i*128;
            int row = f >> 3, kq = (f & 7) << 2;
            int ks = kq >> 4, kk = kq & 15;
            int nt = row >> 3;
            int slot = (kk >> 3) & 1;
            int lane = (row & 7)*4 + ((kk & 7) >> 1);
            unsigned h0, l0, h1, l1;
            bsplit(wv4[i].x, wv4[i].y, h0, l0);
            bsplit(wv4[i].z, wv4[i].w, h1, l1);
            Bh[ks][nt][lane  ][slot] = h0;
            Bh[ks][nt][lane+1][slot] = h1;
            Bl[ks][nt][lane  ][slot] = l0;
            Bl[ks][nt][lane+1][slot] = l1;
        }
        __syncthreads();

        if (kt + 32 < Kn){
            #pragma unroll
            for (int i = 0; i < AIT; i++){
                int f = tid + i*128;
                int row = f >> 3, kq = (f & 7) << 2;
                av[i] = *(const float4*)(A + (size_t)(m0 + row)*Kn + kt + 32 + kq);
            }
            #pragma unroll
            for (int i = 0; i < 4; i++){
                int f = tid + i*128;
                int row = f >> 3, kq = (f & 7) << 2;
                wv4[i] = *(const float4*)(W + (size_t)(n0 + row)*Kn + kt + 32 + kq);
            }
        }

        #pragma unroll
        for (int ks = 0; ks < 2; ks++){
            unsigned ah[WMT][4], al[WMT][4], bh[4][2], bl[4][2];
            #pragma unroll
            for (int mt = 0; mt < WMT; mt++){
                *(uint4*)ah[mt] = *(const uint4*)Ah[ks][wm*WMT + mt][ln];
                *(uint4*)al[mt] = *(const uint4*)Al[ks][wm*WMT + mt][ln];
            }
            #pragma unroll
            for (int nt = 0; nt < 4; nt++){
                *(uint2*)bh[nt] = *(const uint2*)Bh[ks][wn*4 + nt][ln];
                *(uint2*)bl[nt] = *(const uint2*)Bl[ks][wn*4 + nt][ln];
            }
            #pragma unroll
            for (int mt = 0; mt < WMT; mt++)
                #pragma unroll
                for (int nt = 0; nt < 4; nt++){
                    mma16(acc[mt][nt], ah[mt], bh[nt]);
                    mma16(acc[mt][nt], ah[mt], bl[nt]);
                    mma16(acc[mt][nt], al[mt], bh[nt]);
                }
        }
    }

    #pragma unroll
    for (int mt = 0; mt < WMT; mt++){
        #pragma unroll
        for (int rr = 0; rr < 2; rr++){
            int m = m0 + wm*(BM/2) + mt*16 + gid + rr*8;
            #pragma unroll
            for (int nt = 0; nt < 4; nt++){
                int n = n0 + wn*32 + nt*8 + t4*2;
                float2 o;
                o.x = acc[mt][nt][rr*2 + 0];
                o.y = acc[mt][nt][rr*2 + 1];
                float2 bv = *(const float2*)(bias + n);
                o.x += bv.x; o.y += bv.y;
                if (RES){
                    float2 rv = *(const float2*)(res + (size_t)m*Nn + n);
                    o.x += rv.x; o.y += rv.y;
                }
                if (GELU){
                    o.x = gelu_exact(o.x);
                    o.y = gelu_exact(o.y);
                }
                *(float2*)(C + (size_t)m*Nn + n) = o;
            }
        }
    }
}

// ---------------- split-K GEMM body (raw partial output, N stride = DDIM) ----------------
template<int BM>
__device__ __forceinline__ void gemm_split_body(
        const float* __restrict__ A, const float* __restrict__ W,
        float* __restrict__ Cp, int Kn, int Kloop, int kbase, int m0, int n0){
    constexpr int MTILES = BM/16;
    constexpr int WMT    = MTILES/2;
    constexpr int AIT    = BM/16;

    __shared__ unsigned Ah[2][MTILES][32][4];
    __shared__ unsigned Al[2][MTILES][32][4];
    __shared__ unsigned Bh[2][8][32][2];
    __shared__ unsigned Bl[2][8][32][2];

    const int tid = threadIdx.x;
    const int warp = tid >> 5, ln = tid & 31;
    const int wm = warp >> 1, wn = warp & 1;
    const int gid = ln >> 2, t4 = ln & 3;

    float acc[WMT][4][4];
    #pragma unroll
    for (int mt = 0; mt < WMT; mt++)
        #pragma unroll
        for (int nt = 0; nt < 4; nt++)
            #pragma unroll
            for (int r = 0; r < 4; r++) acc[mt][nt][r] = 0.0f;

    float4 av[AIT], wv4[4];
    #pragma unroll
    for (int i = 0; i < AIT; i++){
        int f = tid + i*128;
        int row = f >> 3, kq = (f & 7) << 2;
        av[i] = *(const float4*)(A + (size_t)(m0 + row)*Kn + kbase + kq);
    }
    #pragma unroll
    for (int i = 0; i < 4; i++){
        int f = tid + i*128;
        int row = f >> 3, kq = (f & 7) << 2;
        wv4[i] = *(const float4*)(W + (size_t)(n0 + row)*Kn + kbase + kq);
    }

    for (int kt = 0; kt < Kloop; kt += 32){
        __syncthreads();
        #pragma unroll
        for (int i = 0; i < AIT; i++){
            int f = tid + i*128;
            int row = f >> 3, kq = (f & 7) << 2;
            int ks = kq >> 4, kk = kq & 15;
            int mt = row >> 4, rr = row & 15;
            int slot = ((rr >> 3) & 1) + (((kk >> 3) & 1) << 1);
            int lane = (rr & 7)*4 + ((kk & 7) >> 1);
            unsigned h0, l0, h1, l1;
            bsplit(av[i].x, av[i].y, h0, l0);
            bsplit(av[i].z, av[i].w, h1, l1);
            Ah[ks][mt][lane  ][slot] = h0;
            Ah[ks][mt][lane+1][slot] = h1;
            Al[ks][mt][lane  ][slot] = l0;
            Al[ks][mt][lane+1][slot] = l1;
        }
        #pragma unroll
        for (int i = 0; i < 4; i++){
            int f = tid + i*128;
            int row = f >> 3, kq = (f & 7) << 2;
            int ks = kq >> 4, kk = kq & 15;
            int nt = row >> 3;
            int slot = (kk >> 3) & 1;
            int lane = (row & 7)*4 + ((kk & 7) >> 1);
            unsigned h0, l0, h1, l1;
            bsplit(wv4[i].x, wv4[i].y, h0, l0);
            bsplit(wv4[i].z, wv4[i].w, h1, l1);
            Bh[ks][nt][lane  ][slot] = h0;
            Bh[ks][nt][lane+1][slot] = h1;
            Bl[ks][nt][lane  ][slot] = l0;
            Bl[ks][nt][lane+1][slot] = l1;
        }
        __syncthreads();

        if (kt + 32 < Kloop){
            #pragma unroll
            for (int i = 0; i < AIT; i++){
                int f = tid + i*128;
                int row = f >> 3, kq = (f & 7) << 2;
                av[i] = *(const float4*)(A + (size_t)(m0 + row)*Kn + kbase + kt + 32 + kq);
            }
            #pragma unroll
            for (int i = 0; i < 4; i++){
                int f = tid + i*128;
                int row = f >> 3, kq = (f & 7) << 2;
                wv4[i] = *(const float4*)(W + (size_t)(n0 + row)*Kn + kbase + kt + 32 + kq);
            }
        }

        #pragma unroll
        for (int ks = 0; ks < 2; ks++){
            unsigned ah[WMT][4], al[WMT][4], bh[4][2], bl[4][2];
            #pragma unroll
            for (int mt = 0; mt < WMT; mt++){
                *(uint4*)ah[mt] = *(const uint4*)Ah[ks][wm*WMT + mt][ln];
                *(uint4*)al[mt] = *(const uint4*)Al[ks][wm*WMT + mt][ln];
            }
            #pragma unroll
            for (int nt = 0; nt < 4; nt++){
                *(uint2*)bh[nt] = *(const uint2*)Bh[ks][wn*4 + nt][ln];
                *(uint2*)bl[nt] = *(const uint2*)Bl[ks][wn*4 + nt][ln];
            }
            #pragma unroll
            for (int mt = 0; mt < WMT; mt++)
                #pragma unroll
                for (int nt = 0; nt < 4; nt++){
                    mma16(acc[mt][nt], ah[mt], bh[nt]);
                    mma16(acc[mt][nt], ah[mt], bl[nt]);
                    mma16(acc[mt][nt], al[mt], bh[nt]);
                }
        }
    }

    #pragma unroll
    for (int mt = 0; mt < WMT; mt++){
        #pragma unroll
        for (int rr = 0; rr < 2; rr++){
            int m = m0 + wm*(BM/2) + mt*16 + gid + rr*8;
            #pragma unroll
            for (int nt = 0; nt < 4; nt++){
                int n = n0 + wn*32 + nt*8 + t4*2;
                float2 o;
                o.x = acc[mt][nt][rr*2 + 0];
                o.y = acc[mt][nt][rr*2 + 1];
                *(float2*)(Cp + (size_t)m*DDIM + n) = o;
            }
        }
    }
}

// ---------------- split-K kernels ----------------
// QKV split-K x2: x = sel(3)*8 + ntile(8), y = mtile(32, BM=64), z = ksplit(2)
__global__ void __launch_bounds__(128)
qkv_split(const float* __restrict__ xn,
          const float* __restrict__ wq, const float* __restrict__ wk, const float* __restrict__ wv,
          float* __restrict__ part){
    int sel = blockIdx.x >> 3;
    int n0  = (blockIdx.x & 7) << 6;
    int z   = blockIdx.z;
    const float* W = (sel == 0) ? wq : (sel == 1) ? wk : wv;
    float* Cp = part + (size_t)(sel*2 + z) * MM * DDIM;
    gemm_split_body<64>(xn, W, Cp, DDIM, DDIM/2, z*(DDIM/2), blockIdx.y*64, n0);
}

// generic split (BM=64)
__global__ void __launch_bounds__(128)
gemm_split64(const float* __restrict__ A, const float* __restrict__ W,
             float* __restrict__ Cpart, int Kn, int Kloop){
    float* Cp = Cpart + (size_t)blockIdx.z * MM * DDIM;
    gemm_split_body<64>(A, W, Cp, Kn, Kloop, blockIdx.z*Kloop, blockIdx.y*64, blockIdx.x*64);
}

// ---------------- full-K GEMM kernel (FFN1) ----------------
template<bool GELU, bool RES>
__global__ void __launch_bounds__(128)
gemm64(const float* __restrict__ A, const float* __restrict__ W,
       const float* __restrict__ bias, const float* __restrict__ res,
       float* __restrict__ C, int Kn, int Nn){
    gemm_body<64,GELU,RES>(A, W, bias, res, C, Kn, Nn, blockIdx.y*64, blockIdx.x*64);
}

// ---------------- tensor-core flash attention (fused QKV partial reduction + bias) ----------------
__global__ void __launch_bounds__(128, 3)
attn_kernel(const float* __restrict__ q0, const float* __restrict__ q1,
            const float* __restrict__ k0, const float* __restrict__ k1,
            const float* __restrict__ v0, const float* __restrict__ v1,
            const float* __restrict__ bq, const float* __restrict__ bk,
            const float* __restrict__ bv, float* __restrict__ O){
    __shared__ unsigned Kh[4][8][32][2], Kl[4][8][32][2];
    __shared__ unsigned Vh[4][8][32][2], Vl[4][8][32][2];

    const int bh = blockIdx.y;
    const int b = bh / HH, h = bh % HH;
    const int q0i = blockIdx.x * 64;
    const float lam = g_lam[b];
    const int sp = g_sp[b];
    const int tid = threadIdx.x;
    const int w = tid >> 5, ln = tid & 31;
    const int gid = ln >> 2, t4 = ln & 3;
    const int r0 = q0i + w*16 + gid;
    const int r1 = r0 + 8;

    unsigned qh[4][4], ql[4][4];
    {
        const float* Q0 = q0 + (size_t)(b*SS)*DDIM + h*DH;
        const float* Q1 = q1 + (size_t)(b*SS)*DDIM + h*DH;
        const float* bqh = bq + h*DH;
        #pragma unroll
        for (int ks = 0; ks < 4; ks++){
            int kcol = ks*16 + t4*2;
            float2 b0 = *(const float2*)(bqh + kcol);
            float2 b1 = *(const float2*)(bqh + kcol + 8);
            float2 a00 = *(const float2*)(Q0 + (size_t)r0*DDIM + kcol);
            float2 c00 = *(const float2*)(Q1 + (size_t)r0*DDIM + kcol);
            float2 a10 = *(const float2*)(Q0 + (size_t)r1*DDIM + kcol);
            float2 c10 = *(const float2*)(Q1 + (size_t)r1*DDIM + kcol);
            float2 a01 = *(const float2*)(Q0 + (size_t)r0*DDIM + kcol + 8);
            float2 c01 = *(const float2*)(Q1 + (size_t)r0*DDIM + kcol + 8);
            float2 a11 = *(const float2*)(Q0 + (size_t)r1*DDIM + kcol + 8);
            float2 c11 = *(const float2*)(Q1 + (size_t)r1*DDIM + kcol + 8);
            bsplit(a00.x + c00.x + b0.x, a00.y + c00.y + b0.y, qh[ks][0], ql[ks][0]);
            bsplit(a10.x + c10.x + b0.x, a10.y + c10.y + b0.y, qh[ks][1], ql[ks][1]);
            bsplit(a01.x + c01.x + b1.x, a01.y + c01.y + b1.y, qh[ks][2], ql[ks][2]);
            bsplit(a11.x + c11.x + b1.x, a11.y + c11.y + b1.y, qh[ks][3], ql[ks][3]);
        }
    }

    float oacc[8][4];
    #pragma unroll
    for (int nt = 0; nt < 8; nt++)
        #pragma unroll
        for (int r = 0; r < 4; r++) oacc[nt][r] = 0.0f;
    float mrow0 = -INFINITY, mrow1 = -INFINITY;
    float lrow0 = 0.0f, lrow1 = 0.0f;

    int klo = 0, khi = SS/64;
    if (sp){
        int lo = q0i - 51; if (lo < 0) lo = 0;
        int hi = q0i + 114; if (hi > SS-1) hi = SS-1;
        klo = lo >> 6; khi = (hi >> 6) + 1;
    }

    const float* K0 = k0 + (size_t)(b*SS)*DDIM + h*DH;
    const float* K1 = k1 + (size_t)(b*SS)*DDIM + h*DH;
    const float* V0 = v0 + (size_t)(b*SS)*DDIM + h*DH;
    const float* V1 = v1 + (size_t)(b*SS)*DDIM + h*DH;
    const float* bkh = bk + h*DH;
    const float* bvh = bv + h*DH;

    for (int kb = klo; kb < khi; kb++){
        __syncthreads();
        #pragma unroll
        for (int i = 0; i < 4; i++){
            int f = tid + i*128;
            int r = f >> 3;
            int d8 = (f & 7) * 8;
            size_t ro = (size_t)(kb*64 + r)*DDIM + d8;
            float4 x0 = *(const float4*)(K0 + ro);
            float4 y0 = *(const float4*)(K1 + ro);
            float4 bb0 = *(const float4*)(bkh + d8);
            float4 x1 = *(const float4*)(K0 + ro + 4);
            float4 y1 = *(const float4*)(K1 + ro + 4);
            float4 bb1 = *(const float4*)(bkh + d8 + 4);
            x0.x += y0.x + bb0.x; x0.y += y0.y + bb0.y;
            x0.z += y0.z + bb0.z; x0.w += y0.w + bb0.w;
            x1.x += y1.x + bb1.x; x1.y += y1.y + bb1.y;
            x1.z += y1.z + bb1.z; x1.w += y1.w + bb1.w;
            int ks = d8 >> 4, slot = (d8 >> 3) & 1;
            int lbase = (r & 7) * 4;
            int nt = r >> 3;
            unsigned h0,l0,h1,l1,h2,l2,h3,l3;
            bsplit(x0.x, x0.y, h0, l0);
            bsplit(x0.z, x0.w, h1, l1);
            bsplit(x1.x, x1.y, h2, l2);
            bsplit(x1.z, x1.w, h3, l3);
            Kh[ks][nt][lbase+0][slot] = h0;  Kl[ks][nt][lbase+0][slot] = l0;
            Kh[ks][nt][lbase+1][slot] = h1;  Kl[ks][nt][lbase+1][slot] = l1;
            Kh[ks][nt][lbase+2][slot] = h2;  Kl[ks][nt][lbase+2][slot] = l2;
            Kh[ks][nt][lbase+3][slot] = h3;  Kl[ks][nt][lbase+3][slot] = l3;
        }
        #pragma unroll
        for (int i = 0; i < 4; i++){
            int f = tid + i*128;
            int spr = f >> 4;
            int d4 = (f & 15) * 4;
            int s = spr * 2;
            size_t ro0 = (size_t)(kb*64 + s    )*DDIM + d4;
            size_t ro1 = (size_t)(kb*64 + s + 1)*DDIM + d4;
            float4 x0 = *(const float4*)(V0 + ro0);
            float4 y0 = *(const float4*)(V1 + ro0);
            float4 x1 = *(const float4*)(V0 + ro1);
            float4 y1 = *(const float4*)(V1 + ro1);
            float4 bb = *(const float4*)(bvh + d4);
            float a0[4] = {x0.x+y0.x+bb.x, x0.y+y0.y+bb.y, x0.z+y0.z+bb.z, x0.w+y0.w+bb.w};
            float a1[4] = {x1.x+y1.x+bb.x, x1.y+y1.y+bb.y, x1.z+y1.z+bb.z, x1.w+y1.w+bb.w};
            int ks = s >> 4, slot = (s >> 3) & 1;
            int tp = (s & 7) >> 1;
            #pragma unroll
            for (int j = 0; j < 4; j++){
                int d = d4 + j;
                unsigned hv, lv;
                bsplit(a0[j], a1[j], hv, lv);
                Vh[ks][d>>3][(d&7)*4 + tp][slot] = hv;
                Vl[ks][d>>3][(d&7)*4 + tp][slot] = lv;
            }
        }
        __syncthreads();

        float sfrag[8][4];
        #pragma unroll
        for (int nt = 0; nt < 8; nt++)
            #pragma unroll
            for (int r = 0; r < 4; r++) sfrag[nt][r] = 0.0f;
        #pragma unroll
        for (int ks = 0; ks < 4; ks++){
            #pragma unroll
            for (int nt = 0; nt < 8; nt++){
                unsigned kh2[2], kl2[2];
                *(uint2*)kh2 = *(const uint2*)Kh[ks][nt][ln];
                *(uint2*)kl2 = *(const uint2*)Kl[ks][nt][ln];
                mma16(sfrag[nt], qh[ks], kh2);
                mma16(sfrag[nt], qh[ks], kl2);
                mma16(sfrag[nt], ql[ks], kh2);
            }
        }

        float mx0 = -INFINITY, mx1 = -INFINITY;
        #pragma unroll
        for (int nt = 0; nt < 8; nt++){
            #pragma unroll
            for (int e = 0; e < 2; e++){
                int c = kb*64 + nt*8 + t4*2 + e;
                bool in0 = (c >= r0 - 51) && (c <= r0 + 51);
                bool in1 = (c >= r1 - 51) && (c <= r1 + 51);
                float vv0 = sfrag[nt][e]   * 0.125f;
                float vv1 = sfrag[nt][2+e] * 0.125f;
                if (sp){
                    vv0 = in0 ? vv0 : -INFINITY;
                    vv1 = in1 ? vv1 : -INFINITY;
                } else {
                    if (!in0) vv0 -= lam;
                    if (!in1) vv1 -= lam;
                }
                sfrag[nt][e]   = vv0;
                sfrag[nt][2+e] = vv1;
                mx0 = fmaxf(mx0, vv0);
                mx1 = fmaxf(mx1, vv1);
            }
        }
        #pragma unroll
        for (int o = 1; o <= 2; o <<= 1){
            mx0 = fmaxf(mx0, __shfl_xor_sync(0xffffffffu, mx0, o));
            mx1 = fmaxf(mx1, __shfl_xor_sync(0xffffffffu, mx1, o));
        }
        float mnew0 = fmaxf(mrow0, mx0);
        float mnew1 = fmaxf(mrow1, mx1);
        float sf0 = (mrow0 == mnew0) ? 1.0f : __expf(mrow0 - mnew0);
        float sf1 = (mrow1 == mnew1) ? 1.0f : __expf(mrow1 - mnew1);
        float mc0 = fmaxf(mnew0, -1e30f);
        float mc1 = fmaxf(mnew1, -1e30f);
        float rs0 = 0.0f, rs1 = 0.0f;
        #pragma unroll
        for (int nt = 0; nt < 8; nt++){
            #pragma unroll
            for (int e = 0; e < 2; e++){
                float p0 = __expf(sfrag[nt][e]   - mc0);
                float p1 = __expf(sfrag[nt][2+e] - mc1);
                sfrag[nt][e]   = p0;
                sfrag[nt][2+e] = p1;
                rs0 += p0; rs1 += p1;
            }
        }
        #pragma unroll
        for (int o = 1; o <= 2; o <<= 1){
            rs0 += __shfl_xor_sync(0xffffffffu, rs0, o);
            rs1 += __shfl_xor_sync(0xffffffffu, rs1, o);
        }
        lrow0 = lrow0 * sf0 + rs0;  mrow0 = mnew0;
        lrow1 = lrow1 * sf1 + rs1;  mrow1 = mnew1;
        #pragma unroll
        for (int nt = 0; nt < 8; nt++){
            oacc[nt][0] *= sf0; oacc[nt][1] *= sf0;
            oacc[nt][2] *= sf1; oacc[nt][3] *= sf1;
        }

        #pragma unroll
        for (int pks = 0; pks < 4; pks++){
            unsigned pah[4], pal[4];
            bsplit(sfrag[2*pks  ][0], sfrag[2*pks  ][1], pah[0], pal[0]);
            bsplit(sfrag[2*pks  ][2], sfrag[2*pks  ][3], pah[1], pal[1]);
            bsplit(sfrag[2*pks+1][0], sfrag[2*pks+1][1], pah[2], pal[2]);
            bsplit(sfrag[2*pks+1][2], sfrag[2*pks+1][3], pah[3], pal[3]);
            #pragma unroll
            for (int nt = 0; nt < 8; nt++){
                unsigned vh2[2], vl2[2];
                *(uint2*)vh2 = *(const uint2*)Vh[pks][nt][ln];
                *(uint2*)vl2 = *(const uint2*)Vl[pks][nt][ln];
                mma16(oacc[nt], pah, vh2);
                mma16(oacc[nt], pah, vl2);
                mma16(oacc[nt], pal, vh2);
            }
        }
    }

    float inv0 = 1.0f / lrow0;
    float inv1 = 1.0f / lrow1;
    float* Ob = O + (size_t)(b*SS)*DDIM + h*DH;
    #pragma unroll
    for (int nt = 0; nt < 8; nt++){
        int d = nt*8 + t4*2;
        float2 o0, o1;
        o0.x = oacc[nt][0]*inv0; o0.y = oacc[nt][1]*inv0;
        o1.x = oacc[nt][2]*inv1; o1.y = oacc[nt][3]*inv1;
        *(float2*)(Ob + (size_t)r0*DDIM + d) = o0;
        *(float2*)(Ob + (size_t)r1*DDIM + d) = o1;
    }
}

// ---------------- final: out = sum(8 partials) + b2 + h ; u per-row + batch mean ----------------
__global__ void u_final(const float* __restrict__ part,
                        const float* __restrict__ b2, const float* __restrict__ hres,
                        const float* __restrict__ x, float* __restrict__ outp,
                        int out_size){
    int row = blockIdx.x;
    int t = threadIdx.x;
    size_t off = (size_t)row*DDIM + t*4;
    const size_t slab = (size_t)MM * DDIM;
    float4 bv = *(const float4*)(b2 + t*4);
    float4 hv = *(const float4*)(hres + off);
    float4 o;
    o.x = bv.x + hv.x; o.y = bv.y + hv.y;
    o.z = bv.z + hv.z; o.w = bv.w + hv.w;
    #pragma unroll
    for (int z = 0; z < 8; z++){
        float4 a = *(const float4*)(part + z*slab + off);
        o.x += a.x; o.y += a.y; o.z += a.z; o.w += a.w;
    }
    *(float4*)(outp + off) = o;

    float4 xv = *(const float4*)(x + off);
    float dx = o.x - xv.x, dy = o.y - xv.y, dz = o.z - xv.z, dw = o.w - xv.w;
    float d2 = dx*dx + dy*dy + dz*dz + dw*dw;
    float x2 = xv.x*xv.x + xv.y*xv.y + xv.z*xv.z + xv.w*xv.w;
    #pragma unroll
    for (int o2 = 16; o2; o2 >>= 1){
        d2 += __shfl_xor_sync(0xffffffffu, d2, o2);
        x2 += __shfl_xor_sync(0xffffffffu, x2, o2);
    }
    __shared__ float pd[4], px[4];
    int w = t >> 5;
    if ((t & 31) == 0){ pd[w] = d2; px[w] = x2; }
    __syncthreads();
    if (t == 0){
        d2 = pd[0]+pd[1]+pd[2]+pd[3];
        x2 = px[0]+px[1]+px[2]+px[3];
        float u = sqrtf(d2) / (sqrtf(x2) + 1e-8f);
        int b = row >> 10;
        int idx = MM*DDIM + b;
        if (idx < out_size) atomicAdd(outp + idx, u * (1.0f/SS));
    }
}

// ---------------- launch ----------------
extern "C" void kernel_launch(void* const* d_in, const int* in_sizes, int n_in,
                              void* d_out, int out_size){
    const float* x      = (const float*)d_in[0];
    const float* u_prev = (const float*)d_in[1];
    const float* wq = (const float*)d_in[2];  const float* bq = (const float*)d_in[3];
    const float* wk = (const float*)d_in[4];  const float* bk = (const float*)d_in[5];
    const float* wv = (const float*)d_in[6];  const float* bv = (const float*)d_in[7];
    const float* wo = (const float*)d_in[8];  const float* bo = (const float*)d_in[9];
    const float* ln1g = (const float*)d_in[10]; const float* ln1b = (const float*)d_in[11];
    const float* ln2g = (const float*)d_in[12]; const float* ln2b = (const float*)d_in[13];
    const float* w1 = (const float*)d_in[14]; const float* b1 = (const float*)d_in[15];
    const float* w2 = (const float*)d_in[16]; const float* b2 = (const float*)d_in[17];
    float* outp = (float*)d_out;

    float *p_xn, *p_att, *p_h, *p_hn, *p_f1, *p_part;
    cudaGetSymbolAddress((void**)&p_xn,  g_xn);
    cudaGetSymbolAddress((void**)&p_att, g_att);
    cudaGetSymbolAddress((void**)&p_h,   g_h);
    cudaGetSymbolAddress((void**)&p_hn,  g_hn);
    cudaGetSymbolAddress((void**)&p_f1,  g_f1);
    cudaGetSymbolAddress((void**)&p_part,g_part);

    const size_t slab = (size_t)MM * DDIM;

    // LN1 + lam/sp + output u-slot zeroing (fused)
    ln1_kernel<<<MM, 128>>>(x, ln1g, ln1b, p_xn, u_prev, outp, out_size);

    // QKV split-K x2 -> 6 partial slabs (q0,q1,k0,k1,v0,v1)
    qkv_split<<<dim3(24, MM/64, 2), 128>>>(p_xn, wq, wk, wv, p_part);

    // attention with fused partial reduction + bias
    attn_kernel<<<dim3(SS/64, BB*HH), 128>>>(
        p_part,            p_part + slab,
        p_part + 2*slab,   p_part + 3*slab,
        p_part + 4*slab,   p_part + 5*slab,
        bq, bk, bv, p_att);

    // Wo: split-K x4 (BM=64) -> partial slabs 0..3
    gemm_split64<<<dim3(DDIM/64, MM/64, 4), 128>>>(p_att, wo, p_part, DDIM, DDIM/4);

    // fused: h = p0+p1+p2+p3+x+bo ; hn = LN2(h)
    ln2_fused<<<MM, 128>>>(p_part, p_part + slab, p_part + 2*slab, p_part + 3*slab,
                           x, bo, ln2g, ln2b, p_h, p_hn);

    // FFN1 (full-K, GELU epilogue)
    gemm64<true,false><<<dim3(FF/64, MM/64), 128>>>(p_hn, w1, b1, nullptr, p_f1, DDIM, FF);

    // FFN2: split-K x8 (BM=64) -> partial slabs 0..7
    gemm_split64<<<dim3(DDIM/64, MM/64, 8), 128>>>(p_f1, w2, p_part, FF, FF/8);

    // final: out = sum(8 partials) + b2 + h ; u per-row + batch mean (atomic)
    u_final<<<MM, 128>>>(p_part, b2, p_h, x, outp, out_size);
}

// round 14
// speedup vs baseline: 1.2243x; 1.0198x over previous
#include <cuda_runtime.h>
#include <cuda_bf16.h>
#include <math.h>

#define BB 2
#define SS 1024
#define DDIM 512
#define HH 8
#define DH 64
#define FF 2048
#define MM (BB*SS)

// ---------------- scratch (no allocation allowed) ----------------
__device__ float g_xn[MM*DDIM];
__device__ float g_att[MM*DDIM];
__device__ float g_h [MM*DDIM];
__device__ float g_hn[MM*DDIM];
__device__ float g_f1[MM*FF];
__device__ float g_part[8*MM*DDIM];   // split-K partial slabs
__device__ float g_lam[BB];
__device__ int   g_sp [BB];

// ---------------- helpers ----------------
__device__ __forceinline__ void pdl_wait(){
    asm volatile("griddepcontrol.wait;" ::: "memory");
}

__device__ __forceinline__ void bsplit(float x0, float x1, unsigned &hw, unsigned &lw){
    asm("cvt.rn.bf16x2.f32 %0, %1, %2;" : "=r"(hw) : "f"(x1), "f"(x0));
    float h0 = __uint_as_float(hw << 16);
    float h1 = __uint_as_float(hw & 0xffff0000u);
    float l0 = x0 - h0, l1 = x1 - h1;
    asm("cvt.rn.bf16x2.f32 %0, %1, %2;" : "=r"(lw) : "f"(l1), "f"(l0));
}

__device__ __forceinline__ void mma16(float* c, const unsigned* a, const unsigned* b){
    asm volatile(
        "mma.sync.aligned.m16n8k16.row.col.f32.bf16.bf16.f32 "
        "{%0,%1,%2,%3}, {%4,%5,%6,%7}, {%8,%9}, {%0,%1,%2,%3};\n"
        : "+f"(c[0]), "+f"(c[1]), "+f"(c[2]), "+f"(c[3])
        : "r"(a[0]), "r"(a[1]), "r"(a[2]), "r"(a[3]), "r"(b[0]), "r"(b[1]));
}

__device__ __forceinline__ float gelu_exact(float v){
    return 0.5f * v * (1.0f + erff(v * 0.70710678118654752f));
}

// ---------------- LayerNorm1 (+lam compute / u-slot zero in block 0) ----------------
__global__ void ln1_kernel(const float* __restrict__ x, const float* __restrict__ g,
                           const float* __restrict__ be, float* __restrict__ y,
                           const float* __restrict__ u_prev, float* __restrict__ outp,
                           int out_size){
    pdl_wait();
    int row = blockIdx.x;
    int t = threadIdx.x;
    if (row == 0 && t < BB){
        float lam = 10.0f * expf(-5.0f * u_prev[t]);
        g_lam[t] = lam;
        g_sp[t]  = (lam >= 1.0f) ? 1 : 0;
        int idx = MM*DDIM + t;
        if (idx < out_size) outp[idx] = 0.0f;
    }
    const float* xr = x + (size_t)row * DDIM;
    float4 v = *(const float4*)(xr + t*4);
    float s  = v.x + v.y + v.z + v.w;
    float ss = v.x*v.x + v.y*v.y + v.z*v.z + v.w*v.w;
    #pragma unroll
    for (int o = 16; o; o >>= 1){
        s  += __shfl_xor_sync(0xffffffffu, s,  o);
        ss += __shfl_xor_sync(0xffffffffu, ss, o);
    }
    __shared__ float ps[4], pss[4];
    int w = t >> 5;
    if ((t & 31) == 0){ ps[w] = s; pss[w] = ss; }
    __syncthreads();
    s  = ps[0] + ps[1] + ps[2] + ps[3];
    ss = pss[0] + pss[1] + pss[2] + pss[3];
    float mean = s * (1.0f/DDIM);
    float var  = ss * (1.0f/DDIM) - mean*mean;
    float inv  = rsqrtf(var + 1e-5f);
    float4 gv = *(const float4*)(g  + t*4);
    float4 bv = *(const float4*)(be + t*4);
    float4 o;
    o.x = (v.x - mean)*inv*gv.x + bv.x;
    o.y = (v.y - mean)*inv*gv.y + bv.y;
    o.z = (v.z - mean)*inv*gv.z + bv.z;
    o.w = (v.w - mean)*inv*gv.w + bv.w;
    *(float4*)(y + (size_t)row * DDIM + t*4) = o;
}

// ---------------- fused: h = p0+p1+p2+p3+x+bo ; hn = LN2(h) ----------------
__global__ void ln2_fused(const float* __restrict__ p0, const float* __restrict__ p1,
                          const float* __restrict__ p2, const float* __restrict__ p3,
                          const float* __restrict__ x, const float* __restrict__ bo,
                          const float* __restrict__ g, const float* __restrict__ be,
                          float* __restrict__ h, float* __restrict__ hn){
    pdl_wait();
    int row = blockIdx.x;
    int t = threadIdx.x;
    size_t off = (size_t)row*DDIM + t*4;
    float4 a0 = *(const float4*)(p0 + off);
    float4 a1 = *(const float4*)(p1 + off);
    float4 a2 = *(const float4*)(p2 + off);
    float4 a3 = *(const float4*)(p3 + off);
    float4 xv = *(const float4*)(x + off);
    float4 bv0 = *(const float4*)(bo + t*4);
    float4 v;
    v.x = a0.x + a1.x + a2.x + a3.x + xv.x + bv0.x;
    v.y = a0.y + a1.y + a2.y + a3.y + xv.y + bv0.y;
    v.z = a0.z + a1.z + a2.z + a3.z + xv.z + bv0.z;
    v.w = a0.w + a1.w + a2.w + a3.w + xv.w + bv0.w;
    *(float4*)(h + off) = v;

    float s  = v.x + v.y + v.z + v.w;
    float ss = v.x*v.x + v.y*v.y + v.z*v.z + v.w*v.w;
    #pragma unroll
    for (int o = 16; o; o >>= 1){
        s  += __shfl_xor_sync(0xffffffffu, s,  o);
        ss += __shfl_xor_sync(0xffffffffu, ss, o);
    }
    __shared__ float ps[4], pss[4];
    int w = t >> 5;
    if ((t & 31) == 0){ ps[w] = s; pss[w] = ss; }
    __syncthreads();
    s  = ps[0] + ps[1] + ps[2] + ps[3];
    ss = pss[0] + pss[1] + pss[2] + pss[3];
    float mean = s * (1.0f/DDIM);
    float var  = ss * (1.0f/DDIM) - mean*mean;
    float inv  = rsqrtf(var + 1e-5f);
    float4 gv = *(const float4*)(g  + t*4);
    float4 bv = *(const float4*)(be + t*4);
    float4 o;
    o.x = (v.x - mean)*inv*gv.x + bv.x;
    o.y = (v.y - mean)*inv*gv.y + bv.y;
    o.z = (v.z - mean)*inv*gv.z + bv.z;
    o.w = (v.w - mean)*inv*gv.w + bv.w;
    *(float4*)(hn + off) = o;
}

// ---------------- bf16x3 GEMM body (full-K, with epilogue) ----------------
template<int BM, bool GELU, bool RES>
__device__ __forceinline__ void gemm_body(
        const float* __restrict__ A, const float* __restrict__ W,
        const float* __restrict__ bias, const float* __restrict__ res,
        float* __restrict__ C, int Kn, int Nn, int m0, int n0){
    constexpr int MTILES = BM/16;
    constexpr int WMT    = MTILES/2;
    constexpr int AIT    = BM/16;

    __shared__ unsigned Ah[2][MTILES][32][4];
    __shared__ unsigned Al[2][MTILES][32][4];
    __shared__ unsigned Bh[2][8][32][2];
    __shared__ unsigned Bl[2][8][32][2];

    const int tid = threadIdx.x;
    const int warp = tid >> 5, ln = tid & 31;
    const int wm = warp >> 1, wn = warp & 1;
    const int gid = ln >> 2, t4 = ln & 3;

    float acc[WMT][4][4];
    #pragma unroll
    for (int mt = 0; mt < WMT; mt++)
        #pragma unroll
        for (int nt = 0; nt < 4; nt++)
            #pragma unroll
            for (int r = 0; r < 4; r++) acc[mt][nt][r] = 0.0f;

    float4 av[AIT], wv4[4];
    #pragma unroll
    for (int i = 0; i < AIT; i++){
        int f = tid + i*128;
        int row = f >> 3, kq = (f & 7) << 2;
        av[i] = *(const float4*)(A + (size_t)(m0 + row)*Kn + kq);
    }
    #pragma unroll
    for (int i = 0; i < 4; i++){
        int f = tid + i*128;
        int row = f >> 3, kq = (f & 7) << 2;
        wv4[i] = *(const float4*)(W + (size_t)(n0 + row)*Kn + kq);
    }

    for (int kt = 0; kt < Kn; kt += 32){
        __syncthreads();
        #pragma unroll
        for (int i = 0; i < AIT; i++){
            int f = tid + i*128;
            int row = f >> 3, kq = (f & 7) << 2;
            int ks = kq >> 4, kk = kq & 15;
            int mt = row >> 4, rr = row & 15;
            int slot = ((rr >> 3) & 1) + (((kk >> 3) & 1) << 1);
            int lane = (rr & 7)*4 + ((kk & 7) >> 1);
            unsigned h0, l0, h1, l1;
            bsplit(av[i].x, av[i].y, h0, l0);
            bsplit(av[i].z, av[i].w, h1, l1);
            Ah[ks][mt][lane  ][slot] = h0;
            Ah[ks][mt][lane+1][slot] = h1;
            Al[ks][mt][lane  ][slot] = l0;
            Al[ks][mt][lane+1][slot] = l1;
        }
        #pragma unroll
        for (int i = 0; i < 4; i++){
            int f = tid + i*128;
            int row = f >> 3, kq = (f & 7) << 2;
            int ks = kq >> 4, kk = kq & 15;
            int nt = row >> 3;
            int slot = (kk >> 3) & 1;
            int lane = (row & 7)*4 + ((kk & 7) >> 1);
            unsigned h0, l0, h1, l1;
            bsplit(wv4[i].x, wv4[i].y, h0, l0);
            bsplit(wv4[i].z, wv4[i].w, h1, l1);
            Bh[ks][nt][lane  ][slot] = h0;
            Bh[ks][nt][lane+1][slot] = h1;
            Bl[ks][nt][lane  ][slot] = l0;
            Bl[ks][nt][lane+1][slot] = l1;
        }
        __syncthreads();

        if (kt + 32 < Kn){
            #pragma unroll
            for (int i = 0; i < AIT; i++){
                int f = tid + i*128;
                int row = f >> 3, kq = (f & 7) << 2;
                av[i] = *(const float4*)(A + (size_t)(m0 + row)*Kn + kt + 32 + kq);
            }
            #pragma unroll
            for (int i = 0; i < 4; i++){
                int f = tid + i*128;
                int row = f >> 3, kq = (f & 7) << 2;
                wv4[i] = *(const float4*)(W + (size_t)(n0 + row)*Kn + kt + 32 + kq);
            }
        }

        #pragma unroll
        for (int ks = 0; ks < 2; ks++){
            unsigned ah[WMT][4], al[WMT][4], bh[4][2], bl[4][2];
            #pragma unroll
            for (int mt = 0; mt < WMT; mt++){
                *(uint4*)ah[mt] = *(const uint4*)Ah[ks][wm*WMT + mt][ln];
                *(uint4*)al[mt] = *(const uint4*)Al[ks][wm*WMT + mt][ln];
            }
            #pragma unroll
            for (int nt = 0; nt < 4; nt++){
                *(uint2*)bh[nt] = *(const uint2*)Bh[ks][wn*4 + nt][ln];
                *(uint2*)bl[nt] = *(const uint2*)Bl[ks][wn*4 + nt][ln];
            }
            #pragma unroll
            for (int mt = 0; mt < WMT; mt++)
                #pragma unroll
                for (int nt = 0; nt < 4; nt++){
                    mma16(acc[mt][nt], ah[mt], bh[nt]);
                    mma16(acc[mt][nt], ah[mt], bl[nt]);
                    mma16(acc[mt][nt], al[mt], bh[nt]);
                }
        }
    }

    #pragma unroll
    for (int mt = 0; mt < WMT; mt++){
        #pragma unroll
        for (int rr = 0; rr < 2; rr++){
            int m = m0 + wm*(BM/2) + mt*16 + gid + rr*8;
            #pragma unroll
            for (int nt = 0; nt < 4; nt++){
                int n = n0 + wn*32 + nt*8 + t4*2;
                float2 o;
                o.x = acc[mt][nt][rr*2 + 0];
                o.y = acc[mt][nt][rr*2 + 1];
                float2 bv = *(const float2*)(bias + n);
                o.x += bv.x; o.y += bv.y;
                if (RES){
                    float2 rv = *(const float2*)(res + (size_t)m*Nn + n);
                    o.x += rv.x; o.y += rv.y;
                }
                if (GELU){
                    o.x = gelu_exact(o.x);
                    o.y = gelu_exact(o.y);
                }
                *(float2*)(C + (size_t)m*Nn + n) = o;
            }
        }
    }
}

// ---------------- split-K GEMM body (raw partial output, N stride = DDIM) ----------------
template<int BM>
__device__ __forceinline__ void gemm_split_body(
        const float* __restrict__ A, const float* __restrict__ W,
        float* __restrict__ Cp, int Kn, int Kloop, int kbase, int m0, int n0){
    constexpr int MTILES = BM/16;
    constexpr int WMT    = MTILES/2;
    constexpr int AIT    = BM/16;

    __shared__ unsigned Ah[2][MTILES][32][4];
    __shared__ unsigned Al[2][MTILES][32][4];
    __shared__ unsigned Bh[2][8][32][2];
    __shared__ unsigned Bl[2][8][32][2];

    const int tid = threadIdx.x;
    const int warp = tid >> 5, ln = tid & 31;
    const int wm = warp >> 1, wn = warp & 1;
    const int gid = ln >> 2, t4 = ln & 3;

    float acc[WMT][4][4];
    #pragma unroll
    for (int mt = 0; mt < WMT; mt++)
        #pragma unroll
        for (int nt = 0; nt < 4; nt++)
            #pragma unroll
            for (int r = 0; r < 4; r++) acc[mt][nt][r] = 0.0f;

    float4 av[AIT], wv4[4];
    #pragma unroll
    for (int i = 0; i < AIT; i++){
        int f = tid + i*128;
        int row = f >> 3, kq = (f & 7) << 2;
        av[i] = *(const float4*)(A + (size_t)(m0 + row)*Kn + kbase + kq);
    }
    #pragma unroll
    for (int i = 0; i < 4; i++){
        int f = tid + i*128;
        int row = f >> 3, kq = (f & 7) << 2;
        wv4[i] = *(const float4*)(W + (size_t)(n0 + row)*Kn + kbase + kq);
    }

    for (int kt = 0; kt < Kloop; kt += 32){
        __syncthreads();
        #pragma unroll
        for (int i = 0; i < AIT; i++){
            int f = tid + i*128;
            int row = f >> 3, kq = (f & 7) << 2;
            int ks = kq >> 4, kk = kq & 15;
            int mt = row >> 4, rr = row & 15;
            int slot = ((rr >> 3) & 1) + (((kk >> 3) & 1) << 1);
            int lane = (rr & 7)*4 + ((kk & 7) >> 1);
            unsigned h0, l0, h1, l1;
            bsplit(av[i].x, av[i].y, h0, l0);
            bsplit(av[i].z, av[i].w, h1, l1);
            Ah[ks][mt][lane  ][slot] = h0;
            Ah[ks][mt][lane+1][slot] = h1;
            Al[ks][mt][lane  ][slot] = l0;
            Al[ks][mt][lane+1][slot] = l1;
        }
        #pragma unroll
        for (int i = 0; i < 4; i++){
            int f = tid + i*128;
            int row = f >> 3, kq = (f & 7) << 2;
            int ks = kq >> 4, kk = kq & 15;
            int nt = row >> 3;
            int slot = (kk >> 3) & 1;
            int lane = (row & 7)*4 + ((kk & 7) >> 1);
            unsigned h0, l0, h1, l1;
            bsplit(wv4[i].x, wv4[i].y, h0, l0);
            bsplit(wv4[i].z, wv4[i].w, h1, l1);
            Bh[ks][nt][lane  ][slot] = h0;
            Bh[ks][nt][lane+1][slot] = h1;
            Bl[ks][nt][lane  ][slot] = l0;
            Bl[ks][nt][lane+1][slot] = l1;
        }
        __syncthreads();

        if (kt + 32 < Kloop){
            #pragma unroll
            for (int i = 0; i < AIT; i++){
                int f = tid + i*128;
                int row = f >> 3, kq = (f & 7) << 2;
                av[i] = *(const float4*)(A + (size_t)(m0 + row)*Kn + kbase + kt + 32 + kq);
            }
            #pragma unroll
            for (int i = 0; i < 4; i++){
                int f = tid + i*128;
                int row = f >> 3, kq = (f & 7) << 2;
                wv4[i] = *(const float4*)(W + (size_t)(n0 + row)*Kn + kbase + kt + 32 + kq);
            }
        }

        #pragma unroll
        for (int ks = 0; ks < 2; ks++){
            unsigned ah[WMT][4], al[WMT][4], bh[4][2], bl[4][2];
            #pragma unroll
            for (int mt = 0; mt < WMT; mt++){
                *(uint4*)ah[mt] = *(const uint4*)Ah[ks][wm*WMT + mt][ln];
                *(uint4*)al[mt] = *(const uint4*)Al[ks][wm*WMT + mt][ln];
            }
            #pragma unroll
            for (int nt = 0; nt < 4; nt++){
                *(uint2*)bh[nt] = *(const uint2*)Bh[ks][wn*4 + nt][ln];
                *(uint2*)bl[nt] = *(const uint2*)Bl[ks][wn*4 + nt][ln];
            }
            #pragma unroll
            for (int mt = 0; mt < WMT; mt++)
                #pragma unroll
                for (int nt = 0; nt < 4; nt++){
                    mma16(acc[mt][nt], ah[mt], bh[nt]);
                    mma16(acc[mt][nt], ah[mt], bl[nt]);
                    mma16(acc[mt][nt], al[mt], bh[nt]);
                }
        }
    }

    #pragma unroll
    for (int mt = 0; mt < WMT; mt++){
        #pragma unroll
        for (int rr = 0; rr < 2; rr++){
            int m = m0 + wm*(BM/2) + mt*16 + gid + rr*8;
            #pragma unroll
            for (int nt = 0; nt < 4; nt++){
                int n = n0 + wn*32 + nt*8 + t4*2;
                float2 o;
                o.x = acc[mt][nt][rr*2 + 0];
                o.y = acc[mt][nt][rr*2 + 1];
                *(float2*)(Cp + (size_t)m*DDIM + n) = o;
            }
        }
    }
}

// ---------------- split-K kernels ----------------
__global__ void __launch_bounds__(128)
qkv_split(const float* __restrict__ xn,
          const float* __restrict__ wq, const float* __restrict__ wk, const float* __restrict__ wv,
          float* __restrict__ part){
    pdl_wait();
    int sel = blockIdx.x >> 3;
    int n0  = (blockIdx.x & 7) << 6;
    int z   = blockIdx.z;
    const float* W = (sel == 0) ? wq : (sel == 1) ? wk : wv;
    float* Cp = part + (size_t)(sel*2 + z) * MM * DDIM;
    gemm_split_body<64>(xn, W, Cp, DDIM, DDIM/2, z*(DDIM/2), blockIdx.y*64, n0);
}

__global__ void __launch_bounds__(128)
gemm_split64(const float* __restrict__ A, const float* __restrict__ W,
             float* __restrict__ Cpart, int Kn, int Kloop){
    pdl_wait();
    float* Cp = Cpart + (size_t)blockIdx.z * MM * DDIM;
    gemm_split_body<64>(A, W, Cp, Kn, Kloop, blockIdx.z*Kloop, blockIdx.y*64, blockIdx.x*64);
}

// ---------------- full-K GEMM kernel (FFN1) ----------------
template<bool GELU, bool RES>
__global__ void __launch_bounds__(128)
gemm64(const float* __restrict__ A, const float* __restrict__ W,
       const float* __restrict__ bias, const float* __restrict__ res,
       float* __restrict__ C, int Kn, int Nn){
    pdl_wait();
    gemm_body<64,GELU,RES>(A, W, bias, res, C, Kn, Nn, blockIdx.y*64, blockIdx.x*64);
}

// ---------------- tensor-core flash attention (fused QKV partial reduction + bias) ----------------
__global__ void __launch_bounds__(128, 3)
attn_kernel(const float* __restrict__ q0, const float* __restrict__ q1,
            const float* __restrict__ k0, const float* __restrict__ k1,
            const float* __restrict__ v0, const float* __restrict__ v1,
            const float* __restrict__ bq, const float* __restrict__ bk,
            const float* __restrict__ bv, float* __restrict__ O){
    pdl_wait();
    __shared__ unsigned Kh[4][8][32][2], Kl[4][8][32][2];
    __shared__ unsigned Vh[4][8][32][2], Vl[4][8][32][2];

    const int bh = blockIdx.y;
    const int b = bh / HH, h = bh % HH;
    const int q0i = blockIdx.x * 64;
    const float lam = g_lam[b];
    const int sp = g_sp[b];
    const int tid = threadIdx.x;
    const int w = tid >> 5, ln = tid & 31;
    const int gid = ln >> 2, t4 = ln & 3;
    const int r0 = q0i + w*16 + gid;
    const int r1 = r0 + 8;

    unsigned qh[4][4], ql[4][4];
    {
        const float* Q0 = q0 + (size_t)(b*SS)*DDIM + h*DH;
        const float* Q1 = q1 + (size_t)(b*SS)*DDIM + h*DH;
        const float* bqh = bq + h*DH;
        #pragma unroll
        for (int ks = 0; ks < 4; ks++){
            int kcol = ks*16 + t4*2;
            float2 b0 = *(const float2*)(bqh + kcol);
            float2 b1 = *(const float2*)(bqh + kcol + 8);
            float2 a00 = *(const float2*)(Q0 + (size_t)r0*DDIM + kcol);
            float2 c00 = *(const float2*)(Q1 + (size_t)r0*DDIM + kcol);
            float2 a10 = *(const float2*)(Q0 + (size_t)r1*DDIM + kcol);
            float2 c10 = *(const float2*)(Q1 + (size_t)r1*DDIM + kcol);
            float2 a01 = *(const float2*)(Q0 + (size_t)r0*DDIM + kcol + 8);
            float2 c01 = *(const float2*)(Q1 + (size_t)r0*DDIM + kcol + 8);
            float2 a11 = *(const float2*)(Q0 + (size_t)r1*DDIM + kcol + 8);
            float2 c11 = *(const float2*)(Q1 + (size_t)r1*DDIM + kcol + 8);
            bsplit(a00.x + c00.x + b0.x, a00.y + c00.y + b0.y, qh[ks][0], ql[ks][0]);
            bsplit(a10.x + c10.x + b0.x, a10.y + c10.y + b0.y, qh[ks][1], ql[ks][1]);
            bsplit(a01.x + c01.x + b1.x, a01.y + c01.y + b1.y, qh[ks][2], ql[ks][2]);
            bsplit(a11.x + c11.x + b1.x, a11.y + c11.y + b1.y, qh[ks][3], ql[ks][3]);
        }
    }

    float oacc[8][4];
    #pragma unroll
    for (int nt = 0; nt < 8; nt++)
        #pragma unroll
        for (int r = 0; r < 4; r++) oacc[nt][r] = 0.0f;
    float mrow0 = -INFINITY, mrow1 = -INFINITY;
    float lrow0 = 0.0f, lrow1 = 0.0f;

    int klo = 0, khi = SS/64;
    if (sp){
        int lo = q0i - 51; if (lo < 0) lo = 0;
        int hi = q0i + 114; if (hi > SS-1) hi = SS-1;
        klo = lo >> 6; khi = (hi >> 6) + 1;
    }

    const float* K0 = k0 + (size_t)(b*SS)*DDIM + h*DH;
    const float* K1 = k1 + (size_t)(b*SS)*DDIM + h*DH;
    const float* V0 = v0 + (size_t)(b*SS)*DDIM + h*DH;
    const float* V1 = v1 + (size_t)(b*SS)*DDIM + h*DH;
    const float* bkh = bk + h*DH;
    const float* bvh = bv + h*DH;

    for (int kb = klo; kb < khi; kb++){
        __syncthreads();
        #pragma unroll
        for (int i = 0; i < 4; i++){
            int f = tid + i*128;
            int r = f >> 3;
            int d8 = (f & 7) * 8;
            size_t ro = (size_t)(kb*64 + r)*DDIM + d8;
            float4 x0 = *(const float4*)(K0 + ro);
            float4 y0 = *(const float4*)(K1 + ro);
            float4 bb0 = *(const float4*)(bkh + d8);
            float4 x1 = *(const float4*)(K0 + ro + 4);
            float4 y1 = *(const float4*)(K1 + ro + 4);
            float4 bb1 = *(const float4*)(bkh + d8 + 4);
            x0.x += y0.x + bb0.x; x0.y += y0.y + bb0.y;
            x0.z += y0.z + bb0.z; x0.w += y0.w + bb0.w;
            x1.x += y1.x + bb1.x; x1.y += y1.y + bb1.y;
            x1.z += y1.z + bb1.z; x1.w += y1.w + bb1.w;
            int ks = d8 >> 4, slot = (d8 >> 3) & 1;
            int lbase = (r & 7) * 4;
            int nt = r >> 3;
            unsigned h0,l0,h1,l1,h2,l2,h3,l3;
            bsplit(x0.x, x0.y, h0, l0);
            bsplit(x0.z, x0.w, h1, l1);
            bsplit(x1.x, x1.y, h2, l2);
            bsplit(x1.z, x1.w, h3, l3);
            Kh[ks][nt][lbase+0][slot] = h0;  Kl[ks][nt][lbase+0][slot] = l0;
            Kh[ks][nt][lbase+1][slot] = h1;  Kl[ks][nt][lbase+1][slot] = l1;
            Kh[ks][nt][lbase+2][slot] = h2;  Kl[ks][nt][lbase+2][slot] = l2;
            Kh[ks][nt][lbase+3][slot] = h3;  Kl[ks][nt][lbase+3][slot] = l3;
        }
        #pragma unroll
        for (int i = 0; i < 4; i++){
            int f = tid + i*128;
            int spr = f >> 4;
            int d4 = (f & 15) * 4;
            int s = spr * 2;
            size_t ro0 = (size_t)(kb*64 + s    )*DDIM + d4;
            size_t ro1 = (size_t)(kb*64 + s + 1)*DDIM + d4;
            float4 x0 = *(const float4*)(V0 + ro0);
            float4 y0 = *(const float4*)(V1 + ro0);
            float4 x1 = *(const float4*)(V0 + ro1);
            float4 y1 = *(const float4*)(V1 + ro1);
            float4 bb = *(const float4*)(bvh + d4);
            float a0[4] = {x0.x+y0.x+bb.x, x0.y+y0.y+bb.y, x0.z+y0.z+bb.z, x0.w+y0.w+bb.w};
            float a1[4] = {x1.x+y1.x+bb.x, x1.y+y1.y+bb.y, x1.z+y1.z+bb.z, x1.w+y1.w+bb.w};
            int ks = s >> 4, slot = (s >> 3) & 1;
            int tp = (s & 7) >> 1;
            #pragma unroll
            for (int j = 0; j < 4; j++){
                int d = d4 + j;
                unsigned hv, lv;
                bsplit(a0[j], a1[j], hv, lv);
                Vh[ks][d>>3][(d&7)*4 + tp][slot] = hv;
                Vl[ks][d>>3][(d&7)*4 + tp][slot] = lv;
            }
        }
        __syncthreads();

        float sfrag[8][4];
        #pragma unroll
        for (int nt = 0; nt < 8; nt++)
            #pragma unroll
            for (int r = 0; r < 4; r++) sfrag[nt][r] = 0.0f;
        #pragma unroll
        for (int ks = 0; ks < 4; ks++){
            #pragma unroll
            for (int nt = 0; nt < 8; nt++){
                unsigned kh2[2], kl2[2];
                *(uint2*)kh2 = *(const uint2*)Kh[ks][nt][ln];
                *(uint2*)kl2 = *(const uint2*)Kl[ks][nt][ln];
                mma16(sfrag[nt], qh[ks], kh2);
                mma16(sfrag[nt], qh[ks], kl2);
                mma16(sfrag[nt], ql[ks], kh2);
            }
        }

        float mx0 = -INFINITY, mx1 = -INFINITY;
        #pragma unroll
        for (int nt = 0; nt < 8; nt++){
            #pragma unroll
            for (int e = 0; e < 2; e++){
                int c = kb*64 + nt*8 + t4*2 + e;
                bool in0 = (c >= r0 - 51) && (c <= r0 + 51);
                bool in1 = (c >= r1 - 51) && (c <= r1 + 51);
                float vv0 = sfrag[nt][e]   * 0.125f;
                float vv1 = sfrag[nt][2+e] * 0.125f;
                if (sp){
                    vv0 = in0 ? vv0 : -INFINITY;
                    vv1 = in1 ? vv1 : -INFINITY;
                } else {
                    if (!in0) vv0 -= lam;
                    if (!in1) vv1 -= lam;
                }
                sfrag[nt][e]   = vv0;
                sfrag[nt][2+e] = vv1;
                mx0 = fmaxf(mx0, vv0);
                mx1 = fmaxf(mx1, vv1);
            }
        }
        #pragma unroll
        for (int o = 1; o <= 2; o <<= 1){
            mx0 = fmaxf(mx0, __shfl_xor_sync(0xffffffffu, mx0, o));
            mx1 = fmaxf(mx1, __shfl_xor_sync(0xffffffffu, mx1, o));
        }
        float mnew0 = fmaxf(mrow0, mx0);
        float mnew1 = fmaxf(mrow1, mx1);
        float sf0 = (mrow0 == mnew0) ? 1.0f : __expf(mrow0 - mnew0);
        float sf1 = (mrow1 == mnew1) ? 1.0f : __expf(mrow1 - mnew1);
        float mc0 = fmaxf(mnew0, -1e30f);
        float mc1 = fmaxf(mnew1, -1e30f);
        float rs0 = 0.0f, rs1 = 0.0f;
        #pragma unroll
        for (int nt = 0; nt < 8; nt++){
            #pragma unroll
            for (int e = 0; e < 2; e++){
                float p0 = __expf(sfrag[nt][e]   - mc0);
                float p1 = __expf(sfrag[nt][2+e] - mc1);
                sfrag[nt][e]   = p0;
                sfrag[nt][2+e] = p1;
                rs0 += p0; rs1 += p1;
            }
        }
        #pragma unroll
        for (int o = 1; o <= 2; o <<= 1){
            rs0 += __shfl_xor_sync(0xffffffffu, rs0, o);
            rs1 += __shfl_xor_sync(0xffffffffu, rs1, o);
        }
        lrow0 = lrow0 * sf0 + rs0;  mrow0 = mnew0;
        lrow1 = lrow1 * sf1 + rs1;  mrow1 = mnew1;
        #pragma unroll
        for (int nt = 0; nt < 8; nt++){
            oacc[nt][0] *= sf0; oacc[nt][1] *= sf0;
            oacc[nt][2] *= sf1; oacc[nt][3] *= sf1;
        }

        #pragma unroll
        for (int pks = 0; pks < 4; pks++){
            unsigned pah[4], pal[4];
            bsplit(sfrag[2*pks  ][0], sfrag[2*pks  ][1], pah[0], pal[0]);
            bsplit(sfrag[2*pks  ][2], sfrag[2*pks  ][3], pah[1], pal[1]);
            bsplit(sfrag[2*pks+1][0], sfrag[2*pks+1][1], pah[2], pal[2]);
            bsplit(sfrag[2*pks+1][2], sfrag[2*pks+1][3], pah[3], pal[3]);
            #pragma unroll
            for (int nt = 0; nt < 8; nt++){
                unsigned vh2[2], vl2[2];
                *(uint2*)vh2 = *(const uint2*)Vh[pks][nt][ln];
                *(uint2*)vl2 = *(const uint2*)Vl[pks][nt][ln];
                mma16(oacc[nt], pah, vh2);
                mma16(oacc[nt], pah, vl2);
                mma16(oacc[nt], pal, vh2);
            }
        }
    }

    float inv0 = 1.0f / lrow0;
    float inv1 = 1.0f / lrow1;
    float* Ob = O + (size_t)(b*SS)*DDIM + h*DH;
    #pragma unroll
    for (int nt = 0; nt < 8; nt++){
        int d = nt*8 + t4*2;
        float2 o0, o1;
        o0.x = oacc[nt][0]*inv0; o0.y = oacc[nt][1]*inv0;
        o1.x = oacc[nt][2]*inv1; o1.y = oacc[nt][3]*inv1;
        *(float2*)(Ob + (size_t)r0*DDIM + d) = o0;
        *(float2*)(Ob + (size_t)r1*DDIM + d) = o1;
    }
}

// ---------------- final: out = sum(8 partials) + b2 + h ; u per-row + batch mean ----------------
__global__ void u_final(const float* __restrict__ part,
                        const float* __restrict__ b2, const float* __restrict__ hres,
                        const float* __restrict__ x, float* __restrict__ outp,
                        int out_size){
    pdl_wait();
    int row = blockIdx.x;
    int t = threadIdx.x;
    size_t off = (size_t)row*DDIM + t*4;
    const size_t slab = (size_t)MM * DDIM;
    float4 bv = *(const float4*)(b2 + t*4);
    float4 hv = *(const float4*)(hres + off);
    float4 o;
    o.x = bv.x + hv.x; o.y = bv.y + hv.y;
    o.z = bv.z + hv.z; o.w = bv.w + hv.w;
    #pragma unroll
    for (int z = 0; z < 8; z++){
        float4 a = *(const float4*)(part + z*slab + off);
        o.x += a.x; o.y += a.y; o.z += a.z; o.w += a.w;
    }
    *(float4*)(outp + off) = o;

    float4 xv = *(const float4*)(x + off);
    float dx = o.x - xv.x, dy = o.y - xv.y, dz = o.z - xv.z, dw = o.w - xv.w;
    float d2 = dx*dx + dy*dy + dz*dz + dw*dw;
    float x2 = xv.x*xv.x + xv.y*xv.y + xv.z*xv.z + xv.w*xv.w;
    #pragma unroll
    for (int o2 = 16; o2; o2 >>= 1){
        d2 += __shfl_xor_sync(0xffffffffu, d2, o2);
        x2 += __shfl_xor_sync(0xffffffffu, x2, o2);
    }
    __shared__ float pd[4], px[4];
    int w = t >> 5;
    if ((t & 31) == 0){ pd[w] = d2; px[w] = x2; }
    __syncthreads();
    if (t == 0){
        d2 = pd[0]+pd[1]+pd[2]+pd[3];
        x2 = px[0]+px[1]+px[2]+px[3];
        float u = sqrtf(d2) / (sqrtf(x2) + 1e-8f);
        int b = row >> 10;
        int idx = MM*DDIM + b;
        if (idx < out_size) atomicAdd(outp + idx, u * (1.0f/SS));
    }
}

// ---------------- PDL launch helper ----------------
static void launch_pdl(const void* fn, dim3 grid, dim3 block, void** args){
    cudaLaunchConfig_t cfg;
    memset(&cfg, 0, sizeof(cfg));
    cfg.gridDim = grid;
    cfg.blockDim = block;
    cfg.dynamicSmemBytes = 0;
    cfg.stream = 0;
    cudaLaunchAttribute at[1];
    at[0].id = cudaLaunchAttributeProgrammaticStreamSerialization;
    at[0].val.programmaticStreamSerializationAllowed = 1;
    cfg.attrs = at;
    cfg.numAttrs = 1;
    cudaLaunchKernelExC(&cfg, fn, args);
}

// ---------------- launch ----------------
extern "C" void kernel_launch(void* const* d_in, const int* in_sizes, int n_in,
                              void* d_out, int out_size){
    const float* x      = (const float*)d_in[0];
    const float* u_prev = (const float*)d_in[1];
    const float* wq = (const float*)d_in[2];  const float* bq = (const float*)d_in[3];
    const float* wk = (const float*)d_in[4];  const float* bk = (const float*)d_in[5];
    const float* wv = (const float*)d_in[6];  const float* bv = (const float*)d_in[7];
    const float* wo = (const float*)d_in[8];  const float* bo = (const float*)d_in[9];
    const float* ln1g = (const float*)d_in[10]; const float* ln1b = (const float*)d_in[11];
    const float* ln2g = (const float*)d_in[12]; const float* ln2b = (const float*)d_in[13];
    const float* w1 = (const float*)d_in[14]; const float* b1 = (const float*)d_in[15];
    const float* w2 = (const float*)d_in[16]; const float* b2 = (const float*)d_in[17];
    float* outp = (float*)d_out;

    float *p_xn, *p_att, *p_h, *p_hn, *p_f1, *p_part;
    cudaGetSymbolAddress((void**)&p_xn,  g_xn);
    cudaGetSymbolAddress((void**)&p_att, g_att);
    cudaGetSymbolAddress((void**)&p_h,   g_h);
    cudaGetSymbolAddress((void**)&p_hn,  g_hn);
    cudaGetSymbolAddress((void**)&p_f1,  g_f1);
    cudaGetSymbolAddress((void**)&p_part,g_part);

    const size_t slab = (size_t)MM * DDIM;
    float* s0 = p_part;
    float* s1 = p_part + slab;
    float* s2 = p_part + 2*slab;
    float* s3 = p_part + 3*slab;
    float* s4 = p_part + 4*slab;
    float* s5 = p_part + 5*slab;

    // LN1 + lam/sp + output u-slot zeroing (fused)
    {
        void* a[] = {&x, &ln1g, &ln1b, &p_xn, &u_prev, &outp, (void*)&out_size};
        launch_pdl((const void*)ln1_kernel, dim3(MM), dim3(128), a);
    }
    // QKV split-K x2 -> 6 partial slabs
    {
        void* a[] = {&p_xn, &wq, &wk, &wv, &p_part};
        launch_pdl((const void*)qkv_split, dim3(24, MM/64, 2), dim3(128), a);
    }
    // attention with fused partial reduction + bias
    {
        void* a[] = {&s0, &s1, &s2, &s3, &s4, &s5, &bq, &bk, &bv, &p_att};
        launch_pdl((const void*)attn_kernel, dim3(SS/64, BB*HH), dim3(128), a);
    }
    // Wo: split-K x4 (BM=64) -> partial slabs 0..3
    {
        int Kn = DDIM, Kloop = DDIM/4;
        void* a[] = {&p_att, &wo, &p_part, &Kn, &Kloop};
        launch_pdl((const void*)gemm_split64, dim3(DDIM/64, MM/64, 4), dim3(128), a);
    }
    // fused: h = p0+p1+p2+p3+x+bo ; hn = LN2(h)
    {
        void* a[] = {&s0, &s1, &s2, &s3, &x, &bo, &ln2g, &ln2b, &p_h, &p_hn};
        launch_pdl((const void*)ln2_fused, dim3(MM), dim3(128), a);
    }
    // FFN1 (full-K, GELU epilogue)
    {
        int Kn = DDIM, Nn = FF;
        const float* nullres = nullptr;
        void* a[] = {&p_hn, &w1, &b1, &nullres, &p_f1, &Kn, &Nn};
        launch_pdl((const void*)gemm64<true,false>, dim3(FF/64, MM/64), dim3(128), a);
    }
    // FFN2: split-K x8 (BM=64) -> partial slabs 0..7
    {
        int Kn = FF, Kloop = FF/8;
        void* a[] = {&p_f1, &w2, &p_part, &Kn, &Kloop};
        launch_pdl((const void*)gemm_split64, dim3(DDIM/64, MM/64, 8), dim3(128), a);
    }
    // final: out = sum(8 partials) + b2 + h ; u per-row + batch mean (atomic)
    {
        void* a[] = {&p_part, &b2, &p_h, &x, &outp, (void*)&out_size};
        launch_pdl((const void*)u_final, dim3(MM), dim3(128), a);
    }
}

// round 15
// speedup vs baseline: 1.3594x; 1.1104x over previous
#include <cuda_runtime.h>
#include <cuda_fp16.h>
#include <math.h>

#define BB 2
#define SS 1024
#define DDIM 512
#define HH 8
#define DH 64
#define FF 2048
#define MM (BB*SS)
#define DW (DDIM/2)
#define FW (FF/2)

// ---------------- scratch (no allocation allowed) ----------------
__device__ unsigned g_xnh[MM*DW];     // LN1 out, fp16 plane
__device__ unsigned g_atth[MM*DW];    // attn out, fp16 plane
__device__ unsigned g_hnh[MM*DW];     // LN2 out, fp16 plane
__device__ unsigned g_f1h[MM*FW];     // FFN1 out, fp16 plane
__device__ float    g_h [MM*DDIM];    // residual h (fp32, needed by u_final)
__device__ float    g_part[8*MM*DDIM];
__device__ float    g_lam[BB];
__device__ int      g_sp [BB];

// ---------------- helpers ----------------
__device__ __forceinline__ void pdl_wait(){
    asm volatile("griddepcontrol.wait;" ::: "memory");
}

__device__ __forceinline__ unsigned hpack(float x0, float x1){
    __half2 h = __floats2half2_rn(x0, x1);
    return *reinterpret_cast<unsigned*>(&h);
}

__device__ __forceinline__ void hsplit(float x0, float x1, unsigned &hw, unsigned &lw){
    __half2 h = __floats2half2_rn(x0, x1);
    float2 hf = __half22float2(h);
    __half2 l = __floats2half2_rn(x0 - hf.x, x1 - hf.y);
    hw = *reinterpret_cast<unsigned*>(&h);
    lw = *reinterpret_cast<unsigned*>(&l);
}

__device__ __forceinline__ void mma16(float* c, const unsigned* a, const unsigned* b){
    asm volatile(
        "mma.sync.aligned.m16n8k16.row.col.f32.f16.f16.f32 "
        "{%0,%1,%2,%3}, {%4,%5,%6,%7}, {%8,%9}, {%0,%1,%2,%3};\n"
        : "+f"(c[0]), "+f"(c[1]), "+f"(c[2]), "+f"(c[3])
        : "r"(a[0]), "r"(a[1]), "r"(a[2]), "r"(a[3]), "r"(b[0]), "r"(b[1]));
}

__device__ __forceinline__ float gelu_exact(float v){
    return 0.5f * v * (1.0f + erff(v * 0.70710678118654752f));
}

// ---------------- LayerNorm1 (+lam / u-slot zero) -> fp16 plane ----------------
__global__ void ln1_kernel(const float* __restrict__ x, const float* __restrict__ g,
                           const float* __restrict__ be, unsigned* __restrict__ yh,
                           const float* __restrict__ u_prev, float* __restrict__ outp,
                           int out_size){
    pdl_wait();
    int row = blockIdx.x;
    int t = threadIdx.x;
    if (row == 0 && t < BB){
        float lam = 10.0f * expf(-5.0f * u_prev[t]);
        g_lam[t] = lam;
        g_sp[t]  = (lam >= 1.0f) ? 1 : 0;
        int idx = MM*DDIM + t;
        if (idx < out_size) outp[idx] = 0.0f;
    }
    const float* xr = x + (size_t)row * DDIM;
    float4 v = *(const float4*)(xr + t*4);
    float s  = v.x + v.y + v.z + v.w;
    float ss = v.x*v.x + v.y*v.y + v.z*v.z + v.w*v.w;
    #pragma unroll
    for (int o = 16; o; o >>= 1){
        s  += __shfl_xor_sync(0xffffffffu, s,  o);
        ss += __shfl_xor_sync(0xffffffffu, ss, o);
    }
    __shared__ float ps[4], pss[4];
    int w = t >> 5;
    if ((t & 31) == 0){ ps[w] = s; pss[w] = ss; }
    __syncthreads();
    s  = ps[0] + ps[1] + ps[2] + ps[3];
    ss = pss[0] + pss[1] + pss[2] + pss[3];
    float mean = s * (1.0f/DDIM);
    float var  = ss * (1.0f/DDIM) - mean*mean;
    float inv  = rsqrtf(var + 1e-5f);
    float4 gv = *(const float4*)(g  + t*4);
    float4 bv = *(const float4*)(be + t*4);
    float o0 = (v.x - mean)*inv*gv.x + bv.x;
    float o1 = (v.y - mean)*inv*gv.y + bv.y;
    float o2 = (v.z - mean)*inv*gv.z + bv.z;
    float o3 = (v.w - mean)*inv*gv.w + bv.w;
    uint2 ww;
    ww.x = hpack(o0, o1);
    ww.y = hpack(o2, o3);
    *(uint2*)(yh + (size_t)row*DW + t*2) = ww;
}

// ---------------- fused: h = p0..p3+x+bo (fp32) ; hn = LN2(h) -> fp16 plane ----------------
__global__ void ln2_fused(const float* __restrict__ p0, const float* __restrict__ p1,
                          const float* __restrict__ p2, const float* __restrict__ p3,
                          const float* __restrict__ x, const float* __restrict__ bo,
                          const float* __restrict__ g, const float* __restrict__ be,
                          float* __restrict__ h, unsigned* __restrict__ hnh){
    pdl_wait();
    int row = blockIdx.x;
    int t = threadIdx.x;
    size_t off = (size_t)row*DDIM + t*4;
    float4 a0 = *(const float4*)(p0 + off);
    float4 a1 = *(const float4*)(p1 + off);
    float4 a2 = *(const float4*)(p2 + off);
    float4 a3 = *(const float4*)(p3 + off);
    float4 xv = *(const float4*)(x + off);
    float4 bv0 = *(const float4*)(bo + t*4);
    float4 v;
    v.x = a0.x + a1.x + a2.x + a3.x + xv.x + bv0.x;
    v.y = a0.y + a1.y + a2.y + a3.y + xv.y + bv0.y;
    v.z = a0.z + a1.z + a2.z + a3.z + xv.z + bv0.z;
    v.w = a0.w + a1.w + a2.w + a3.w + xv.w + bv0.w;
    *(float4*)(h + off) = v;

    float s  = v.x + v.y + v.z + v.w;
    float ss = v.x*v.x + v.y*v.y + v.z*v.z + v.w*v.w;
    #pragma unroll
    for (int o = 16; o; o >>= 1){
        s  += __shfl_xor_sync(0xffffffffu, s,  o);
        ss += __shfl_xor_sync(0xffffffffu, ss, o);
    }
    __shared__ float ps[4], pss[4];
    int w = t >> 5;
    if ((t & 31) == 0){ ps[w] = s; pss[w] = ss; }
    __syncthreads();
    s  = ps[0] + ps[1] + ps[2] + ps[3];
    ss = pss[0] + pss[1] + pss[2] + pss[3];
    float mean = s * (1.0f/DDIM);
    float var  = ss * (1.0f/DDIM) - mean*mean;
    float inv  = rsqrtf(var + 1e-5f);
    float4 gv = *(const float4*)(g  + t*4);
    float4 bv = *(const float4*)(be + t*4);
    float o0 = (v.x - mean)*inv*gv.x + bv.x;
    float o1 = (v.y - mean)*inv*gv.y + bv.y;
    float o2 = (v.z - mean)*inv*gv.z + bv.z;
    float o3 = (v.w - mean)*inv*gv.w + bv.w;
    uint2 ww;
    ww.x = hpack(o0, o1);
    ww.y = hpack(o2, o3);
    *(uint2*)(hnh + (size_t)row*DW + t*2) = ww;
}

// ---------------- fp16 2-MMA GEMM body ----------------
// A: fp16 plane (2 elems/word). W: fp32 (hsplit at staging, 2 planes).
// D += A*Wh ; D += A*Wl.
// EPI 0: store fp32 partial to Cp (N stride DDIM).
// EPI 1: bias + GELU -> fp16 plane Chp (N stride = Nn words/2).
template<int EPI>
__device__ __forceinline__ void gemm_pbody(
        const unsigned* __restrict__ Ap, const float* __restrict__ W,
        const float* __restrict__ bias,
        float* __restrict__ Cp, unsigned* __restrict__ Chp,
        int Kn, int Kloop, int kbase, int Nn, int m0, int n0){
    __shared__ unsigned Ah[2][4][32][4];
    __shared__ unsigned Bh[2][8][32][2];
    __shared__ unsigned Bl[2][8][32][2];

    const int tid = threadIdx.x;
    const int warp = tid >> 5, ln = tid & 31;
    const int wm = warp >> 1, wn = warp & 1;
    const int gid = ln >> 2, t4 = ln & 3;
    const int Kw = Kn >> 1;
    const int kbw = kbase >> 1;

    float acc[2][4][4];
    #pragma unroll
    for (int mt = 0; mt < 2; mt++)
        #pragma unroll
        for (int nt = 0; nt < 4; nt++)
            #pragma unroll
            for (int r = 0; r < 4; r++) acc[mt][nt][r] = 0.0f;

    uint4 av[2];
    float4 wv4[4];
    #pragma unroll
    for (int i = 0; i < 2; i++){
        int f = tid + i*128;
        int row = f >> 2, w4 = (f & 3) << 2;
        av[i] = *(const uint4*)(Ap + (size_t)(m0 + row)*Kw + kbw + w4);
    }
    #pragma unroll
    for (int i = 0; i < 4; i++){
        int f = tid + i*128;
        int row = f >> 3, kq = (f & 7) << 2;
        wv4[i] = *(const float4*)(W + (size_t)(n0 + row)*Kn + kbase + kq);
    }

    for (int kt = 0; kt < Kloop; kt += 32){
        __syncthreads();
        // stage A (word scatter, no conversion)
        #pragma unroll
        for (int i = 0; i < 2; i++){
            int f = tid + i*128;
            int row = f >> 2, w4 = (f & 3) << 2;
            int rr = row & 15, mt = row >> 4;
            unsigned wd[4] = {av[i].x, av[i].y, av[i].z, av[i].w};
            #pragma unroll
            for (int j = 0; j < 4; j++){
                int kk = w4 + j;
                int ks = kk >> 3;
                int slot = ((rr >> 3) & 1) + (((kk >> 2) & 1) << 1);
                int lane = (rr & 7)*4 + (kk & 3);
                Ah[ks][mt][lane][slot] = wd[j];
            }
        }
        // stage B (hsplit)
        #pragma unroll
        for (int i = 0; i < 4; i++){
            int f = tid + i*128;
            int row = f >> 3, kq = (f & 7) << 2;
            int ks = kq >> 4, kk = kq & 15;
            int nt = row >> 3;
            int slot = (kk >> 3) & 1;
            int lane = (row & 7)*4 + ((kk & 7) >> 1);
            unsigned h0, l0, h1, l1;
            hsplit(wv4[i].x, wv4[i].y, h0, l0);
            hsplit(wv4[i].z, wv4[i].w, h1, l1);
            Bh[ks][nt][lane  ][slot] = h0;
            Bh[ks][nt][lane+1][slot] = h1;
            Bl[ks][nt][lane  ][slot] = l0;
            Bl[ks][nt][lane+1][slot] = l1;
        }
        __syncthreads();

        if (kt + 32 < Kloop){
            int ktw = (kt + 32) >> 1;
            #pragma unroll
            for (int i = 0; i < 2; i++){
                int f = tid + i*128;
                int row = f >> 2, w4 = (f & 3) << 2;
                av[i] = *(const uint4*)(Ap + (size_t)(m0 + row)*Kw + kbw + ktw + w4);
            }
            #pragma unroll
            for (int i = 0; i < 4; i++){
                int f = tid + i*128;
                int row = f >> 3, kq = (f & 7) << 2;
                wv4[i] = *(const float4*)(W + (size_t)(n0 + row)*Kn + kbase + kt + 32 + kq);
            }
        }

        #pragma unroll
        for (int ks = 0; ks < 2; ks++){
            unsigned ah[2][4], bh[4][2], bl[4][2];
            #pragma unroll
            for (int mt = 0; mt < 2; mt++)
                *(uint4*)ah[mt] = *(const uint4*)Ah[ks][wm*2 + mt][ln];
            #pragma unroll
            for (int nt = 0; nt < 4; nt++){
                *(uint2*)bh[nt] = *(const uint2*)Bh[ks][wn*4 + nt][ln];
                *(uint2*)bl[nt] = *(const uint2*)Bl[ks][wn*4 + nt][ln];
            }
            #pragma unroll
            for (int mt = 0; mt < 2; mt++)
                #pragma unroll
                for (int nt = 0; nt < 4; nt++){
                    mma16(acc[mt][nt], ah[mt], bh[nt]);
                    mma16(acc[mt][nt], ah[mt], bl[nt]);
                }
        }
    }

    #pragma unroll
    for (int mt = 0; mt < 2; mt++){
        #pragma unroll
        for (int rr = 0; rr < 2; rr++){
            int m = m0 + wm*32 + mt*16 + gid + rr*8;
            #pragma unroll
            for (int nt = 0; nt < 4; nt++){
                int n = n0 + wn*32 + nt*8 + t4*2;
                float2 o;
                o.x = acc[mt][nt][rr*2 + 0];
                o.y = acc[mt][nt][rr*2 + 1];
                if (EPI == 0){
                    *(float2*)(Cp + (size_t)m*DDIM + n) = o;
                } else {
                    float2 bv = *(const float2*)(bias + n);
                    o.x = gelu_exact(o.x + bv.x);
                    o.y = gelu_exact(o.y + bv.y);
                    Chp[(size_t)m*(Nn >> 1) + (n >> 1)] = hpack(o.x, o.y);
                }
            }
        }
    }
}

// ---------------- GEMM kernels ----------------
__global__ void __launch_bounds__(128)
qkv_split(const unsigned* __restrict__ xnh,
          const float* __restrict__ wq, const float* __restrict__ wk, const float* __restrict__ wv,
          float* __restrict__ part){
    pdl_wait();
    int sel = blockIdx.x >> 3;
    int n0  = (blockIdx.x & 7) << 6;
    int z   = blockIdx.z;
    const float* W = (sel == 0) ? wq : (sel == 1) ? wk : wv;
    float* Cp = part + (size_t)(sel*2 + z) * MM * DDIM;
    gemm_pbody<0>(xnh, W, nullptr, Cp, nullptr, DDIM, DDIM/2, z*(DDIM/2), DDIM, blockIdx.y*64, n0);
}

__global__ void __launch_bounds__(128)
gemm_split(const unsigned* __restrict__ Ap, const float* __restrict__ W,
           float* __restrict__ Cpart, int Kn, int Kloop){
    pdl_wait();
    float* Cp = Cpart + (size_t)blockIdx.z * MM * DDIM;
    gemm_pbody<0>(Ap, W, nullptr, Cp, nullptr, Kn, Kloop, blockIdx.z*Kloop, DDIM, blockIdx.y*64, blockIdx.x*64);
}

__global__ void __launch_bounds__(128)
ffn1_kernel(const unsigned* __restrict__ hnh, const float* __restrict__ w1,
            const float* __restrict__ b1, unsigned* __restrict__ f1h){
    pdl_wait();
    gemm_pbody<1>(hnh, w1, b1, nullptr, f1h, DDIM, DDIM, 0, FF, blockIdx.y*64, blockIdx.x*64);
}

// ---------------- fp16 tensor-core flash attention ----------------
// Q single-plane (fp32 partials summed -> hpack); K/V 2-plane fp16; P single-plane.
__global__ void __launch_bounds__(128, 3)
attn_kernel(const float* __restrict__ q0, const float* __restrict__ q1,
            const float* __restrict__ k0, const float* __restrict__ k1,
            const float* __restrict__ v0, const float* __restrict__ v1,
            const float* __restrict__ bq, const float* __restrict__ bk,
            const float* __restrict__ bv, unsigned* __restrict__ Oh){
    pdl_wait();
    __shared__ unsigned Kh[4][8][32][2], Kl[4][8][32][2];
    __shared__ unsigned Vh[4][8][32][2], Vl[4][8][32][2];

    const int bh = blockIdx.y;
    const int b = bh / HH, h = bh % HH;
    const int q0i = blockIdx.x * 64;
    const float lam = g_lam[b];
    const int sp = g_sp[b];
    const int tid = threadIdx.x;
    const int w = tid >> 5, ln = tid & 31;
    const int gid = ln >> 2, t4 = ln & 3;
    const int r0 = q0i + w*16 + gid;
    const int r1 = r0 + 8;

    unsigned qh[4][4];
    {
        const float* Q0 = q0 + (size_t)(b*SS)*DDIM + h*DH;
        const float* Q1 = q1 + (size_t)(b*SS)*DDIM + h*DH;
        const float* bqh = bq + h*DH;
        #pragma unroll
        for (int ks = 0; ks < 4; ks++){
            int kcol = ks*16 + t4*2;
            float2 b0 = *(const float2*)(bqh + kcol);
            float2 b1v = *(const float2*)(bqh + kcol + 8);
            float2 a00 = *(const float2*)(Q0 + (size_t)r0*DDIM + kcol);
            float2 c00 = *(const float2*)(Q1 + (size_t)r0*DDIM + kcol);
            float2 a10 = *(const float2*)(Q0 + (size_t)r1*DDIM + kcol);
            float2 c10 = *(const float2*)(Q1 + (size_t)r1*DDIM + kcol);
            float2 a01 = *(const float2*)(Q0 + (size_t)r0*DDIM + kcol + 8);
            float2 c01 = *(const float2*)(Q1 + (size_t)r0*DDIM + kcol + 8);
            float2 a11 = *(const float2*)(Q0 + (size_t)r1*DDIM + kcol + 8);
            float2 c11 = *(const float2*)(Q1 + (size_t)r1*DDIM + kcol + 8);
            qh[ks][0] = hpack(a00.x + c00.x + b0.x,  a00.y + c00.y + b0.y);
            qh[ks][1] = hpack(a10.x + c10.x + b0.x,  a10.y + c10.y + b0.y);
            qh[ks][2] = hpack(a01.x + c01.x + b1v.x, a01.y + c01.y + b1v.y);
            qh[ks][3] = hpack(a11.x + c11.x + b1v.x, a11.y + c11.y + b1v.y);
        }
    }

    float oacc[8][4];
    #pragma unroll
    for (int nt = 0; nt < 8; nt++)
        #pragma unroll
        for (int r = 0; r < 4; r++) oacc[nt][r] = 0.0f;
    float mrow0 = -INFINITY, mrow1 = -INFINITY;
    float lrow0 = 0.0f, lrow1 = 0.0f;

    int klo = 0, khi = SS/64;
    if (sp){
        int lo = q0i - 51; if (lo < 0) lo = 0;
        int hi = q0i + 114; if (hi > SS-1) hi = SS-1;
        klo = lo >> 6; khi = (hi >> 6) + 1;
    }

    const float* K0 = k0 + (size_t)(b*SS)*DDIM + h*DH;
    const float* K1 = k1 + (size_t)(b*SS)*DDIM + h*DH;
    const float* V0 = v0 + (size_t)(b*SS)*DDIM + h*DH;
    const float* V1 = v1 + (size_t)(b*SS)*DDIM + h*DH;
    const float* bkh = bk + h*DH;
    const float* bvh = bv + h*DH;

    for (int kb = klo; kb < khi; kb++){
        __syncthreads();
        #pragma unroll
        for (int i = 0; i < 4; i++){
            int f = tid + i*128;
            int r = f >> 3;
            int d8 = (f & 7) * 8;
            size_t ro = (size_t)(kb*64 + r)*DDIM + d8;
            float4 x0 = *(const float4*)(K0 + ro);
            float4 y0 = *(const float4*)(K1 + ro);
            float4 bb0 = *(const float4*)(bkh + d8);
            float4 x1 = *(const float4*)(K0 + ro + 4);
            float4 y1 = *(const float4*)(K1 + ro + 4);
            float4 bb1 = *(const float4*)(bkh + d8 + 4);
            x0.x += y0.x + bb0.x; x0.y += y0.y + bb0.y;
            x0.z += y0.z + bb0.z; x0.w += y0.w + bb0.w;
            x1.x += y1.x + bb1.x; x1.y += y1.y + bb1.y;
            x1.z += y1.z + bb1.z; x1.w += y1.w + bb1.w;
            int ks = d8 >> 4, slot = (d8 >> 3) & 1;
            int lbase = (r & 7) * 4;
            int nt = r >> 3;
            unsigned h0,l0,h1,l1,h2,l2,h3,l3;
            hsplit(x0.x, x0.y, h0, l0);
            hsplit(x0.z, x0.w, h1, l1);
            hsplit(x1.x, x1.y, h2, l2);
            hsplit(x1.z, x1.w, h3, l3);
            Kh[ks][nt][lbase+0][slot] = h0;  Kl[ks][nt][lbase+0][slot] = l0;
            Kh[ks][nt][lbase+1][slot] = h1;  Kl[ks][nt][lbase+1][slot] = l1;
            Kh[ks][nt][lbase+2][slot] = h2;  Kl[ks][nt][lbase+2][slot] = l2;
            Kh[ks][nt][lbase+3][slot] = h3;  Kl[ks][nt][lbase+3][slot] = l3;
        }
        #pragma unroll
        for (int i = 0; i < 4; i++){
            int f = tid + i*128;
            int spr = f >> 4;
            int d4 = (f & 15) * 4;
            int s = spr * 2;
            size_t ro0 = (size_t)(kb*64 + s    )*DDIM + d4;
            size_t ro1 = (size_t)(kb*64 + s + 1)*DDIM + d4;
            float4 x0 = *(const float4*)(V0 + ro0);
            float4 y0 = *(const float4*)(V1 + ro0);
            float4 x1 = *(const float4*)(V0 + ro1);
            float4 y1 = *(const float4*)(V1 + ro1);
            float4 bb = *(const float4*)(bvh + d4);
            float a0[4] = {x0.x+y0.x+bb.x, x0.y+y0.y+bb.y, x0.z+y0.z+bb.z, x0.w+y0.w+bb.w};
            float a1[4] = {x1.x+y1.x+bb.x, x1.y+y1.y+bb.y, x1.z+y1.z+bb.z, x1.w+y1.w+bb.w};
            int ks = s >> 4, slot = (s >> 3) & 1;
            int tp = (s & 7) >> 1;
            #pragma unroll
            for (int j = 0; j < 4; j++){
                int d = d4 + j;
                unsigned hv, lv;
                hsplit(a0[j], a1[j], hv, lv);
                Vh[ks][d>>3][(d&7)*4 + tp][slot] = hv;
                Vl[ks][d>>3][(d&7)*4 + tp][slot] = lv;
            }
        }
        __syncthreads();

        float sfrag[8][4];
        #pragma unroll
        for (int nt = 0; nt < 8; nt++)
            #pragma unroll
            for (int r = 0; r < 4; r++) sfrag[nt][r] = 0.0f;
        #pragma unroll
        for (int ks = 0; ks < 4; ks++){
            #pragma unroll
            for (int nt = 0; nt < 8; nt++){
                unsigned kh2[2], kl2[2];
                *(uint2*)kh2 = *(const uint2*)Kh[ks][nt][ln];
                *(uint2*)kl2 = *(const uint2*)Kl[ks][nt][ln];
                mma16(sfrag[nt], qh[ks], kh2);
                mma16(sfrag[nt], qh[ks], kl2);
            }
        }

        float mx0 = -INFINITY, mx1 = -INFINITY;
        #pragma unroll
        for (int nt = 0; nt < 8; nt++){
            #pragma unroll
            for (int e = 0; e < 2; e++){
                int c = kb*64 + nt*8 + t4*2 + e;
                bool in0 = (c >= r0 - 51) && (c <= r0 + 51);
                bool in1 = (c >= r1 - 51) && (c <= r1 + 51);
                float vv0 = sfrag[nt][e]   * 0.125f;
                float vv1 = sfrag[nt][2+e] * 0.125f;
                if (sp){
                    vv0 = in0 ? vv0 : -INFINITY;
                    vv1 = in1 ? vv1 : -INFINITY;
                } else {
                    if (!in0) vv0 -= lam;
                    if (!in1) vv1 -= lam;
                }
                sfrag[nt][e]   = vv0;
                sfrag[nt][2+e] = vv1;
                mx0 = fmaxf(mx0, vv0);
                mx1 = fmaxf(mx1, vv1);
            }
        }
        #pragma unroll
        for (int o = 1; o <= 2; o <<= 1){
            mx0 = fmaxf(mx0, __shfl_xor_sync(0xffffffffu, mx0, o));
            mx1 = fmaxf(mx1, __shfl_xor_sync(0xffffffffu, mx1, o));
        }
        float mnew0 = fmaxf(mrow0, mx0);
        float mnew1 = fmaxf(mrow1, mx1);
        float sf0 = (mrow0 == mnew0) ? 1.0f : __expf(mrow0 - mnew0);
        float sf1 = (mrow1 == mnew1) ? 1.0f : __expf(mrow1 - mnew1);
        float mc0 = fmaxf(mnew0, -1e30f);
        float mc1 = fmaxf(mnew1, -1e30f);
        float rs0 = 0.0f, rs1 = 0.0f;
        #pragma unroll
        for (int nt = 0; nt < 8; nt++){
            #pragma unroll
            for (int e = 0; e < 2; e++){
                float p0 = __expf(sfrag[nt][e]   - mc0);
                float p1 = __expf(sfrag[nt][2+e] - mc1);
                sfrag[nt][e]   = p0;
                sfrag[nt][2+e] = p1;
                rs0 += p0; rs1 += p1;
            }
        }
        #pragma unroll
        for (int o = 1; o <= 2; o <<= 1){
            rs0 += __shfl_xor_sync(0xffffffffu, rs0, o);
            rs1 += __shfl_xor_sync(0xffffffffu, rs1, o);
        }
        lrow0 = lrow0 * sf0 + rs0;  mrow0 = mnew0;
        lrow1 = lrow1 * sf1 + rs1;  mrow1 = mnew1;
        #pragma unroll
        for (int nt = 0; nt < 8; nt++){
            oacc[nt][0] *= sf0; oacc[nt][1] *= sf0;
            oacc[nt][2] *= sf1; oacc[nt][3] *= sf1;
        }

        #pragma unroll
        for (int pks = 0; pks < 4; pks++){
            unsigned pah[4];
            pah[0] = hpack(sfrag[2*pks  ][0], sfrag[2*pks  ][1]);
            pah[1] = hpack(sfrag[2*pks  ][2], sfrag[2*pks  ][3]);
            pah[2] = hpack(sfrag[2*pks+1][0], sfrag[2*pks+1][1]);
            pah[3] = hpack(sfrag[2*pks+1][2], sfrag[2*pks+1][3]);
            #pragma unroll
            for (int nt = 0; nt < 8; nt++){
                unsigned vh2[2], vl2[2];
                *(uint2*)vh2 = *(const uint2*)Vh[pks][nt][ln];
                *(uint2*)vl2 = *(const uint2*)Vl[pks][nt][ln];
                mma16(oacc[nt], pah, vh2);
                mma16(oacc[nt], pah, vl2);
            }
        }
    }

    float inv0 = 1.0f / lrow0;
    float inv1 = 1.0f / lrow1;
    unsigned* Ob = Oh + (size_t)(b*SS)*DW + (h*DH >> 1);
    #pragma unroll
    for (int nt = 0; nt < 8; nt++){
        int dwd = nt*4 + t4;
        Ob[(size_t)r0*DW + dwd] = hpack(oacc[nt][0]*inv0, oacc[nt][1]*inv0);
        Ob[(size_t)r1*DW + dwd] = hpack(oacc[nt][2]*inv1, oacc[nt][3]*inv1);
    }
}

// ---------------- final: out = sum(8 partials) + b2 + h ; u ----------------
__global__ void u_final(const float* __restrict__ part,
                        const float* __restrict__ b2, const float* __restrict__ hres,
                        const float* __restrict__ x, float* __restrict__ outp,
                        int out_size){
    pdl_wait();
    int row = blockIdx.x;
    int t = threadIdx.x;
    size_t off = (size_t)row*DDIM + t*4;
    const size_t slab = (size_t)MM * DDIM;
    float4 bv = *(const float4*)(b2 + t*4);
    float4 hv = *(const float4*)(hres + off);
    float4 o;
    o.x = bv.x + hv.x; o.y = bv.y + hv.y;
    o.z = bv.z + hv.z; o.w = bv.w + hv.w;
    #pragma unroll
    for (int z = 0; z < 8; z++){
        float4 a = *(const float4*)(part + z*slab + off);
        o.x += a.x; o.y += a.y; o.z += a.z; o.w += a.w;
    }
    *(float4*)(outp + off) = o;

    float4 xv = *(const float4*)(x + off);
    float dx = o.x - xv.x, dy = o.y - xv.y, dz = o.z - xv.z, dw = o.w - xv.w;
    float d2 = dx*dx + dy*dy + dz*dz + dw*dw;
    float x2 = xv.x*xv.x + xv.y*xv.y + xv.z*xv.z + xv.w*xv.w;
    #pragma unroll
    for (int o2 = 16; o2; o2 >>= 1){
        d2 += __shfl_xor_sync(0xffffffffu, d2, o2);
        x2 += __shfl_xor_sync(0xffffffffu, x2, o2);
    }
    __shared__ float pd[4], px[4];
    int w = t >> 5;
    if ((t & 31) == 0){ pd[w] = d2; px[w] = x2; }
    __syncthreads();
    if (t == 0){
        d2 = pd[0]+pd[1]+pd[2]+pd[3];
        x2 = px[0]+px[1]+px[2]+px[3];
        float u = sqrtf(d2) / (sqrtf(x2) + 1e-8f);
        int b = row >> 10;
        int idx = MM*DDIM + b;
        if (idx < out_size) atomicAdd(outp + idx, u * (1.0f/SS));
    }
}

// ---------------- PDL launch helper ----------------
static void launch_pdl(const void* fn, dim3 grid, dim3 block, void** args){
    cudaLaunchConfig_t cfg;
    memset(&cfg, 0, sizeof(cfg));
    cfg.gridDim = grid;
    cfg.blockDim = block;
    cfg.dynamicSmemBytes = 0;
    cfg.stream = 0;
    cudaLaunchAttribute at[1];
    at[0].id = cudaLaunchAttributeProgrammaticStreamSerialization;
    at[0].val.programmaticStreamSerializationAllowed = 1;
    cfg.attrs = at;
    cfg.numAttrs = 1;
    cudaLaunchKernelExC(&cfg, fn, args);
}

// ---------------- launch ----------------
extern "C" void kernel_launch(void* const* d_in, const int* in_sizes, int n_in,
                              void* d_out, int out_size){
    const float* x      = (const float*)d_in[0];
    const float* u_prev = (const float*)d_in[1];
    const float* wq = (const float*)d_in[2];  const float* bq = (const float*)d_in[3];
    const float* wk = (const float*)d_in[4];  const float* bk = (const float*)d_in[5];
    const float* wv = (const float*)d_in[6];  const float* bv = (const float*)d_in[7];
    const float* wo = (const float*)d_in[8];  const float* bo = (const float*)d_in[9];
    const float* ln1g = (const float*)d_in[10]; const float* ln1b = (const float*)d_in[11];
    const float* ln2g = (const float*)d_in[12]; const float* ln2b = (const float*)d_in[13];
    const float* w1 = (const float*)d_in[14]; const float* b1 = (const float*)d_in[15];
    const float* w2 = (const float*)d_in[16]; const float* b2 = (const float*)d_in[17];
    float* outp = (float*)d_out;

    unsigned *p_xnh, *p_atth, *p_hnh, *p_f1h;
    float *p_h, *p_part;
    cudaGetSymbolAddress((void**)&p_xnh, g_xnh);
    cudaGetSymbolAddress((void**)&p_atth,g_atth);
    cudaGetSymbolAddress((void**)&p_hnh, g_hnh);
    cudaGetSymbolAddress((void**)&p_f1h, g_f1h);
    cudaGetSymbolAddress((void**)&p_h,   g_h);
    cudaGetSymbolAddress((void**)&p_part,g_part);

    const size_t slab = (size_t)MM * DDIM;
    float* s0 = p_part;
    float* s1 = p_part + slab;
    float* s2 = p_part + 2*slab;
    float* s3 = p_part + 3*slab;
    float* s4 = p_part + 4*slab;
    float* s5 = p_part + 5*slab;

    // LN1 -> xnh plane (+lam, u-slot zero)
    {
        void* a[] = {&x, &ln1g, &ln1b, &p_xnh, &u_prev, &outp, (void*)&out_size};
        launch_pdl((const void*)ln1_kernel, dim3(MM), dim3(128), a);
    }
    // QKV split-K x2 -> 6 fp32 partial slabs
    {
        void* a[] = {&p_xnh, &wq, &wk, &wv, &p_part};
        launch_pdl((const void*)qkv_split, dim3(24, MM/64, 2), dim3(128), a);
    }
    // attention (fused partial reduce + bias) -> atth plane
    {
        void* a[] = {&s0, &s1, &s2, &s3, &s4, &s5, &bq, &bk, &bv, &p_atth};
        launch_pdl((const void*)attn_kernel, dim3(SS/64, BB*HH), dim3(128), a);
    }
    // Wo: split-K x4 -> fp32 partial slabs 0..3
    {
        int Kn = DDIM, Kloop = DDIM/4;
        void* a[] = {&p_atth, &wo, &p_part, &Kn, &Kloop};
        launch_pdl((const void*)gemm_split, dim3(DDIM/64, MM/64, 4), dim3(128), a);
    }
    // h = p0..p3+x+bo ; hn -> hnh plane
    {
        void* a[] = {&s0, &s1, &s2, &s3, &x, &bo, &ln2g, &ln2b, &p_h, &p_hnh};
        launch_pdl((const void*)ln2_fused, dim3(MM), dim3(128), a);
    }
    // FFN1 full-K + bias + GELU -> f1h plane
    {
        void* a[] = {&p_hnh, &w1, &b1, &p_f1h};
        launch_pdl((const void*)ffn1_kernel, dim3(FF/64, MM/64), dim3(128), a);
    }
    // FFN2: split-K x8 -> fp32 partial slabs 0..7
    {
        int Kn = FF, Kloop = FF/8;
        void* a[] = {&p_f1h, &w2, &p_part, &Kn, &Kloop};
        launch_pdl((const void*)gemm_split, dim3(DDIM/64, MM/64, 8), dim3(128), a);
    }
    // final: out = sum(partials) + b2 + h ; u
    {
        void* a[] = {&p_part, &b2, &p_h, &x, &outp, (void*)&out_size};
        launch_pdl((const void*)u_final, dim3(MM), dim3(128), a);
    }
}

// round 16
// speedup vs baseline: 1.4547x; 1.0701x over previous
#include <cuda_runtime.h>
#include <cuda_fp16.h>
#include <math.h>

#define BB 2
#define SS 1024
#define DDIM 512
#define HH 8
#define DH 64
#define FF 2048
#define MM (BB*SS)
#define DW (DDIM/2)
#define FW (FF/2)

// ---------------- scratch (no allocation allowed) ----------------
__device__ unsigned g_xnh[MM*DW];     // LN1 out, fp16 plane
__device__ unsigned g_atth[MM*DW];    // attn out, fp16 plane
__device__ unsigned g_hnh[MM*DW];     // LN2 out, fp16 plane
__device__ unsigned g_f1h[MM*FW];     // FFN1 out, fp16 plane
__device__ float    g_h [MM*DDIM];    // residual h (fp32)
__device__ float    g_part[8*MM*DDIM];
// fp16 weight planes
__device__ unsigned g_wqh[DDIM*DW], g_wkh[DDIM*DW], g_wvh[DDIM*DW], g_woh[DDIM*DW];
__device__ unsigned g_w1h[FF*DW],   g_w2h[DDIM*FW];
__device__ float g_lam[BB];
__device__ int   g_sp [BB];

// ---------------- helpers ----------------
__device__ __forceinline__ void pdl_wait(){
    asm volatile("griddepcontrol.wait;" ::: "memory");
}

__device__ __forceinline__ unsigned hpack(float x0, float x1){
    __half2 h = __floats2half2_rn(x0, x1);
    return *reinterpret_cast<unsigned*>(&h);
}

__device__ __forceinline__ void mma16(float* c, const unsigned* a, const unsigned* b){
    asm volatile(
        "mma.sync.aligned.m16n8k16.row.col.f32.f16.f16.f32 "
        "{%0,%1,%2,%3}, {%4,%5,%6,%7}, {%8,%9}, {%0,%1,%2,%3};\n"
        : "+f"(c[0]), "+f"(c[1]), "+f"(c[2]), "+f"(c[3])
        : "r"(a[0]), "r"(a[1]), "r"(a[2]), "r"(a[3]), "r"(b[0]), "r"(b[1]));
}

__device__ __forceinline__ float gelu_exact(float v){
    return 0.5f * v * (1.0f + erff(v * 0.70710678118654752f));
}

// ---------------- weight conversion: fp32 -> fp16 plane (all 6, z-indexed) ----------------
__global__ void wconv_kernel(const float* __restrict__ a0, const float* __restrict__ a1,
                             const float* __restrict__ a2, const float* __restrict__ a3,
                             const float* __restrict__ a4, const float* __restrict__ a5,
                             unsigned* __restrict__ o0, unsigned* __restrict__ o1,
                             unsigned* __restrict__ o2, unsigned* __restrict__ o3,
                             unsigned* __restrict__ o4, unsigned* __restrict__ o5){
    pdl_wait();
    int z = blockIdx.z;
    const float* src = (z==0)?a0:(z==1)?a1:(z==2)?a2:(z==3)?a3:(z==4)?a4:a5;
    unsigned* dst    = (z==0)?o0:(z==1)?o1:(z==2)?o2:(z==3)?o3:(z==4)?o4:o5;
    int n = (z < 4) ? (DDIM*DW) : ((z==4) ? (FF*DW) : (DDIM*FW));
    int i = blockIdx.x*256 + threadIdx.x;
    if (i < n){
        float2 v = ((const float2*)src)[i];
        dst[i] = hpack(v.x, v.y);
    }
}

// ---------------- LayerNorm1 (+lam / u-slot zero) -> fp16 plane ----------------
__global__ void ln1_kernel(const float* __restrict__ x, const float* __restrict__ g,
                           const float* __restrict__ be, unsigned* __restrict__ yh,
                           const float* __restrict__ u_prev, float* __restrict__ outp,
                           int out_size){
    pdl_wait();
    int row = blockIdx.x;
    int t = threadIdx.x;
    if (row == 0 && t < BB){
        float lam = 10.0f * expf(-5.0f * u_prev[t]);
        g_lam[t] = lam;
        g_sp[t]  = (lam >= 1.0f) ? 1 : 0;
        int idx = MM*DDIM + t;
        if (idx < out_size) outp[idx] = 0.0f;
    }
    const float* xr = x + (size_t)row * DDIM;
    float4 v = *(const float4*)(xr + t*4);
    float s  = v.x + v.y + v.z + v.w;
    float ss = v.x*v.x + v.y*v.y + v.z*v.z + v.w*v.w;
    #pragma unroll
    for (int o = 16; o; o >>= 1){
        s  += __shfl_xor_sync(0xffffffffu, s,  o);
        ss += __shfl_xor_sync(0xffffffffu, ss, o);
    }
    __shared__ float ps[4], pss[4];
    int w = t >> 5;
    if ((t & 31) == 0){ ps[w] = s; pss[w] = ss; }
    __syncthreads();
    s  = ps[0] + ps[1] + ps[2] + ps[3];
    ss = pss[0] + pss[1] + pss[2] + pss[3];
    float mean = s * (1.0f/DDIM);
    float var  = ss * (1.0f/DDIM) - mean*mean;
    float inv  = rsqrtf(var + 1e-5f);
    float4 gv = *(const float4*)(g  + t*4);
    float4 bv = *(const float4*)(be + t*4);
    float o0 = (v.x - mean)*inv*gv.x + bv.x;
    float o1 = (v.y - mean)*inv*gv.y + bv.y;
    float o2 = (v.z - mean)*inv*gv.z + bv.z;
    float o3 = (v.w - mean)*inv*gv.w + bv.w;
    uint2 ww;
    ww.x = hpack(o0, o1);
    ww.y = hpack(o2, o3);
    *(uint2*)(yh + (size_t)row*DW + t*2) = ww;
}

// ---------------- fused: h = p0..p3+x+bo ; hn = LN2(h) -> fp16 plane ----------------
__global__ void ln2_fused(const float* __restrict__ p0, const float* __restrict__ p1,
                          const float* __restrict__ p2, const float* __restrict__ p3,
                          const float* __restrict__ x, const float* __restrict__ bo,
                          const float* __restrict__ g, const float* __restrict__ be,
                          float* __restrict__ h, unsigned* __restrict__ hnh){
    pdl_wait();
    int row = blockIdx.x;
    int t = threadIdx.x;
    size_t off = (size_t)row*DDIM + t*4;
    float4 a0 = *(const float4*)(p0 + off);
    float4 a1 = *(const float4*)(p1 + off);
    float4 a2 = *(const float4*)(p2 + off);
    float4 a3 = *(const float4*)(p3 + off);
    float4 xv = *(const float4*)(x + off);
    float4 bv0 = *(const float4*)(bo + t*4);
    float4 v;
    v.x = a0.x + a1.x + a2.x + a3.x + xv.x + bv0.x;
    v.y = a0.y + a1.y + a2.y + a3.y + xv.y + bv0.y;
    v.z = a0.z + a1.z + a2.z + a3.z + xv.z + bv0.z;
    v.w = a0.w + a1.w + a2.w + a3.w + xv.w + bv0.w;
    *(float4*)(h + off) = v;

    float s  = v.x + v.y + v.z + v.w;
    float ss = v.x*v.x + v.y*v.y + v.z*v.z + v.w*v.w;
    #pragma unroll
    for (int o = 16; o; o >>= 1){
        s  += __shfl_xor_sync(0xffffffffu, s,  o);
        ss += __shfl_xor_sync(0xffffffffu, ss, o);
    }
    __shared__ float ps[4], pss[4];
    int w = t >> 5;
    if ((t & 31) == 0){ ps[w] = s; pss[w] = ss; }
    __syncthreads();
    s  = ps[0] + ps[1] + ps[2] + ps[3];
    ss = pss[0] + pss[1] + pss[2] + pss[3];
    float mean = s * (1.0f/DDIM);
    float var  = ss * (1.0f/DDIM) - mean*mean;
    float inv  = rsqrtf(var + 1e-5f);
    float4 gv = *(const float4*)(g  + t*4);
    float4 bv = *(const float4*)(be + t*4);
    float o0 = (v.x - mean)*inv*gv.x + bv.x;
    float o1 = (v.y - mean)*inv*gv.y + bv.y;
    float o2 = (v.z - mean)*inv*gv.z + bv.z;
    float o3 = (v.w - mean)*inv*gv.w + bv.w;
    uint2 ww;
    ww.x = hpack(o0, o1);
    ww.y = hpack(o2, o3);
    *(uint2*)(hnh + (size_t)row*DW + t*2) = ww;
}

// ---------------- fp16 single-term GEMM body ----------------
// A: fp16 plane. W: fp16 plane. D += A*W. BM=64, BN=64, BK=32, 128 thr.
// EPI 0: fp32 partial to Cp (N stride DDIM).  EPI 1: bias+GELU -> fp16 plane.
template<int EPI>
__device__ __forceinline__ void gemm_pbody(
        const unsigned* __restrict__ Ap, const unsigned* __restrict__ Wp,
        const float* __restrict__ bias,
        float* __restrict__ Cp, unsigned* __restrict__ Chp,
        int Kn, int Kloop, int kbase, int Nn, int m0, int n0){
    __shared__ unsigned Ah[2][4][32][4];
    __shared__ unsigned Bh[2][8][32][2];

    const int tid = threadIdx.x;
    const int warp = tid >> 5, ln = tid & 31;
    const int wm = warp >> 1, wn = warp & 1;
    const int gid = ln >> 2, t4 = ln & 3;
    const int Kw = Kn >> 1;
    const int kbw = kbase >> 1;

    float acc[2][4][4];
    #pragma unroll
    for (int mt = 0; mt < 2; mt++)
        #pragma unroll
        for (int nt = 0; nt < 4; nt++)
            #pragma unroll
            for (int r = 0; r < 4; r++) acc[mt][nt][r] = 0.0f;

    uint4 av[2], wv[2];
    #pragma unroll
    for (int i = 0; i < 2; i++){
        int f = tid + i*128;
        int row = f >> 2, w4 = (f & 3) << 2;
        av[i] = *(const uint4*)(Ap + (size_t)(m0 + row)*Kw + kbw + w4);
        wv[i] = *(const uint4*)(Wp + (size_t)(n0 + row)*Kw + kbw + w4);
    }

    for (int kt = 0; kt < Kloop; kt += 32){
        __syncthreads();
        #pragma unroll
        for (int i = 0; i < 2; i++){
            int f = tid + i*128;
            int row = f >> 2, w4 = (f & 3) << 2;
            int rr = row & 15, mt = row >> 4;
            int nt = row >> 3;
            unsigned ad[4] = {av[i].x, av[i].y, av[i].z, av[i].w};
            unsigned wd[4] = {wv[i].x, wv[i].y, wv[i].z, wv[i].w};
            #pragma unroll
            for (int j = 0; j < 4; j++){
                int kk = w4 + j;
                int ks = kk >> 3;
                // A scatter
                int aslot = ((rr >> 3) & 1) + (((kk >> 2) & 1) << 1);
                int alane = (rr & 7)*4 + (kk & 3);
                Ah[ks][mt][alane][aslot] = ad[j];
                // B scatter
                int bslot = (kk >> 2) & 1;
                int blane = (row & 7)*4 + (kk & 3);
                Bh[ks][nt][blane][bslot] = wd[j];
            }
        }
        __syncthreads();

        if (kt + 32 < Kloop){
            int ktw = (kt + 32) >> 1;
            #pragma unroll
            for (int i = 0; i < 2; i++){
                int f = tid + i*128;
                int row = f >> 2, w4 = (f & 3) << 2;
                av[i] = *(const uint4*)(Ap + (size_t)(m0 + row)*Kw + kbw + ktw + w4);
                wv[i] = *(const uint4*)(Wp + (size_t)(n0 + row)*Kw + kbw + ktw + w4);
            }
        }

        #pragma unroll
        for (int ks = 0; ks < 2; ks++){
            unsigned ah[2][4], bh[4][2];
            #pragma unroll
            for (int mt = 0; mt < 2; mt++)
                *(uint4*)ah[mt] = *(const uint4*)Ah[ks][wm*2 + mt][ln];
            #pragma unroll
            for (int nt = 0; nt < 4; nt++)
                *(uint2*)bh[nt] = *(const uint2*)Bh[ks][wn*4 + nt][ln];
            #pragma unroll
            for (int mt = 0; mt < 2; mt++)
                #pragma unroll
                for (int nt = 0; nt < 4; nt++)
                    mma16(acc[mt][nt], ah[mt], bh[nt]);
        }
    }

    #pragma unroll
    for (int mt = 0; mt < 2; mt++){
        #pragma unroll
        for (int rr = 0; rr < 2; rr++){
            int m = m0 + wm*32 + mt*16 + gid + rr*8;
            #pragma unroll
            for (int nt = 0; nt < 4; nt++){
                int n = n0 + wn*32 + nt*8 + t4*2;
                float2 o;
                o.x = acc[mt][nt][rr*2 + 0];
                o.y = acc[mt][nt][rr*2 + 1];
                if (EPI == 0){
                    *(float2*)(Cp + (size_t)m*DDIM + n) = o;
                } else {
                    float2 bv = *(const float2*)(bias + n);
                    o.x = gelu_exact(o.x + bv.x);
                    o.y = gelu_exact(o.y + bv.y);
                    Chp[(size_t)m*(Nn >> 1) + (n >> 1)] = hpack(o.x, o.y);
                }
            }
        }
    }
}

// ---------------- GEMM kernels ----------------
__global__ void __launch_bounds__(128)
qkv_split(const unsigned* __restrict__ xnh,
          const unsigned* __restrict__ wqh, const unsigned* __restrict__ wkh,
          const unsigned* __restrict__ wvh, float* __restrict__ part){
    pdl_wait();
    int sel = blockIdx.x >> 3;
    int n0  = (blockIdx.x & 7) << 6;
    int z   = blockIdx.z;
    const unsigned* W = (sel == 0) ? wqh : (sel == 1) ? wkh : wvh;
    float* Cp = part + (size_t)(sel*2 + z) * MM * DDIM;
    gemm_pbody<0>(xnh, W, nullptr, Cp, nullptr, DDIM, DDIM/2, z*(DDIM/2), DDIM, blockIdx.y*64, n0);
}

__global__ void __launch_bounds__(128)
gemm_split(const unsigned* __restrict__ Ap, const unsigned* __restrict__ Wp,
           float* __restrict__ Cpart, int Kn, int Kloop){
    pdl_wait();
    float* Cp = Cpart + (size_t)blockIdx.z * MM * DDIM;
    gemm_pbody<0>(Ap, Wp, nullptr, Cp, nullptr, Kn, Kloop, blockIdx.z*Kloop, DDIM, blockIdx.y*64, blockIdx.x*64);
}

__global__ void __launch_bounds__(128)
ffn1_kernel(const unsigned* __restrict__ hnh, const unsigned* __restrict__ w1h,
            const float* __restrict__ b1, unsigned* __restrict__ f1h){
    pdl_wait();
    gemm_pbody<1>(hnh, w1h, b1, nullptr, f1h, DDIM, DDIM, 0, FF, blockIdx.y*64, blockIdx.x*64);
}

// ---------------- fp16 single-plane flash attention ----------------
__global__ void __launch_bounds__(128, 3)
attn_kernel(const float* __restrict__ q0, const float* __restrict__ q1,
            const float* __restrict__ k0, const float* __restrict__ k1,
            const float* __restrict__ v0, const float* __restrict__ v1,
            const float* __restrict__ bq, const float* __restrict__ bk,
            const float* __restrict__ bv, unsigned* __restrict__ Oh){
    pdl_wait();
    __shared__ unsigned Kh[4][8][32][2];
    __shared__ unsigned Vh[4][8][32][2];

    const int bh = blockIdx.y;
    const int b = bh / HH, h = bh % HH;
    const int q0i = blockIdx.x * 64;
    const float lam = g_lam[b];
    const int sp = g_sp[b];
    const int tid = threadIdx.x;
    const int w = tid >> 5, ln = tid & 31;
    const int gid = ln >> 2, t4 = ln & 3;
    const int r0 = q0i + w*16 + gid;
    const int r1 = r0 + 8;

    unsigned qh[4][4];
    {
        const float* Q0 = q0 + (size_t)(b*SS)*DDIM + h*DH;
        const float* Q1 = q1 + (size_t)(b*SS)*DDIM + h*DH;
        const float* bqh = bq + h*DH;
        #pragma unroll
        for (int ks = 0; ks < 4; ks++){
            int kcol = ks*16 + t4*2;
            float2 b0 = *(const float2*)(bqh + kcol);
            float2 b1v = *(const float2*)(bqh + kcol + 8);
            float2 a00 = *(const float2*)(Q0 + (size_t)r0*DDIM + kcol);
            float2 c00 = *(const float2*)(Q1 + (size_t)r0*DDIM + kcol);
            float2 a10 = *(const float2*)(Q0 + (size_t)r1*DDIM + kcol);
            float2 c10 = *(const float2*)(Q1 + (size_t)r1*DDIM + kcol);
            float2 a01 = *(const float2*)(Q0 + (size_t)r0*DDIM + kcol + 8);
            float2 c01 = *(const float2*)(Q1 + (size_t)r0*DDIM + kcol + 8);
            float2 a11 = *(const float2*)(Q0 + (size_t)r1*DDIM + kcol + 8);
            float2 c11 = *(const float2*)(Q1 + (size_t)r1*DDIM + kcol + 8);
            qh[ks][0] = hpack(a00.x + c00.x + b0.x,  a00.y + c00.y + b0.y);
            qh[ks][1] = hpack(a10.x + c10.x + b0.x,  a10.y + c10.y + b0.y);
            qh[ks][2] = hpack(a01.x + c01.x + b1v.x, a01.y + c01.y + b1v.y);
            qh[ks][3] = hpack(a11.x + c11.x + b1v.x, a11.y + c11.y + b1v.y);
        }
    }

    float oacc[8][4];
    #pragma unroll
    for (int nt = 0; nt < 8; nt++)
        #pragma unroll
        for (int r = 0; r < 4; r++) oacc[nt][r] = 0.0f;
    float mrow0 = -INFINITY, mrow1 = -INFINITY;
    float lrow0 = 0.0f, lrow1 = 0.0f;

    int klo = 0, khi = SS/64;
    if (sp){
        int lo = q0i - 51; if (lo < 0) lo = 0;
        int hi = q0i + 114; if (hi > SS-1) hi = SS-1;
        klo = lo >> 6; khi = (hi >> 6) + 1;
    }

    const float* K0 = k0 + (size_t)(b*SS)*DDIM + h*DH;
    const float* K1 = k1 + (size_t)(b*SS)*DDIM + h*DH;
    const float* V0 = v0 + (size_t)(b*SS)*DDIM + h*DH;
    const float* V1 = v1 + (size_t)(b*SS)*DDIM + h*DH;
    const float* bkh = bk + h*DH;
    const float* bvh = bv + h*DH;

    for (int kb = klo; kb < khi; kb++){
        __syncthreads();
        #pragma unroll
        for (int i = 0; i < 4; i++){
            int f = tid + i*128;
            int r = f >> 3;
            int d8 = (f & 7) * 8;
            size_t ro = (size_t)(kb*64 + r)*DDIM + d8;
            float4 x0 = *(const float4*)(K0 + ro);
            float4 y0 = *(const float4*)(K1 + ro);
            float4 bb0 = *(const float4*)(bkh + d8);
            float4 x1 = *(const float4*)(K0 + ro + 4);
            float4 y1 = *(const float4*)(K1 + ro + 4);
            float4 bb1 = *(const float4*)(bkh + d8 + 4);
            x0.x += y0.x + bb0.x; x0.y += y0.y + bb0.y;
            x0.z += y0.z + bb0.z; x0.w += y0.w + bb0.w;
            x1.x += y1.x + bb1.x; x1.y += y1.y + bb1.y;
            x1.z += y1.z + bb1.z; x1.w += y1.w + bb1.w;
            int ks = d8 >> 4, slot = (d8 >> 3) & 1;
            int lbase = (r & 7) * 4;
            int nt = r >> 3;
            Kh[ks][nt][lbase+0][slot] = hpack(x0.x, x0.y);
            Kh[ks][nt][lbase+1][slot] = hpack(x0.z, x0.w);
            Kh[ks][nt][lbase+2][slot] = hpack(x1.x, x1.y);
            Kh[ks][nt][lbase+3][slot] = hpack(x1.z, x1.w);
        }
        #pragma unroll
        for (int i = 0; i < 4; i++){
            int f = tid + i*128;
            int spr = f >> 4;
            int d4 = (f & 15) * 4;
            int s = spr * 2;
            size_t ro0 = (size_t)(kb*64 + s    )*DDIM + d4;
            size_t ro1 = (size_t)(kb*64 + s + 1)*DDIM + d4;
            float4 x0 = *(const float4*)(V0 + ro0);
            float4 y0 = *(const float4*)(V1 + ro0);
            float4 x1 = *(const float4*)(V0 + ro1);
            float4 y1 = *(const float4*)(V1 + ro1);
            float4 bb = *(const float4*)(bvh + d4);
            float a0[4] = {x0.x+y0.x+bb.x, x0.y+y0.y+bb.y, x0.z+y0.z+bb.z, x0.w+y0.w+bb.w};
            float a1[4] = {x1.x+y1.x+bb.x, x1.y+y1.y+bb.y, x1.z+y1.z+bb.z, x1.w+y1.w+bb.w};
            int ks = s >> 4, slot = (s >> 3) & 1;
            int tp = (s & 7) >> 1;
            #pragma unroll
            for (int j = 0; j < 4; j++){
                int d = d4 + j;
                Vh[ks][d>>3][(d&7)*4 + tp][slot] = hpack(a0[j], a1[j]);
            }
        }
        __syncthreads();

        float sfrag[8][4];
        #pragma unroll
        for (int nt = 0; nt < 8; nt++)
            #pragma unroll
            for (int r = 0; r < 4; r++) sfrag[nt][r] = 0.0f;
        #pragma unroll
        for (int ks = 0; ks < 4; ks++){
            #pragma unroll
            for (int nt = 0; nt < 8; nt++){
                unsigned kh2[2];
                *(uint2*)kh2 = *(const uint2*)Kh[ks][nt][ln];
                mma16(sfrag[nt], qh[ks], kh2);
            }
        }

        float mx0 = -INFINITY, mx1 = -INFINITY;
        #pragma unroll
        for (int nt = 0; nt < 8; nt++){
            #pragma unroll
            for (int e = 0; e < 2; e++){
                int c = kb*64 + nt*8 + t4*2 + e;
                bool in0 = (c >= r0 - 51) && (c <= r0 + 51);
                bool in1 = (c >= r1 - 51) && (c <= r1 + 51);
                float vv0 = sfrag[nt][e]   * 0.125f;
                float vv1 = sfrag[nt][2+e] * 0.125f;
                if (sp){
                    vv0 = in0 ? vv0 : -INFINITY;
                    vv1 = in1 ? vv1 : -INFINITY;
                } else {
                    if (!in0) vv0 -= lam;
                    if (!in1) vv1 -= lam;
                }
                sfrag[nt][e]   = vv0;
                sfrag[nt][2+e] = vv1;
                mx0 = fmaxf(mx0, vv0);
                mx1 = fmaxf(mx1, vv1);
            }
        }
        #pragma unroll
        for (int o = 1; o <= 2; o <<= 1){
            mx0 = fmaxf(mx0, __shfl_xor_sync(0xffffffffu, mx0, o));
            mx1 = fmaxf(mx1, __shfl_xor_sync(0xffffffffu, mx1, o));
        }
        float mnew0 = fmaxf(mrow0, mx0);
        float mnew1 = fmaxf(mrow1, mx1);
        float sf0 = (mrow0 == mnew0) ? 1.0f : __expf(mrow0 - mnew0);
        float sf1 = (mrow1 == mnew1) ? 1.0f : __expf(mrow1 - mnew1);
        float mc0 = fmaxf(mnew0, -1e30f);
        float mc1 = fmaxf(mnew1, -1e30f);
        float rs0 = 0.0f, rs1 = 0.0f;
        #pragma unroll
        for (int nt = 0; nt < 8; nt++){
            #pragma unroll
            for (int e = 0; e < 2; e++){
                float p0 = __expf(sfrag[nt][e]   - mc0);
                float p1 = __expf(sfrag[nt][2+e] - mc1);
                sfrag[nt][e]   = p0;
                sfrag[nt][2+e] = p1;
                rs0 += p0; rs1 += p1;
            }
        }
        #pragma unroll
        for (int o = 1; o <= 2; o <<= 1){
            rs0 += __shfl_xor_sync(0xffffffffu, rs0, o);
            rs1 += __shfl_xor_sync(0xffffffffu, rs1, o);
        }
        lrow0 = lrow0 * sf0 + rs0;  mrow0 = mnew0;
        lrow1 = lrow1 * sf1 + rs1;  mrow1 = mnew1;
        #pragma unroll
        for (int nt = 0; nt < 8; nt++){
            oacc[nt][0] *= sf0; oacc[nt][1] *= sf0;
            oacc[nt][2] *= sf1; oacc[nt][3] *= sf1;
        }

        #pragma unroll
        for (int pks = 0; pks < 4; pks++){
            unsigned pah[4];
            pah[0] = hpack(sfrag[2*pks  ][0], sfrag[2*pks  ][1]);
            pah[1] = hpack(sfrag[2*pks  ][2], sfrag[2*pks  ][3]);
            pah[2] = hpack(sfrag[2*pks+1][0], sfrag[2*pks+1][1]);
            pah[3] = hpack(sfrag[2*pks+1][2], sfrag[2*pks+1][3]);
            #pragma unroll
            for (int nt = 0; nt < 8; nt++){
                unsigned vh2[2];
                *(uint2*)vh2 = *(const uint2*)Vh[pks][nt][ln];
                mma16(oacc[nt], pah, vh2);
            }
        }
    }

    float inv0 = 1.0f / lrow0;
    float inv1 = 1.0f / lrow1;
    unsigned* Ob = Oh + (size_t)(b*SS)*DW + (h*DH >> 1);
    #pragma unroll
    for (int nt = 0; nt < 8; nt++){
        int dwd = nt*4 + t4;
        Ob[(size_t)r0*DW + dwd] = hpack(oacc[nt][0]*inv0, oacc[nt][1]*inv0);
        Ob[(size_t)r1*DW + dwd] = hpack(oacc[nt][2]*inv1, oacc[nt][3]*inv1);
    }
}

// ---------------- final: out = sum(8 partials) + b2 + h ; u ----------------
__global__ void u_final(const float* __restrict__ part,
                        const float* __restrict__ b2, const float* __restrict__ hres,
                        const float* __restrict__ x, float* __restrict__ outp,
                        int out_size){
    pdl_wait();
    int row = blockIdx.x;
    int t = threadIdx.x;
    size_t off = (size_t)row*DDIM + t*4;
    const size_t slab = (size_t)MM * DDIM;
    float4 bv = *(const float4*)(b2 + t*4);
    float4 hv = *(const float4*)(hres + off);
    float4 o;
    o.x = bv.x + hv.x; o.y = bv.y + hv.y;
    o.z = bv.z + hv.z; o.w = bv.w + hv.w;
    #pragma unroll
    for (int z = 0; z < 8; z++){
        float4 a = *(const float4*)(part + z*slab + off);
        o.x += a.x; o.y += a.y; o.z += a.z; o.w += a.w;
    }
    *(float4*)(outp + off) = o;

    float4 xv = *(const float4*)(x + off);
    float dx = o.x - xv.x, dy = o.y - xv.y, dz = o.z - xv.z, dw = o.w - xv.w;
    float d2 = dx*dx + dy*dy + dz*dz + dw*dw;
    float x2 = xv.x*xv.x + xv.y*xv.y + xv.z*xv.z + xv.w*xv.w;
    #pragma unroll
    for (int o2 = 16; o2; o2 >>= 1){
        d2 += __shfl_xor_sync(0xffffffffu, d2, o2);
        x2 += __shfl_xor_sync(0xffffffffu, x2, o2);
    }
    __shared__ float pd[4], px[4];
    int w = t >> 5;
    if ((t & 31) == 0){ pd[w] = d2; px[w] = x2; }
    __syncthreads();
    if (t == 0){
        d2 = pd[0]+pd[1]+pd[2]+pd[3];
        x2 = px[0]+px[1]+px[2]+px[3];
        float u = sqrtf(d2) / (sqrtf(x2) + 1e-8f);
        int b = row >> 10;
        int idx = MM*DDIM + b;
        if (idx < out_size) atomicAdd(outp + idx, u * (1.0f/SS));
    }
}

// ---------------- PDL launch helper ----------------
static void launch_pdl(const void* fn, dim3 grid, dim3 block, void** args){
    cudaLaunchConfig_t cfg;
    memset(&cfg, 0, sizeof(cfg));
    cfg.gridDim = grid;
    cfg.blockDim = block;
    cfg.dynamicSmemBytes = 0;
    cfg.stream = 0;
    cudaLaunchAttribute at[1];
    at[0].id = cudaLaunchAttributeProgrammaticStreamSerialization;
    at[0].val.programmaticStreamSerializationAllowed = 1;
    cfg.attrs = at;
    cfg.numAttrs = 1;
    cudaLaunchKernelExC(&cfg, fn, args);
}

// ---------------- launch ----------------
extern "C" void kernel_launch(void* const* d_in, const int* in_sizes, int n_in,
                              void* d_out, int out_size){
    const float* x      = (const float*)d_in[0];
    const float* u_prev = (const float*)d_in[1];
    const float* wq = (const float*)d_in[2];  const float* bq = (const float*)d_in[3];
    const float* wk = (const float*)d_in[4];  const float* bk = (const float*)d_in[5];
    const float* wv = (const float*)d_in[6];  const float* bv = (const float*)d_in[7];
    const float* wo = (const float*)d_in[8];  const float* bo = (const float*)d_in[9];
    const float* ln1g = (const float*)d_in[10]; const float* ln1b = (const float*)d_in[11];
    const float* ln2g = (const float*)d_in[12]; const float* ln2b = (const float*)d_in[13];
    const float* w1 = (const float*)d_in[14]; const float* b1 = (const float*)d_in[15];
    const float* w2 = (const float*)d_in[16]; const float* b2 = (const float*)d_in[17];
    float* outp = (float*)d_out;

    unsigned *p_xnh, *p_atth, *p_hnh, *p_f1h;
    unsigned *p_wqh, *p_wkh, *p_wvh, *p_woh, *p_w1h, *p_w2h;
    float *p_h, *p_part;
    cudaGetSymbolAddress((void**)&p_xnh, g_xnh);
    cudaGetSymbolAddress((void**)&p_atth,g_atth);
    cudaGetSymbolAddress((void**)&p_hnh, g_hnh);
    cudaGetSymbolAddress((void**)&p_f1h, g_f1h);
    cudaGetSymbolAddress((void**)&p_wqh, g_wqh);
    cudaGetSymbolAddress((void**)&p_wkh, g_wkh);
    cudaGetSymbolAddress((void**)&p_wvh, g_wvh);
    cudaGetSymbolAddress((void**)&p_woh, g_woh);
    cudaGetSymbolAddress((void**)&p_w1h, g_w1h);
    cudaGetSymbolAddress((void**)&p_w2h, g_w2h);
    cudaGetSymbolAddress((void**)&p_h,   g_h);
    cudaGetSymbolAddress((void**)&p_part,g_part);

    const size_t slab = (size_t)MM * DDIM;
    float* s0 = p_part;
    float* s1 = p_part + slab;
    float* s2 = p_part + 2*slab;
    float* s3 = p_part + 3*slab;
    float* s4 = p_part + 4*slab;
    float* s5 = p_part + 5*slab;

    // weight fp16 plane conversion (one launch, z-indexed)
    {
        void* a[] = {&wq, &wk, &wv, &wo, &w1, &w2,
                     &p_wqh, &p_wkh, &p_wvh, &p_woh, &p_w1h, &p_w2h};
        launch_pdl((const void*)wconv_kernel, dim3(2048, 1, 6), dim3(256), a);
    }
    // LN1 -> xnh plane (+lam, u-slot zero)
    {
        void* a[] = {&x, &ln1g, &ln1b, &p_xnh, &u_prev, &outp, (void*)&out_size};
        launch_pdl((const void*)ln1_kernel, dim3(MM), dim3(128), a);
    }
    // QKV split-K x2 -> 6 fp32 partial slabs
    {
        void* a[] = {&p_xnh, &p_wqh, &p_wkh, &p_wvh, &p_part};
        launch_pdl((const void*)qkv_split, dim3(24, MM/64, 2), dim3(128), a);
    }
    // attention (fused partial reduce + bias) -> atth plane
    {
        void* a[] = {&s0, &s1, &s2, &s3, &s4, &s5, &bq, &bk, &bv, &p_atth};
        launch_pdl((const void*)attn_kernel, dim3(SS/64, BB*HH), dim3(128), a);
    }
    // Wo: split-K x4 -> fp32 partial slabs 0..3
    {
        int Kn = DDIM, Kloop = DDIM/4;
        void* a[] = {&p_atth, &p_woh, &p_part, &Kn, &Kloop};
        launch_pdl((const void*)gemm_split, dim3(DDIM/64, MM/64, 4), dim3(128), a);
    }
    // h = p0..p3+x+bo ; hn -> hnh plane
    {
        void* a[] = {&s0, &s1, &s2, &s3, &x, &bo, &ln2g, &ln2b, &p_h, &p_hnh};
        launch_pdl((const void*)ln2_fused, dim3(MM), dim3(128), a);
    }
    // FFN1 full-K + bias + GELU -> f1h plane
    {
        void* a[] = {&p_hnh, &p_w1h, &b1, &p_f1h};
        launch_pdl((const void*)ffn1_kernel, dim3(FF/64, MM/64), dim3(128), a);
    }
    // FFN2: split-K x8 -> fp32 partial slabs 0..7
    {
        int Kn = FF, Kloop = FF/8;
        void* a[] = {&p_f1h, &p_w2h, &p_part, &Kn, &Kloop};
        launch_pdl((const void*)gemm_split, dim3(DDIM/64, MM/64, 8), dim3(128), a);
    }
    // final: out = sum(partials) + b2 + h ; u
    {
        void* a[] = {&p_part, &b2, &p_h, &x, &outp, (void*)&out_size};
        launch_pdl((const void*)u_final, dim3(MM), dim3(128), a);
    }
}